// round 12
// baseline (speedup 1.0000x reference)
#include <cuda_runtime.h>
#include <math.h>
#include <stdint.h>

#define FULLMASK 0xffffffffu
#define LOG2E 1.4426950408889634f

// problem dims
#define NTOK   343
#define NHEAD  6
#define HD     32
#define CDIM   192
#define LTOT   21952
#define NWIN   128
#define NROWS  43904
#define RPBS   344

// ---------------- device scratch ------------------------------------------------
__device__ float g_hb[2197 * 6];
__device__ __align__(16) float g_rpb[6 * 343 * RPBS];
__device__ __align__(16) float g_q[(size_t)NWIN * NHEAD * NTOK * HD];
__device__ __align__(16) float g_k[(size_t)NWIN * NHEAD * NTOK * HD];
__device__ __align__(16) float g_v[(size_t)NWIN * NHEAD * NTOK * HD];
__device__ __align__(16) float g_attnout[(size_t)NWIN * NTOK * CDIM];   // tf32-rounded
__device__ __align__(16) float g_x1[(size_t)2 * LTOT * CDIM];           // fp32
__device__ __align__(16) float g_x1t[(size_t)2 * LTOT * CDIM];          // tf32-rounded
__device__ __align__(16) float g_xt[(size_t)2 * LTOT * CDIM];           // tf32-rounded
__device__ __align__(16) float g_hmid[(size_t)NROWS * 768];             // tf32-rounded
__device__ __align__(16) float g_wq[576 * 192];
__device__ __align__(16) float g_wp[192 * 192];
__device__ __align__(16) float g_w1[768 * 192];
__device__ __align__(16) float g_w2[192 * 768];

// ---------------- helpers -------------------------------------------------------
__device__ __forceinline__ uint32_t f2tf32(float x) {
    uint32_t r;
    asm("cvt.rna.tf32.f32 %0, %1;" : "=r"(r) : "f"(x));
    return r;
}

__device__ __forceinline__ void mma_tf32(float* c, const uint32_t* a, const uint32_t* b) {
    asm volatile(
        "mma.sync.aligned.m16n8k8.row.col.f32.tf32.tf32.f32 "
        "{%0,%1,%2,%3}, {%4,%5,%6,%7}, {%8,%9}, {%0,%1,%2,%3};"
        : "+f"(c[0]), "+f"(c[1]), "+f"(c[2]), "+f"(c[3])
        : "r"(a[0]), "r"(a[1]), "r"(a[2]), "r"(a[3]), "r"(b[0]), "r"(b[1]));
}

__device__ __forceinline__ uint32_t smem_u32(const void* p) {
    uint32_t a;
    asm("{ .reg .u64 t; cvta.to.shared.u64 t, %1; cvt.u32.u64 %0, t; }" : "=r"(a) : "l"(p));
    return a;
}

__device__ __forceinline__ void cp16(uint32_t dst, const void* src) {
    asm volatile("cp.async.ca.shared.global [%0], [%1], 16;" :: "r"(dst), "l"(src));
}
#define CP_COMMIT() asm volatile("cp.async.commit_group;" ::: "memory")
#define CP_WAIT1()  asm volatile("cp.async.wait_group 1;" ::: "memory")

// ---------------- fused tf32 convert kernel --------------------------------------
__global__ void __launch_bounds__(256) cvt_all(const float* __restrict__ x,
                                               const float* __restrict__ wq,
                                               const float* __restrict__ wp,
                                               const float* __restrict__ w1,
                                               const float* __restrict__ w2) {
    const int N0 = 2107392;            // x: 2*LTOT*CDIM/4
    const int N1 = N0 + 27648;         // wq
    const int N2 = N1 + 9216;          // wp
    const int N3 = N2 + 36864;         // w1
    const int N4 = N3 + 36864;         // w2
    for (int i = blockIdx.x * blockDim.x + threadIdx.x; i < N4;
         i += gridDim.x * blockDim.x) {
        const float4* s;
        uint4* d;
        int off;
        if (i < N0) { s = (const float4*)x; d = (uint4*)g_xt; off = i; }
        else if (i < N1) { s = (const float4*)wq; d = (uint4*)g_wq; off = i - N0; }
        else if (i < N2) { s = (const float4*)wp; d = (uint4*)g_wp; off = i - N1; }
        else if (i < N3) { s = (const float4*)w1; d = (uint4*)g_w1; off = i - N2; }
        else { s = (const float4*)w2; d = (uint4*)g_w2; off = i - N3; }
        float4 v = s[off];
        uint4 u;
        u.x = f2tf32(v.x);
        u.y = f2tf32(v.y);
        u.z = f2tf32(v.z);
        u.w = f2tf32(v.w);
        d[off] = u;
    }
}

// ---------------- CPB MLP -------------------------------------------------------
__device__ __forceinline__ float cpb_coord(int i) {
    float v = (float)(i - 6) * (8.0f / 6.0f);
    float av = fabsf(v);
    float r = log2f(av + 1.0f) * (1.0f / 3.0f);
    return (v < 0.f) ? -r : r;
}

__global__ void __launch_bounds__(256) cpb_kernel(const float* __restrict__ w1,
                                                  const float* __restrict__ b1,
                                                  const float* __restrict__ w2) {
    __shared__ float hid[512];
    int t = blockIdx.x;
    int a = t / 169;
    int rem = t - a * 169;
    int b = rem / 13;
    int c = rem - b * 13;
    float c0 = cpb_coord(a), c1 = cpb_coord(b), c2 = cpb_coord(c);
    for (int j = threadIdx.x; j < 512; j += blockDim.x) {
        float hv = c0 * w1[j * 3 + 0] + c1 * w1[j * 3 + 1] + c2 * w1[j * 3 + 2] + b1[j];
        hid[j] = fmaxf(hv, 0.f);
    }
    __syncthreads();
    if (threadIdx.x < 192) {
        int hh = threadIdx.x >> 5, lane = threadIdx.x & 31;
        float s = 0.f;
        for (int j = lane; j < 512; j += 32) s += hid[j] * w2[hh * 512 + j];
#pragma unroll
        for (int off = 16; off; off >>= 1) s += __shfl_xor_sync(FULLMASK, s, off);
        if (lane == 0) g_hb[t * 6 + hh] = s;
    }
}

// rpb in log2 units (pre-scaled by LOG2E for exp2f softmax)
__global__ void rpb_kernel() {
    const int total = 6 * 343 * RPBS;
    for (int idx = blockIdx.x * blockDim.x + threadIdx.x; idx < total;
         idx += gridDim.x * blockDim.x) {
        int hh = idx / (343 * RPBS);
        int rem = idx - hh * (343 * RPBS);
        int i = rem / RPBS;
        int j = rem - i * RPBS;
        if (j >= 343) {
            g_rpb[idx] = 0.f;
            continue;
        }
        int dh = i / 49 - j / 49 + 6;
        int dw = (i / 7) % 7 - (j / 7) % 7 + 6;
        int dd = i % 7 - j % 7 + 6;
        int tix = (dh * 13 + dw) * 13 + dd;
        float v = g_hb[tix * 6 + hh];
        g_rpb[idx] = (16.f / (1.f + __expf(-v))) * LOG2E;
    }
}

// ---------------- tf32 mma GEMM, 512 threads, BN=192, BK=32, cp.async ------------
// MODE 0: QKV (A = g_xt gathered; W = g_wq; out -> g_q/g_k/g_v + biases; sct=blockIdx.x)
// MODE 1: FC1 (A = g_x1t; W = g_w1; out -> g_hmid tf32-rounded with GELU)
#define BM 128
#define BK2 32
#define SPAD2 36
#define A2_WORDS (BM * SPAD2)      // 4608
#define BL_WORDS (192 * SPAD2)     // 6912
#define G5_SMEM (3 * (A2_WORDS + BL_WORDS) * 4)          // 138240
#define LN_SMEM ((3 * (A2_WORDS + BL_WORDS) + 1024) * 4) // 142336

template <int MODE>
__global__ void __launch_bounds__(512) mma_gemm512(const float* __restrict__ bias1,
                                                   const float* __restrict__ bias2,
                                                   int K) {
    extern __shared__ uint32_t sh[];
    uint32_t* As = sh;
    uint32_t* Bs = sh + 3 * A2_WORDS;
    const uint32_t sbA = smem_u32(As);
    const uint32_t sbB = smem_u32(Bs);

    const int tid = threadIdx.x;
    const int lane = tid & 31;
    const int warp = tid >> 5;      // 0..15
    const int warpM = warp & 3;
    const int warpN = warp >> 2;    // 0..3
    const int gr = lane >> 2;
    const int tg = lane & 3;

    const int m0 = blockIdx.y * BM;
    const int n0 = blockIdx.x * 192;

    const float* Asrc = (MODE == 0) ? g_xt : g_x1t;
    const float* W = (MODE == 0) ? g_wq : g_w1;

    // A: 2 chunks of 16B per thread per tile (128 rows x 8 chunks = 1024)
    const float* aptr[2];
    uint32_t aoffB[2];
#pragma unroll
    for (int i = 0; i < 2; ++i) {
        int idx = tid + i * 512;
        int arow = idx >> 3, c8 = idx & 7;
        int rho = m0 + arow;
        const float* p;
        if (MODE == 0) {
            int b_ = rho / 343, n = rho - b_ * 343;
            int bb = b_ >> 6, win = b_ & 63;
            int wa = win >> 4, wb = (win >> 2) & 3, wc = win & 3;
            int ii = n / 49, jj = (n / 7) % 7, kk = n % 7;
            int hs = (wa * 7 + ii + 3) % 28;
            int ws = (wb * 7 + jj + 3) % 28;
            int ds = (wc * 7 + kk + 3) % 28;
            p = Asrc + ((size_t)bb * LTOT + (hs * 784 + ws * 28 + ds)) * CDIM;
        } else {
            p = Asrc + (size_t)rho * K;
        }
        aptr[i] = p + c8 * 4;
        aoffB[i] = (arow * SPAD2 + c8 * 4) * 4;
    }
    // B: 3 chunks per thread per tile (192 rows x 8 chunks = 1536)
    const float* bptr[3];
    uint32_t boff[3];
#pragma unroll
    for (int i = 0; i < 3; ++i) {
        int idx = tid + i * 512;
        int brow = idx >> 3, c8 = idx & 7;
        bptr[i] = W + (size_t)(n0 + brow) * K + c8 * 4;
        boff[i] = (brow * SPAD2 + c8 * 4) * 4;
    }

    float acc[2][6][4];
#pragma unroll
    for (int mi = 0; mi < 2; ++mi)
#pragma unroll
        for (int ni = 0; ni < 6; ++ni)
#pragma unroll
            for (int e = 0; e < 4; ++e) acc[mi][ni][e] = 0.f;

    const int ntiles = K >> 5;
#pragma unroll
    for (int s = 0; s < 2; ++s) {
        const int kt = s * BK2;
#pragma unroll
        for (int i = 0; i < 2; ++i) cp16(sbA + s * (A2_WORDS * 4) + aoffB[i], aptr[i] + kt);
#pragma unroll
        for (int i = 0; i < 3; ++i) cp16(sbB + s * (BL_WORDS * 4) + boff[i], bptr[i] + kt);
        CP_COMMIT();
    }

    for (int t = 0; t < ntiles; ++t) {
        const int buf = t % 3;
        CP_WAIT1();
        __syncthreads();

        const uint32_t* Ab = As + buf * A2_WORDS;
        const uint32_t* Bb = Bs + buf * BL_WORDS;
#pragma unroll
        for (int kk = 0; kk < 32; kk += 8) {
            uint32_t afr[2][4];
#pragma unroll
            for (int mi = 0; mi < 2; ++mi) {
                int rb = warpM * 32 + mi * 16;
                afr[mi][0] = Ab[(rb + gr) * SPAD2 + kk + tg];
                afr[mi][1] = Ab[(rb + gr + 8) * SPAD2 + kk + tg];
                afr[mi][2] = Ab[(rb + gr) * SPAD2 + kk + tg + 4];
                afr[mi][3] = Ab[(rb + gr + 8) * SPAD2 + kk + tg + 4];
            }
            uint32_t bfr[6][2];
#pragma unroll
            for (int ni = 0; ni < 6; ++ni) {
                int nb = warpN * 48 + ni * 8 + gr;
                bfr[ni][0] = Bb[nb * SPAD2 + kk + tg];
                bfr[ni][1] = Bb[nb * SPAD2 + kk + tg + 4];
            }
#pragma unroll
            for (int mi = 0; mi < 2; ++mi)
#pragma unroll
                for (int ni = 0; ni < 6; ++ni)
                    mma_tf32(acc[mi][ni], afr[mi], bfr[ni]);
        }

        const int tn = t + 2;
        if (tn < ntiles) {
            const int s = tn % 3;
            const int kt = tn * BK2;
#pragma unroll
            for (int i = 0; i < 2; ++i)
                cp16(sbA + s * (A2_WORDS * 4) + aoffB[i], aptr[i] + kt);
#pragma unroll
            for (int i = 0; i < 3; ++i)
                cp16(sbB + s * (BL_WORDS * 4) + boff[i], bptr[i] + kt);
        }
        CP_COMMIT();
    }

    // ---------------- epilogue ----------------------------------------------------
    const int sct = blockIdx.x;   // QKV: 0=q,1=k,2=v (192 cols each)
#pragma unroll
    for (int mi = 0; mi < 2; ++mi) {
        int rows[2];
        rows[0] = m0 + warpM * 32 + mi * 16 + gr;
        rows[1] = rows[0] + 8;
#pragma unroll
        for (int half = 0; half < 2; ++half) {
            const int r = rows[half];
            int b_ = 0, n = 0;
            if (MODE == 0) {
                b_ = r / 343;
                n = r - b_ * 343;
            }
#pragma unroll
            for (int ni = 0; ni < 6; ++ni) {
                int remc = warpN * 48 + ni * 8 + tg * 2;
                float v0 = acc[mi][ni][half * 2 + 0];
                float v1 = acc[mi][ni][half * 2 + 1];
                if (MODE == 0) {
                    int hh = remc >> 5, dd = remc & 31;
                    float* dst = (sct == 0 ? g_q : (sct == 1 ? g_k : g_v)) +
                                 ((size_t)(b_ * 6 + hh) * NTOK + n) * HD + dd;
                    float e0 = 0.f, e1 = 0.f;
                    if (sct == 0) { e0 = bias1[remc]; e1 = bias1[remc + 1]; }
                    else if (sct == 2) { e0 = bias2[remc]; e1 = bias2[remc + 1]; }
                    *(float2*)dst = make_float2(v0 + e0, v1 + e1);
                } else {
                    int c = n0 + remc;
                    float x0 = v0 + bias1[c], x1 = v1 + bias1[c + 1];
                    float g0 = 0.5f * x0 * (1.f + erff(x0 * 0.70710678118654752f));
                    float g1 = 0.5f * x1 * (1.f + erff(x1 * 0.70710678118654752f));
                    *(float2*)(g_hmid + (size_t)r * 768 + c) =
                        make_float2(__uint_as_float(f2tf32(g0)),
                                    __uint_as_float(f2tf32(g1)));
                }
            }
        }
    }
}

// ---------------- GEMM (BN=192) + fused LayerNorm + residual, BK=32 --------------
// MODE 0: PROJ  g_x1[pos] = x[pos] + LN(acc+bias) (window-reverse scatter); also g_x1t
// MODE 1: FC2   out[row] = g_x1[row] + LN(acc+bias)
template <int MODE>
__global__ void __launch_bounds__(512) gemm_ln(const float* __restrict__ bias,
                                               const float* __restrict__ basex,
                                               const float* __restrict__ gw,
                                               const float* __restrict__ bw,
                                               float* __restrict__ outp,
                                               int K) {
    extern __shared__ uint32_t sh[];
    uint32_t* Asm = sh;
    uint32_t* Bsm = sh + 3 * A2_WORDS;
    float* part = (float*)(sh + 3 * A2_WORDS + 3 * BL_WORDS);  // [128][4][2]
    const uint32_t sbA = smem_u32(Asm);
    const uint32_t sbB = smem_u32(Bsm);

    const int tid = threadIdx.x;
    const int lane = tid & 31;
    const int warp = tid >> 5;
    const int warpM = warp & 3;
    const int warpN = warp >> 2;
    const int gr = lane >> 2;
    const int tg = lane & 3;

    const int m0 = blockIdx.x * BM;

    const float* Asrc = (MODE == 0) ? g_attnout : g_hmid;
    const float* W = (MODE == 0) ? g_wp : g_w2;

    const float* aptr[2];
    uint32_t aoff[2];
#pragma unroll
    for (int i = 0; i < 2; ++i) {
        int idx = tid + i * 512;
        int arow = idx >> 3, c8 = idx & 7;
        aptr[i] = Asrc + (size_t)(m0 + arow) * K + c8 * 4;
        aoff[i] = (arow * SPAD2 + c8 * 4) * 4;
    }
    const float* bptr[3];
    uint32_t boff[3];
#pragma unroll
    for (int i = 0; i < 3; ++i) {
        int idx = tid + i * 512;
        int brow = idx >> 3, c8 = idx & 7;
        bptr[i] = W + (size_t)brow * K + c8 * 4;
        boff[i] = (brow * SPAD2 + c8 * 4) * 4;
    }

    float acc[2][6][4];
#pragma unroll
    for (int mi = 0; mi < 2; ++mi)
#pragma unroll
        for (int ni = 0; ni < 6; ++ni)
#pragma unroll
            for (int e = 0; e < 4; ++e) acc[mi][ni][e] = 0.f;

    const int ntiles = K >> 5;
#pragma unroll
    for (int s = 0; s < 2; ++s) {
        const int kt = s * BK2;
#pragma unroll
        for (int i = 0; i < 2; ++i) cp16(sbA + s * (A2_WORDS * 4) + aoff[i], aptr[i] + kt);
#pragma unroll
        for (int i = 0; i < 3; ++i) cp16(sbB + s * (BL_WORDS * 4) + boff[i], bptr[i] + kt);
        CP_COMMIT();
    }

    for (int t = 0; t < ntiles; ++t) {
        const int buf = t % 3;
        CP_WAIT1();
        __syncthreads();

        const uint32_t* Ab = Asm + buf * A2_WORDS;
        const uint32_t* Bb = Bsm + buf * BL_WORDS;
#pragma unroll
        for (int kk = 0; kk < 32; kk += 8) {
            uint32_t afr[2][4];
#pragma unroll
            for (int mi = 0; mi < 2; ++mi) {
                int rb = warpM * 32 + mi * 16;
                afr[mi][0] = Ab[(rb + gr) * SPAD2 + kk + tg];
                afr[mi][1] = Ab[(rb + gr + 8) * SPAD2 + kk + tg];
                afr[mi][2] = Ab[(rb + gr) * SPAD2 + kk + tg + 4];
                afr[mi][3] = Ab[(rb + gr + 8) * SPAD2 + kk + tg + 4];
            }
            uint32_t bfr[6][2];
#pragma unroll
            for (int ni = 0; ni < 6; ++ni) {
                int nb = warpN * 48 + ni * 8 + gr;
                bfr[ni][0] = Bb[nb * SPAD2 + kk + tg];
                bfr[ni][1] = Bb[nb * SPAD2 + kk + tg + 4];
            }
#pragma unroll
            for (int mi = 0; mi < 2; ++mi)
#pragma unroll
                for (int ni = 0; ni < 6; ++ni)
                    mma_tf32(acc[mi][ni], afr[mi], bfr[ni]);
        }

        const int tn = t + 2;
        if (tn < ntiles) {
            const int s = tn % 3;
            const int kt = tn * BK2;
#pragma unroll
            for (int i = 0; i < 2; ++i)
                cp16(sbA + s * (A2_WORDS * 4) + aoff[i], aptr[i] + kt);
#pragma unroll
            for (int i = 0; i < 3; ++i)
                cp16(sbB + s * (BL_WORDS * 4) + boff[i], bptr[i] + kt);
        }
        CP_COMMIT();
    }
    __syncthreads();

    // ---------------- fused bias + LN partials -------------------------------------
#pragma unroll
    for (int mi = 0; mi < 2; ++mi) {
#pragma unroll
        for (int half = 0; half < 2; ++half) {
            const int rl = warpM * 32 + mi * 16 + gr + half * 8;
            float s = 0.f, sq = 0.f;
#pragma unroll
            for (int ni = 0; ni < 6; ++ni) {
                int c = warpN * 48 + ni * 8 + tg * 2;
                float v0 = acc[mi][ni][half * 2 + 0] + bias[c];
                float v1 = acc[mi][ni][half * 2 + 1] + bias[c + 1];
                acc[mi][ni][half * 2 + 0] = v0;
                acc[mi][ni][half * 2 + 1] = v1;
                s += v0 + v1;
                sq += v0 * v0 + v1 * v1;
            }
            s += __shfl_xor_sync(FULLMASK, s, 1);
            s += __shfl_xor_sync(FULLMASK, s, 2);
            sq += __shfl_xor_sync(FULLMASK, sq, 1);
            sq += __shfl_xor_sync(FULLMASK, sq, 2);
            if (tg == 0) {
                part[(rl * 4 + warpN) * 2 + 0] = s;
                part[(rl * 4 + warpN) * 2 + 1] = sq;
            }
        }
    }
    __syncthreads();

#pragma unroll
    for (int mi = 0; mi < 2; ++mi) {
#pragma unroll
        for (int half = 0; half < 2; ++half) {
            const int rl = warpM * 32 + mi * 16 + gr + half * 8;
            const int r = m0 + rl;
            float s = 0.f, sq = 0.f;
#pragma unroll
            for (int g2 = 0; g2 < 4; ++g2) {
                s += part[(rl * 4 + g2) * 2 + 0];
                sq += part[(rl * 4 + g2) * 2 + 1];
            }
            float mean = s * (1.f / 192.f);
            float var = sq * (1.f / 192.f) - mean * mean;
            float inv = rsqrtf(var + 1e-5f);

            const float* bsrow;
            float* orow;
            float* orow2 = nullptr;
            if (MODE == 0) {
                int b_ = r / 343, n = r - b_ * 343;
                int bb2 = b_ >> 6, win = b_ & 63;
                int wa = win >> 4, wb = (win >> 2) & 3, wc = win & 3;
                int i3 = n / 49, j3 = (n / 7) % 7, k3 = n % 7;
                int hd_ = (wa * 7 + i3 + 3) % 28;
                int wd_ = (wb * 7 + j3 + 3) % 28;
                int dd_ = (wc * 7 + k3 + 3) % 28;
                size_t pos = ((size_t)bb2 * LTOT + (hd_ * 784 + wd_ * 28 + dd_)) * CDIM;
                bsrow = basex + pos;
                orow = g_x1 + pos;
                orow2 = g_x1t + pos;
            } else {
                bsrow = g_x1 + (size_t)r * CDIM;
                orow = outp + (size_t)r * CDIM;
            }
#pragma unroll
            for (int ni = 0; ni < 6; ++ni) {
                int c = warpN * 48 + ni * 8 + tg * 2;
                float v0 = acc[mi][ni][half * 2 + 0];
                float v1 = acc[mi][ni][half * 2 + 1];
                float2 bse = *(const float2*)(bsrow + c);
                float2 gg = *(const float2*)(gw + c);
                float2 bb = *(const float2*)(bw + c);
                float o0 = bse.x + (v0 - mean) * inv * gg.x + bb.x;
                float o1 = bse.y + (v1 - mean) * inv * gg.y + bb.y;
                *(float2*)(orow + c) = make_float2(o0, o1);
                if (MODE == 0)
                    *(float2*)(orow2 + c) =
                        make_float2(__uint_as_float(f2tf32(o0)),
                                    __uint_as_float(f2tf32(o1)));
            }
        }
    }
}

// ---------------- tensor-core flash attention (static max, exp2) -----------------
#define KS_WORDS (384 * 36)
#define VT_WORDS (32 * 388)
#define ATTN4_SMEM ((KS_WORDS + VT_WORDS) * 4 + 512)

__global__ void __launch_bounds__(256, 2) attn4_kernel(const float* __restrict__ logit_scale) {
    extern __shared__ uint32_t asmem[];
    uint32_t* Ks = asmem;                       // [384][36]
    uint32_t* Vt = asmem + KS_WORDS;            // [32][388]
    unsigned char* region = (unsigned char*)(Vt + VT_WORDS);

    const int bh = blockIdx.x;
    const int b_ = bh / 6, h = bh - (bh / 6) * 6;
    const int tid = threadIdx.x;
    const int lane = tid & 31, warp = tid >> 5;
    const int gr = lane >> 2, tg = lane & 3;

    const size_t kvbase = (size_t)bh * (NTOK * HD);
    const float* kg = g_k + kvbase;
    const float* vg = g_v + kvbase;
    const float* qg = g_q + kvbase;

    for (int r = warp; r < 384; r += 8) {
        if (r < NTOK) {
            float v = kg[r * 32 + lane];
            float s = v * v;
#pragma unroll
            for (int o = 16; o; o >>= 1) s += __shfl_xor_sync(FULLMASK, s, o);
            float inv = 1.f / fmaxf(sqrtf(s), 1e-12f);
            Ks[r * 36 + lane] = f2tf32(v * inv);
        } else {
            Ks[r * 36 + lane] = 0u;
        }
    }
    for (int idx = tid; idx < NTOK * 32; idx += 256) {
        int j = idx >> 5, d = idx & 31;
        Vt[d * 388 + j] = f2tf32(vg[idx]);
    }
    for (int idx = tid; idx < 32 * 45; idx += 256) {
        int d = idx / 45, j = NTOK + idx - (idx / 45) * 45;
        Vt[d * 388 + j] = 0u;
    }
    const int win = b_ & 63;
    const int wa = win >> 4, wb = (win >> 2) & 3, wc = win & 3;
    const bool maskedw = (wa == 3) || (wb == 3) || (wc == 3);
    if (maskedw) {
        for (int t = tid; t < 384; t += 256) {
            if (t < NTOK) {
                int ih = t / 49, iw = (t / 7) % 7, id = t % 7;
                int rH = (wa < 3) ? 0 : ((ih < 4) ? 1 : 2);
                int rW = (wb < 3) ? 0 : ((iw < 4) ? 1 : 2);
                int rD = (wc < 3) ? 0 : ((id < 4) ? 1 : 2);
                region[t] = (unsigned char)(rH * 9 + rW * 3 + rD);
            } else {
                region[t] = 0;
            }
        }
    }
    __syncthreads();

    const float scale = __expf(fminf(logit_scale[h], 4.6051701859880914f));
    const float Mstat = (scale + 16.f) * LOG2E;   // static bound, log2 units
    const float* rpbh = g_rpb + (size_t)h * (343 * RPBS);

    for (int rb = 0; rb < 3; ++rb) {
        const int r0 = rb * 128 + warp * 16;
        if (r0 >= NTOK) continue;

        const int r_lo = r0 + gr, r_hi = r0 + gr + 8;
        const bool v_lo = r_lo < NTOK, v_hi = r_hi < NTOK;

        float qf[4][4];
        const float* qlo = qg + (size_t)(v_lo ? r_lo : 0) * 32;
        const float* qhi = qg + (size_t)(v_hi ? r_hi : 0) * 32;
#pragma unroll
        for (int kk = 0; kk < 4; ++kk) {
            qf[kk][0] = v_lo ? qlo[kk * 8 + tg] : 0.f;
            qf[kk][1] = v_hi ? qhi[kk * 8 + tg] : 0.f;
            qf[kk][2] = v_lo ? qlo[kk * 8 + tg + 4] : 0.f;
            qf[kk][3] = v_hi ? qhi[kk * 8 + tg + 4] : 0.f;
        }
        float s0 = 0.f, s1 = 0.f;
#pragma unroll
        for (int kk = 0; kk < 4; ++kk) {
            s0 += qf[kk][0] * qf[kk][0] + qf[kk][2] * qf[kk][2];
            s1 += qf[kk][1] * qf[kk][1] + qf[kk][3] * qf[kk][3];
        }
        s0 += __shfl_xor_sync(FULLMASK, s0, 1);
        s0 += __shfl_xor_sync(FULLMASK, s0, 2);
        s1 += __shfl_xor_sync(FULLMASK, s1, 1);
        s1 += __shfl_xor_sync(FULLMASK, s1, 2);
        const float i0 = scale * LOG2E / fmaxf(sqrtf(s0), 1e-12f);
        const float i1 = scale * LOG2E / fmaxf(sqrtf(s1), 1e-12f);
        uint32_t aQ[4][4];
#pragma unroll
        for (int kk = 0; kk < 4; ++kk) {
            aQ[kk][0] = f2tf32(qf[kk][0] * i0);
            aQ[kk][1] = f2tf32(qf[kk][1] * i1);
            aQ[kk][2] = f2tf32(qf[kk][2] * i0);
            aQ[kk][3] = f2tf32(qf[kk][3] * i1);
        }

        unsigned char rq0 = 0, rq1 = 0;
        if (maskedw) {
            rq0 = region[v_lo ? r_lo : (NTOK - 1)];
            rq1 = region[v_hi ? r_hi : (NTOK - 1)];
        }
        const float* rpr_lo = rpbh + (size_t)(v_lo ? r_lo : 0) * RPBS;
        const float* rpr_hi = rpbh + (size_t)(v_hi ? r_hi : 0) * RPBS;

        float l0 = 0.f, l1 = 0.f;
        float o[4][4];
#pragma unroll
        for (int nt = 0; nt < 4; ++nt)
#pragma unroll
            for (int e = 0; e < 4; ++e) o[nt][e] = 0.f;

        for (int ch = 0; ch < 6; ++ch) {
            const int j0 = ch * 64;
            float s[8][4];
#pragma unroll
            for (int nt = 0; nt < 8; ++nt)
#pragma unroll
                for (int e = 0; e < 4; ++e) s[nt][e] = 0.f;
#pragma unroll
            for (int kk = 0; kk < 4; ++kk) {
#pragma unroll
                for (int nt = 0; nt < 8; ++nt) {
                    uint32_t bb[2];
                    bb[0] = Ks[(j0 + nt * 8 + gr) * 36 + kk * 8 + tg];
                    bb[1] = Ks[(j0 + nt * 8 + gr) * 36 + kk * 8 + tg + 4];
                    mma_tf32(s[nt], aQ[kk], bb);
                }
            }
            // bias + mask + exp2(static max) + per-thread sums
#pragma unroll
            for (int nt = 0; nt < 8; ++nt) {
                const int jc = j0 + nt * 8 + tg * 2;
                float2 blo = *(const float2*)(rpr_lo + jc);
                float2 bhi = *(const float2*)(rpr_hi + jc);
                float t0 = s[nt][0] + blo.x - Mstat;
                float t1 = s[nt][1] + blo.y - Mstat;
                float t2 = s[nt][2] + bhi.x - Mstat;
                float t3 = s[nt][3] + bhi.y - Mstat;
                if (maskedw) {
                    unsigned char rk0 = region[jc];
                    unsigned char rk1 = region[jc + 1];
                    if (rk0 != rq0) t0 -= 144.26950408f;
                    if (rk1 != rq0) t1 -= 144.26950408f;
                    if (rk0 != rq1) t2 -= 144.26950408f;
                    if (rk1 != rq1) t3 -= 144.26950408f;
                }
                float p0 = exp2f(t0);
                float p1 = exp2f(t1);
                float p2 = exp2f(t2);
                float p3 = exp2f(t3);
                if (ch == 5) {
                    if (jc >= NTOK) { p0 = 0.f; p2 = 0.f; }
                    if (jc + 1 >= NTOK) { p1 = 0.f; p3 = 0.f; }
                }
                l0 += p0 + p1;
                l1 += p2 + p3;
                s[nt][0] = p0;
                s[nt][1] = p1;
                s[nt][2] = p2;
                s[nt][3] = p3;
            }
            // O += P * V : acc-frag -> A-frag via intra-quad shuffles
            const int src0 = (lane & ~3) | (tg >> 1);
            const int src2 = src0 + 2;
            const bool odd = (tg & 1);
#pragma unroll
            for (int kk = 0; kk < 8; ++kk) {
                float v00 = __shfl_sync(FULLMASK, s[kk][0], src0);
                float v01 = __shfl_sync(FULLMASK, s[kk][1], src0);
                float v20 = __shfl_sync(FULLMASK, s[kk][0], src2);
                float v21 = __shfl_sync(FULLMASK, s[kk][1], src2);
                float v10 = __shfl_sync(FULLMASK, s[kk][2], src0);
                float v11 = __shfl_sync(FULLMASK, s[kk][3], src0);
                float v30 = __shfl_sync(FULLMASK, s[kk][2], src2);
                float v31 = __shfl_sync(FULLMASK, s[kk][3], src2);
                uint32_t aP[4];
                aP[0] = f2tf32(odd ? v01 : v00);
                aP[1] = f2tf32(odd ? v11 : v10);
                aP[2] = f2tf32(odd ? v21 : v20);
                aP[3] = f2tf32(odd ? v31 : v30);
#pragma unroll
                for (int nt = 0; nt < 4; ++nt) {
                    uint32_t bb[2];
                    bb[0] = Vt[(nt * 8 + gr) * 388 + j0 + kk * 8 + tg];
                    bb[1] = Vt[(nt * 8 + gr) * 388 + j0 + kk * 8 + tg + 4];
                    mma_tf32(o[nt], aP, bb);
                }
            }
        }

        // single end-of-loop row-sum reduction
        l0 += __shfl_xor_sync(FULLMASK, l0, 1);
        l0 += __shfl_xor_sync(FULLMASK, l0, 2);
        l1 += __shfl_xor_sync(FULLMASK, l1, 1);
        l1 += __shfl_xor_sync(FULLMASK, l1, 2);

        if (v_lo) {
            const float il0 = 1.f / l0;
            float* dst = g_attnout + ((size_t)b_ * NTOK + r_lo) * CDIM + h * HD;
#pragma unroll
            for (int nt = 0; nt < 4; ++nt)
                *(float2*)(dst + nt * 8 + tg * 2) =
                    make_float2(__uint_as_float(f2tf32(o[nt][0] * il0)),
                                __uint_as_float(f2tf32(o[nt][1] * il0)));
        }
        if (v_hi) {
            const float il1 = 1.f / l1;
            float* dst = g_attnout + ((size_t)b_ * NTOK + r_hi) * CDIM + h * HD;
#pragma unroll
            for (int nt = 0; nt < 4; ++nt)
                *(float2*)(dst + nt * 8 + tg * 2) =
                    make_float2(__uint_as_float(f2tf32(o[nt][2] * il1)),
                                __uint_as_float(f2tf32(o[nt][3] * il1)));
        }
    }
}

// ---------------- launch ---------------------------------------------------------
extern "C" void kernel_launch(void* const* d_in, const int* in_sizes, int n_in,
                              void* d_out, int out_size) {
    (void)in_sizes; (void)n_in; (void)out_size;
    const float* x = (const float*)d_in[0];
    const float* qkv_w = (const float*)d_in[1];
    const float* q_bias = (const float*)d_in[2];
    const float* v_bias = (const float*)d_in[3];
    const float* logit_scale = (const float*)d_in[4];
    const float* cpb_w1 = (const float*)d_in[5];
    const float* cpb_b1 = (const float*)d_in[6];
    const float* cpb_w2 = (const float*)d_in[7];
    const float* proj_w = (const float*)d_in[8];
    const float* proj_b = (const float*)d_in[9];
    const float* norm1_g = (const float*)d_in[10];
    const float* norm1_b = (const float*)d_in[11];
    const float* fc1_w = (const float*)d_in[12];
    const float* fc1_b = (const float*)d_in[13];
    const float* fc2_w = (const float*)d_in[14];
    const float* fc2_b = (const float*)d_in[15];
    const float* norm2_g = (const float*)d_in[16];
    const float* norm2_b = (const float*)d_in[17];
    float* out = (float*)d_out;

    static bool attr_done = false;
    if (!attr_done) {
        cudaFuncSetAttribute(attn4_kernel, cudaFuncAttributeMaxDynamicSharedMemorySize,
                             ATTN4_SMEM);
        cudaFuncSetAttribute(mma_gemm512<0>, cudaFuncAttributeMaxDynamicSharedMemorySize,
                             G5_SMEM);
        cudaFuncSetAttribute(mma_gemm512<1>, cudaFuncAttributeMaxDynamicSharedMemorySize,
                             G5_SMEM);
        cudaFuncSetAttribute(gemm_ln<0>, cudaFuncAttributeMaxDynamicSharedMemorySize,
                             LN_SMEM);
        cudaFuncSetAttribute(gemm_ln<1>, cudaFuncAttributeMaxDynamicSharedMemorySize,
                             LN_SMEM);
        attr_done = true;
    }

    // tf32 pre-conversion of all GEMM operands (one fused kernel)
    cvt_all<<<1024, 256>>>(x, qkv_w, proj_w, fc1_w, fc2_w);

    // constants
    cpb_kernel<<<2197, 256>>>(cpb_w1, cpb_b1, cpb_w2);
    rpb_kernel<<<888, 256>>>();

    // qkv (fused shift + window gather): M=43904, N=576 (3 x 192), K=192
    mma_gemm512<0><<<dim3(3, 343), 512, G5_SMEM>>>(q_bias, v_bias, 192);

    // attention (tensor-core flash, static max, exp2)
    attn4_kernel<<<768, 256, ATTN4_SMEM>>>(logit_scale);

    // proj + LN + residual (fused window reverse + roll scatter): N=192, K=192
    gemm_ln<0><<<343, 512, LN_SMEM>>>(proj_b, x, norm1_g, norm1_b, nullptr, 192);

    // fc1: N=768 (4 x 192), K=192 (GELU)
    mma_gemm512<1><<<dim3(4, 343), 512, G5_SMEM>>>(fc1_b, nullptr, 192);

    // fc2 + LN + residual: N=192, K=768
    gemm_ln<1><<<343, 512, LN_SMEM>>>(fc2_b, nullptr, norm2_g, norm2_b, out, 768);
}

// round 13
// speedup vs baseline: 1.0281x; 1.0281x over previous
#include <cuda_runtime.h>
#include <math.h>
#include <stdint.h>

#define FULLMASK 0xffffffffu
#define LOG2E 1.4426950408889634f

// problem dims
#define NTOK   343
#define NHEAD  6
#define HD     32
#define CDIM   192
#define LTOT   21952
#define NWIN   128
#define NROWS  43904
#define RPBS   344

// ---------------- device scratch ------------------------------------------------
__device__ float g_hb[2197 * 6];
__device__ __align__(16) float g_rpb[6 * 343 * RPBS];
__device__ __align__(16) float g_q[(size_t)NWIN * NHEAD * NTOK * HD];
__device__ __align__(16) float g_k[(size_t)NWIN * NHEAD * NTOK * HD];
__device__ __align__(16) float g_v[(size_t)NWIN * NHEAD * NTOK * HD];
__device__ __align__(16) float g_attnout[(size_t)NWIN * NTOK * CDIM];   // tf32-rounded
__device__ __align__(16) float g_x1[(size_t)2 * LTOT * CDIM];           // fp32
__device__ __align__(16) float g_x1t[(size_t)2 * LTOT * CDIM];          // tf32-rounded
__device__ __align__(16) float g_xt[(size_t)2 * LTOT * CDIM];           // tf32-rounded
__device__ __align__(16) float g_hmid[(size_t)NROWS * 768];             // tf32-rounded
__device__ __align__(16) float g_wq[576 * 192];
__device__ __align__(16) float g_wp[192 * 192];
__device__ __align__(16) float g_w1[768 * 192];
__device__ __align__(16) float g_w2[192 * 768];

// ---------------- helpers -------------------------------------------------------
__device__ __forceinline__ uint32_t f2tf32(float x) {
    uint32_t r;
    asm("cvt.rna.tf32.f32 %0, %1;" : "=r"(r) : "f"(x));
    return r;
}

__device__ __forceinline__ void mma_tf32(float* c, const uint32_t* a, const uint32_t* b) {
    asm volatile(
        "mma.sync.aligned.m16n8k8.row.col.f32.tf32.tf32.f32 "
        "{%0,%1,%2,%3}, {%4,%5,%6,%7}, {%8,%9}, {%0,%1,%2,%3};"
        : "+f"(c[0]), "+f"(c[1]), "+f"(c[2]), "+f"(c[3])
        : "r"(a[0]), "r"(a[1]), "r"(a[2]), "r"(a[3]), "r"(b[0]), "r"(b[1]));
}

__device__ __forceinline__ uint32_t smem_u32(const void* p) {
    uint32_t a;
    asm("{ .reg .u64 t; cvta.to.shared.u64 t, %1; cvt.u32.u64 %0, t; }" : "=r"(a) : "l"(p));
    return a;
}

__device__ __forceinline__ void cp16(uint32_t dst, const void* src) {
    asm volatile("cp.async.ca.shared.global [%0], [%1], 16;" :: "r"(dst), "l"(src));
}
#define CP_COMMIT() asm volatile("cp.async.commit_group;" ::: "memory")
#define CP_WAIT1()  asm volatile("cp.async.wait_group 1;" ::: "memory")

// ---------------- CPB coord helper ----------------------------------------------
__device__ __forceinline__ float cpb_coord(int i) {
    float v = (float)(i - 6) * (8.0f / 6.0f);
    float av = fabsf(v);
    float r = log2f(av + 1.0f) * (1.0f / 3.0f);
    return (v < 0.f) ? -r : r;
}

// ---------------- fused tf32 convert + CPB MLP kernel ----------------------------
// blocks [0, 1024): grid-stride tf32 conversion of x + 4 weights
// blocks [1024, 1024+2197): CPB MLP table row -> g_hb
__global__ void __launch_bounds__(256) cvt_cpb(const float* __restrict__ x,
                                               const float* __restrict__ wq,
                                               const float* __restrict__ wp,
                                               const float* __restrict__ w1cv,
                                               const float* __restrict__ w2cv,
                                               const float* __restrict__ cw1,
                                               const float* __restrict__ cb1,
                                               const float* __restrict__ cw2) {
    __shared__ float hid[512];
    if (blockIdx.x >= 1024) {
        // ---- CPB MLP ----
        int t = blockIdx.x - 1024;
        int a = t / 169;
        int rem = t - a * 169;
        int b = rem / 13;
        int c = rem - b * 13;
        float c0 = cpb_coord(a), c1 = cpb_coord(b), c2 = cpb_coord(c);
        for (int j = threadIdx.x; j < 512; j += blockDim.x) {
            float hv = c0 * cw1[j * 3 + 0] + c1 * cw1[j * 3 + 1] + c2 * cw1[j * 3 + 2] +
                       cb1[j];
            hid[j] = fmaxf(hv, 0.f);
        }
        __syncthreads();
        if (threadIdx.x < 192) {
            int hh = threadIdx.x >> 5, lane = threadIdx.x & 31;
            float s = 0.f;
            for (int j = lane; j < 512; j += 32) s += hid[j] * cw2[hh * 512 + j];
#pragma unroll
            for (int off = 16; off; off >>= 1) s += __shfl_xor_sync(FULLMASK, s, off);
            if (lane == 0) g_hb[t * 6 + hh] = s;
        }
        return;
    }
    // ---- tf32 conversion ----
    const int N0 = 2107392;            // x: 2*LTOT*CDIM/4
    const int N1 = N0 + 27648;         // wq
    const int N2 = N1 + 9216;          // wp
    const int N3 = N2 + 36864;         // w1
    const int N4 = N3 + 36864;         // w2
    for (int i = blockIdx.x * blockDim.x + threadIdx.x; i < N4; i += 1024 * 256) {
        const float4* s;
        uint4* d;
        int off;
        if (i < N0) { s = (const float4*)x; d = (uint4*)g_xt; off = i; }
        else if (i < N1) { s = (const float4*)wq; d = (uint4*)g_wq; off = i - N0; }
        else if (i < N2) { s = (const float4*)wp; d = (uint4*)g_wp; off = i - N1; }
        else if (i < N3) { s = (const float4*)w1cv; d = (uint4*)g_w1; off = i - N2; }
        else { s = (const float4*)w2cv; d = (uint4*)g_w2; off = i - N3; }
        float4 v = s[off];
        uint4 u;
        u.x = f2tf32(v.x);
        u.y = f2tf32(v.y);
        u.z = f2tf32(v.z);
        u.w = f2tf32(v.w);
        d[off] = u;
    }
}

// ---------------- tf32 mma GEMM, BK=32, cp.async 3-stage pipeline ----------------
// MODE 0: QKV (A = g_xt gathered; W = g_wq; out -> g_q/g_k/g_v + biases)
//         blocks with blockIdx.y >= 343 build the rpb table instead (96 blocks).
// MODE 2: FC1 (A = g_x1t; W = g_w1; out -> g_hmid tf32-rounded with GELU)
#define BM 128
#define BN 96
#define BK2 32
#define SPAD2 36
#define A2_WORDS (BM * SPAD2)      // 4608
#define B2_WORDS (BN * SPAD2)      // 3456
#define GT_SMEM (3 * (A2_WORDS + B2_WORDS) * 4)   // 96768

template <int MODE>
__global__ void __launch_bounds__(256) mma_gemm(const float* __restrict__ bias1,
                                                const float* __restrict__ bias2,
                                                int K) {
    if (MODE == 0 && blockIdx.y >= 343) {
        // ---- rpb table (log2 units) ----
        const int total = 6 * 343 * RPBS;       // 708072
        const int slice = blockIdx.x + 6 * (blockIdx.y - 343);   // 0..95
        const int per = 7376;                   // ceil(total/96)
        const int start = slice * per;
        const int end = (start + per < total) ? (start + per) : total;
        for (int idx = start + threadIdx.x; idx < end; idx += 256) {
            int hh = idx / (343 * RPBS);
            int rem = idx - hh * (343 * RPBS);
            int i = rem / RPBS;
            int j = rem - i * RPBS;
            if (j >= 343) {
                g_rpb[idx] = 0.f;
                continue;
            }
            int dh = i / 49 - j / 49 + 6;
            int dw = (i / 7) % 7 - (j / 7) % 7 + 6;
            int dd = i % 7 - j % 7 + 6;
            int tix = (dh * 13 + dw) * 13 + dd;
            float v = g_hb[tix * 6 + hh];
            g_rpb[idx] = (16.f / (1.f + __expf(-v))) * LOG2E;
        }
        return;
    }

    extern __shared__ uint32_t sh[];
    uint32_t* As = sh;
    uint32_t* Bs = sh + 3 * A2_WORDS;
    const uint32_t sbA = smem_u32(As);
    const uint32_t sbB = smem_u32(Bs);

    const int tid = threadIdx.x;
    const int lane = tid & 31;
    const int warp = tid >> 5;
    const int warpM = warp & 3;
    const int warpN = warp >> 2;
    const int gr = lane >> 2;
    const int tg = lane & 3;

    const int m0 = blockIdx.y * BM;
    const int n0 = blockIdx.x * BN;

    const float* Asrc = (MODE == 0) ? g_xt : g_x1t;
    const float* W = (MODE == 0) ? g_wq : g_w1;

    const float* aptr[4];
    uint32_t aoffB[4];
#pragma unroll
    for (int i = 0; i < 4; ++i) {
        int idx = tid + i * 256;
        int arow = idx >> 3, c8 = idx & 7;
        int rho = m0 + arow;
        const float* p;
        if (MODE == 0) {
            int b_ = rho / 343, n = rho - b_ * 343;
            int bb = b_ >> 6, win = b_ & 63;
            int wa = win >> 4, wb = (win >> 2) & 3, wc = win & 3;
            int ii = n / 49, jj = (n / 7) % 7, kk = n % 7;
            int hs = (wa * 7 + ii + 3) % 28;
            int ws = (wb * 7 + jj + 3) % 28;
            int ds = (wc * 7 + kk + 3) % 28;
            p = Asrc + ((size_t)bb * LTOT + (hs * 784 + ws * 28 + ds)) * CDIM;
        } else {
            p = Asrc + (size_t)rho * K;
        }
        aptr[i] = p + c8 * 4;
        aoffB[i] = (arow * SPAD2 + c8 * 4) * 4;
    }
    const float* bptr[3];
    uint32_t boff[3];
#pragma unroll
    for (int i = 0; i < 3; ++i) {
        int idx = tid + i * 256;
        int brow = idx >> 3, c8 = idx & 7;
        bptr[i] = W + (size_t)(n0 + brow) * K + c8 * 4;
        boff[i] = (brow * SPAD2 + c8 * 4) * 4;
    }

    float acc[2][6][4];
#pragma unroll
    for (int mi = 0; mi < 2; ++mi)
#pragma unroll
        for (int ni = 0; ni < 6; ++ni)
#pragma unroll
            for (int e = 0; e < 4; ++e) acc[mi][ni][e] = 0.f;

    const int ntiles = K >> 5;
#pragma unroll
    for (int s = 0; s < 2; ++s) {
        const int kt = s * BK2;
#pragma unroll
        for (int i = 0; i < 4; ++i) cp16(sbA + s * (A2_WORDS * 4) + aoffB[i], aptr[i] + kt);
#pragma unroll
        for (int i = 0; i < 3; ++i) cp16(sbB + s * (B2_WORDS * 4) + boff[i], bptr[i] + kt);
        CP_COMMIT();
    }

    for (int t = 0; t < ntiles; ++t) {
        const int buf = t % 3;
        CP_WAIT1();
        __syncthreads();

        const uint32_t* Ab = As + buf * A2_WORDS;
        const uint32_t* Bb = Bs + buf * B2_WORDS;
#pragma unroll
        for (int kk = 0; kk < 32; kk += 8) {
            uint32_t afr[2][4];
#pragma unroll
            for (int mi = 0; mi < 2; ++mi) {
                int rb = warpM * 32 + mi * 16;
                afr[mi][0] = Ab[(rb + gr) * SPAD2 + kk + tg];
                afr[mi][1] = Ab[(rb + gr + 8) * SPAD2 + kk + tg];
                afr[mi][2] = Ab[(rb + gr) * SPAD2 + kk + tg + 4];
                afr[mi][3] = Ab[(rb + gr + 8) * SPAD2 + kk + tg + 4];
            }
            uint32_t bfr[6][2];
#pragma unroll
            for (int ni = 0; ni < 6; ++ni) {
                int nb = warpN * 48 + ni * 8 + gr;
                bfr[ni][0] = Bb[nb * SPAD2 + kk + tg];
                bfr[ni][1] = Bb[nb * SPAD2 + kk + tg + 4];
            }
#pragma unroll
            for (int mi = 0; mi < 2; ++mi)
#pragma unroll
                for (int ni = 0; ni < 6; ++ni)
                    mma_tf32(acc[mi][ni], afr[mi], bfr[ni]);
        }

        const int tn = t + 2;
        if (tn < ntiles) {
            const int s = tn % 3;
            const int kt = tn * BK2;
#pragma unroll
            for (int i = 0; i < 4; ++i)
                cp16(sbA + s * (A2_WORDS * 4) + aoffB[i], aptr[i] + kt);
#pragma unroll
            for (int i = 0; i < 3; ++i)
                cp16(sbB + s * (B2_WORDS * 4) + boff[i], bptr[i] + kt);
        }
        CP_COMMIT();
    }

    // ---------------- epilogue ----------------------------------------------------
#pragma unroll
    for (int mi = 0; mi < 2; ++mi) {
        int rows[2];
        rows[0] = m0 + warpM * 32 + mi * 16 + gr;
        rows[1] = rows[0] + 8;
#pragma unroll
        for (int half = 0; half < 2; ++half) {
            const int r = rows[half];
            int b_ = 0, n = 0;
            if (MODE == 0) {
                b_ = r / 343;
                n = r - b_ * 343;
            }
#pragma unroll
            for (int ni = 0; ni < 6; ++ni) {
                int c = n0 + warpN * 48 + ni * 8 + tg * 2;
                float v0 = acc[mi][ni][half * 2 + 0];
                float v1 = acc[mi][ni][half * 2 + 1];
                if (MODE == 0) {
                    int sct = c / 192;
                    int remc = c - sct * 192;
                    int hh = remc >> 5, dd = remc & 31;
                    float* dst = (sct == 0 ? g_q : (sct == 1 ? g_k : g_v)) +
                                 ((size_t)(b_ * 6 + hh) * NTOK + n) * HD + dd;
                    float e0 = 0.f, e1 = 0.f;
                    if (sct == 0) { e0 = bias1[remc]; e1 = bias1[remc + 1]; }
                    else if (sct == 2) { e0 = bias2[remc]; e1 = bias2[remc + 1]; }
                    *(float2*)dst = make_float2(v0 + e0, v1 + e1);
                } else {
                    float x0 = v0 + bias1[c], x1 = v1 + bias1[c + 1];
                    float g0 = 0.5f * x0 * (1.f + erff(x0 * 0.70710678118654752f));
                    float g1 = 0.5f * x1 * (1.f + erff(x1 * 0.70710678118654752f));
                    *(float2*)(g_hmid + (size_t)r * 768 + c) =
                        make_float2(__uint_as_float(f2tf32(g0)),
                                    __uint_as_float(f2tf32(g1)));
                }
            }
        }
    }
}

// ---------------- GEMM (BN=192) + fused LayerNorm + residual, BK=32 --------------
// MODE 0: PROJ  g_x1[pos] = x[pos] + LN(acc+bias) (window-reverse scatter); also g_x1t
// MODE 1: FC2   out[row] = g_x1[row] + LN(acc+bias)
#define B2L_WORDS (192 * SPAD2)    // 6912
#define LN_SMEM ((3 * (A2_WORDS + B2L_WORDS) + 128 * 4 * 2) * 4)

template <int MODE>
__global__ void __launch_bounds__(512) gemm_ln(const float* __restrict__ bias,
                                               const float* __restrict__ basex,
                                               const float* __restrict__ gw,
                                               const float* __restrict__ bw,
                                               float* __restrict__ outp,
                                               int K) {
    extern __shared__ uint32_t sh[];
    uint32_t* Asm = sh;
    uint32_t* Bsm = sh + 3 * A2_WORDS;
    float* part = (float*)(sh + 3 * A2_WORDS + 3 * B2L_WORDS);  // [128][4][2]
    const uint32_t sbA = smem_u32(Asm);
    const uint32_t sbB = smem_u32(Bsm);

    const int tid = threadIdx.x;
    const int lane = tid & 31;
    const int warp = tid >> 5;
    const int warpM = warp & 3;
    const int warpN = warp >> 2;
    const int gr = lane >> 2;
    const int tg = lane & 3;

    const int m0 = blockIdx.x * BM;

    const float* Asrc = (MODE == 0) ? g_attnout : g_hmid;
    const float* W = (MODE == 0) ? g_wp : g_w2;

    const float* aptr[2];
    uint32_t aoff[2];
#pragma unroll
    for (int i = 0; i < 2; ++i) {
        int idx = tid + i * 512;
        int arow = idx >> 3, c8 = idx & 7;
        aptr[i] = Asrc + (size_t)(m0 + arow) * K + c8 * 4;
        aoff[i] = (arow * SPAD2 + c8 * 4) * 4;
    }
    const float* bptr[3];
    uint32_t boff[3];
#pragma unroll
    for (int i = 0; i < 3; ++i) {
        int idx = tid + i * 512;
        int brow = idx >> 3, c8 = idx & 7;
        bptr[i] = W + (size_t)brow * K + c8 * 4;
        boff[i] = (brow * SPAD2 + c8 * 4) * 4;
    }

    float acc[2][6][4];
#pragma unroll
    for (int mi = 0; mi < 2; ++mi)
#pragma unroll
        for (int ni = 0; ni < 6; ++ni)
#pragma unroll
            for (int e = 0; e < 4; ++e) acc[mi][ni][e] = 0.f;

    const int ntiles = K >> 5;
#pragma unroll
    for (int s = 0; s < 2; ++s) {
        const int kt = s * BK2;
#pragma unroll
        for (int i = 0; i < 2; ++i) cp16(sbA + s * (A2_WORDS * 4) + aoff[i], aptr[i] + kt);
#pragma unroll
        for (int i = 0; i < 3; ++i) cp16(sbB + s * (B2L_WORDS * 4) + boff[i], bptr[i] + kt);
        CP_COMMIT();
    }

    for (int t = 0; t < ntiles; ++t) {
        const int buf = t % 3;
        CP_WAIT1();
        __syncthreads();

        const uint32_t* Ab = Asm + buf * A2_WORDS;
        const uint32_t* Bb = Bsm + buf * B2L_WORDS;
#pragma unroll
        for (int kk = 0; kk < 32; kk += 8) {
            uint32_t afr[2][4];
#pragma unroll
            for (int mi = 0; mi < 2; ++mi) {
                int rb = warpM * 32 + mi * 16;
                afr[mi][0] = Ab[(rb + gr) * SPAD2 + kk + tg];
                afr[mi][1] = Ab[(rb + gr + 8) * SPAD2 + kk + tg];
                afr[mi][2] = Ab[(rb + gr) * SPAD2 + kk + tg + 4];
                afr[mi][3] = Ab[(rb + gr + 8) * SPAD2 + kk + tg + 4];
            }
            uint32_t bfr[6][2];
#pragma unroll
            for (int ni = 0; ni < 6; ++ni) {
                int nb = warpN * 48 + ni * 8 + gr;
                bfr[ni][0] = Bb[nb * SPAD2 + kk + tg];
                bfr[ni][1] = Bb[nb * SPAD2 + kk + tg + 4];
            }
#pragma unroll
            for (int mi = 0; mi < 2; ++mi)
#pragma unroll
                for (int ni = 0; ni < 6; ++ni)
                    mma_tf32(acc[mi][ni], afr[mi], bfr[ni]);
        }

        const int tn = t + 2;
        if (tn < ntiles) {
            const int s = tn % 3;
            const int kt = tn * BK2;
#pragma unroll
            for (int i = 0; i < 2; ++i)
                cp16(sbA + s * (A2_WORDS * 4) + aoff[i], aptr[i] + kt);
#pragma unroll
            for (int i = 0; i < 3; ++i)
                cp16(sbB + s * (B2L_WORDS * 4) + boff[i], bptr[i] + kt);
        }
        CP_COMMIT();
    }
    __syncthreads();

    // ---------------- fused bias + LN partials -------------------------------------
#pragma unroll
    for (int mi = 0; mi < 2; ++mi) {
#pragma unroll
        for (int half = 0; half < 2; ++half) {
            const int rl = warpM * 32 + mi * 16 + gr + half * 8;
            float s = 0.f, sq = 0.f;
#pragma unroll
            for (int ni = 0; ni < 6; ++ni) {
                int c = warpN * 48 + ni * 8 + tg * 2;
                float v0 = acc[mi][ni][half * 2 + 0] + bias[c];
                float v1 = acc[mi][ni][half * 2 + 1] + bias[c + 1];
                acc[mi][ni][half * 2 + 0] = v0;
                acc[mi][ni][half * 2 + 1] = v1;
                s += v0 + v1;
                sq += v0 * v0 + v1 * v1;
            }
            s += __shfl_xor_sync(FULLMASK, s, 1);
            s += __shfl_xor_sync(FULLMASK, s, 2);
            sq += __shfl_xor_sync(FULLMASK, sq, 1);
            sq += __shfl_xor_sync(FULLMASK, sq, 2);
            if (tg == 0) {
                part[(rl * 4 + warpN) * 2 + 0] = s;
                part[(rl * 4 + warpN) * 2 + 1] = sq;
            }
        }
    }
    __syncthreads();

#pragma unroll
    for (int mi = 0; mi < 2; ++mi) {
#pragma unroll
        for (int half = 0; half < 2; ++half) {
            const int rl = warpM * 32 + mi * 16 + gr + half * 8;
            const int r = m0 + rl;
            float s = 0.f, sq = 0.f;
#pragma unroll
            for (int g2 = 0; g2 < 4; ++g2) {
                s += part[(rl * 4 + g2) * 2 + 0];
                sq += part[(rl * 4 + g2) * 2 + 1];
            }
            float mean = s * (1.f / 192.f);
            float var = sq * (1.f / 192.f) - mean * mean;
            float inv = rsqrtf(var + 1e-5f);

            const float* bsrow;
            float* orow;
            float* orow2 = nullptr;
            if (MODE == 0) {
                int b_ = r / 343, n = r - b_ * 343;
                int bb2 = b_ >> 6, win = b_ & 63;
                int wa = win >> 4, wb = (win >> 2) & 3, wc = win & 3;
                int i3 = n / 49, j3 = (n / 7) % 7, k3 = n % 7;
                int hd_ = (wa * 7 + i3 + 3) % 28;
                int wd_ = (wb * 7 + j3 + 3) % 28;
                int dd_ = (wc * 7 + k3 + 3) % 28;
                size_t pos = ((size_t)bb2 * LTOT + (hd_ * 784 + wd_ * 28 + dd_)) * CDIM;
                bsrow = basex + pos;
                orow = g_x1 + pos;
                orow2 = g_x1t + pos;
            } else {
                bsrow = g_x1 + (size_t)r * CDIM;
                orow = outp + (size_t)r * CDIM;
            }
#pragma unroll
            for (int ni = 0; ni < 6; ++ni) {
                int c = warpN * 48 + ni * 8 + tg * 2;
                float v0 = acc[mi][ni][half * 2 + 0];
                float v1 = acc[mi][ni][half * 2 + 1];
                float2 bse = *(const float2*)(bsrow + c);
                float2 gg = *(const float2*)(gw + c);
                float2 bb = *(const float2*)(bw + c);
                float o0 = bse.x + (v0 - mean) * inv * gg.x + bb.x;
                float o1 = bse.y + (v1 - mean) * inv * gg.y + bb.y;
                *(float2*)(orow + c) = make_float2(o0, o1);
                if (MODE == 0)
                    *(float2*)(orow2 + c) =
                        make_float2(__uint_as_float(f2tf32(o0)),
                                    __uint_as_float(f2tf32(o1)));
            }
        }
    }
}

// ---------------- tensor-core flash attention (static max, exp2) -----------------
#define KS_WORDS (384 * 36)
#define VT_WORDS (32 * 388)
#define ATTN4_SMEM ((KS_WORDS + VT_WORDS) * 4 + 512)

__global__ void __launch_bounds__(256, 2) attn4_kernel(const float* __restrict__ logit_scale) {
    extern __shared__ uint32_t asmem[];
    uint32_t* Ks = asmem;                       // [384][36]
    uint32_t* Vt = asmem + KS_WORDS;            // [32][388]
    unsigned char* region = (unsigned char*)(Vt + VT_WORDS);

    const int bh = blockIdx.x;
    const int b_ = bh / 6, h = bh - (bh / 6) * 6;
    const int tid = threadIdx.x;
    const int lane = tid & 31, warp = tid >> 5;
    const int gr = lane >> 2, tg = lane & 3;

    const size_t kvbase = (size_t)bh * (NTOK * HD);
    const float* kg = g_k + kvbase;
    const float* vg = g_v + kvbase;
    const float* qg = g_q + kvbase;

    for (int r = warp; r < 384; r += 8) {
        if (r < NTOK) {
            float v = kg[r * 32 + lane];
            float s = v * v;
#pragma unroll
            for (int o = 16; o; o >>= 1) s += __shfl_xor_sync(FULLMASK, s, o);
            float inv = 1.f / fmaxf(sqrtf(s), 1e-12f);
            Ks[r * 36 + lane] = f2tf32(v * inv);
        } else {
            Ks[r * 36 + lane] = 0u;
        }
    }
    for (int idx = tid; idx < NTOK * 32; idx += 256) {
        int j = idx >> 5, d = idx & 31;
        Vt[d * 388 + j] = f2tf32(vg[idx]);
    }
    for (int idx = tid; idx < 32 * 45; idx += 256) {
        int d = idx / 45, j = NTOK + idx - (idx / 45) * 45;
        Vt[d * 388 + j] = 0u;
    }
    const int win = b_ & 63;
    const int wa = win >> 4, wb = (win >> 2) & 3, wc = win & 3;
    const bool maskedw = (wa == 3) || (wb == 3) || (wc == 3);
    if (maskedw) {
        for (int t = tid; t < 384; t += 256) {
            if (t < NTOK) {
                int ih = t / 49, iw = (t / 7) % 7, id = t % 7;
                int rH = (wa < 3) ? 0 : ((ih < 4) ? 1 : 2);
                int rW = (wb < 3) ? 0 : ((iw < 4) ? 1 : 2);
                int rD = (wc < 3) ? 0 : ((id < 4) ? 1 : 2);
                region[t] = (unsigned char)(rH * 9 + rW * 3 + rD);
            } else {
                region[t] = 0;
            }
        }
    }
    __syncthreads();

    const float scale = __expf(fminf(logit_scale[h], 4.6051701859880914f));
    const float Mstat = (scale + 16.f) * LOG2E;   // static bound, log2 units
    const float* rpbh = g_rpb + (size_t)h * (343 * RPBS);

    for (int rb = 0; rb < 3; ++rb) {
        const int r0 = rb * 128 + warp * 16;
        if (r0 >= NTOK) continue;

        const int r_lo = r0 + gr, r_hi = r0 + gr + 8;
        const bool v_lo = r_lo < NTOK, v_hi = r_hi < NTOK;

        float qf[4][4];
        const float* qlo = qg + (size_t)(v_lo ? r_lo : 0) * 32;
        const float* qhi = qg + (size_t)(v_hi ? r_hi : 0) * 32;
#pragma unroll
        for (int kk = 0; kk < 4; ++kk) {
            qf[kk][0] = v_lo ? qlo[kk * 8 + tg] : 0.f;
            qf[kk][1] = v_hi ? qhi[kk * 8 + tg] : 0.f;
            qf[kk][2] = v_lo ? qlo[kk * 8 + tg + 4] : 0.f;
            qf[kk][3] = v_hi ? qhi[kk * 8 + tg + 4] : 0.f;
        }
        float s0 = 0.f, s1 = 0.f;
#pragma unroll
        for (int kk = 0; kk < 4; ++kk) {
            s0 += qf[kk][0] * qf[kk][0] + qf[kk][2] * qf[kk][2];
            s1 += qf[kk][1] * qf[kk][1] + qf[kk][3] * qf[kk][3];
        }
        s0 += __shfl_xor_sync(FULLMASK, s0, 1);
        s0 += __shfl_xor_sync(FULLMASK, s0, 2);
        s1 += __shfl_xor_sync(FULLMASK, s1, 1);
        s1 += __shfl_xor_sync(FULLMASK, s1, 2);
        const float i0 = scale * LOG2E / fmaxf(sqrtf(s0), 1e-12f);
        const float i1 = scale * LOG2E / fmaxf(sqrtf(s1), 1e-12f);
        uint32_t aQ[4][4];
#pragma unroll
        for (int kk = 0; kk < 4; ++kk) {
            aQ[kk][0] = f2tf32(qf[kk][0] * i0);
            aQ[kk][1] = f2tf32(qf[kk][1] * i1);
            aQ[kk][2] = f2tf32(qf[kk][2] * i0);
            aQ[kk][3] = f2tf32(qf[kk][3] * i1);
        }

        unsigned char rq0 = 0, rq1 = 0;
        if (maskedw) {
            rq0 = region[v_lo ? r_lo : (NTOK - 1)];
            rq1 = region[v_hi ? r_hi : (NTOK - 1)];
        }
        const float* rpr_lo = rpbh + (size_t)(v_lo ? r_lo : 0) * RPBS;
        const float* rpr_hi = rpbh + (size_t)(v_hi ? r_hi : 0) * RPBS;

        float l0 = 0.f, l1 = 0.f;
        float o[4][4];
#pragma unroll
        for (int nt = 0; nt < 4; ++nt)
#pragma unroll
            for (int e = 0; e < 4; ++e) o[nt][e] = 0.f;

        for (int ch = 0; ch < 6; ++ch) {
            const int j0 = ch * 64;
            float s[8][4];
#pragma unroll
            for (int nt = 0; nt < 8; ++nt)
#pragma unroll
                for (int e = 0; e < 4; ++e) s[nt][e] = 0.f;
#pragma unroll
            for (int kk = 0; kk < 4; ++kk) {
#pragma unroll
                for (int nt = 0; nt < 8; ++nt) {
                    uint32_t bb[2];
                    bb[0] = Ks[(j0 + nt * 8 + gr) * 36 + kk * 8 + tg];
                    bb[1] = Ks[(j0 + nt * 8 + gr) * 36 + kk * 8 + tg + 4];
                    mma_tf32(s[nt], aQ[kk], bb);
                }
            }
#pragma unroll
            for (int nt = 0; nt < 8; ++nt) {
                const int jc = j0 + nt * 8 + tg * 2;
                float2 blo = *(const float2*)(rpr_lo + jc);
                float2 bhi = *(const float2*)(rpr_hi + jc);
                float t0 = s[nt][0] + blo.x - Mstat;
                float t1 = s[nt][1] + blo.y - Mstat;
                float t2 = s[nt][2] + bhi.x - Mstat;
                float t3 = s[nt][3] + bhi.y - Mstat;
                if (maskedw) {
                    unsigned char rk0 = region[jc];
                    unsigned char rk1 = region[jc + 1];
                    if (rk0 != rq0) t0 -= 144.26950408f;
                    if (rk1 != rq0) t1 -= 144.26950408f;
                    if (rk0 != rq1) t2 -= 144.26950408f;
                    if (rk1 != rq1) t3 -= 144.26950408f;
                }
                float p0 = exp2f(t0);
                float p1 = exp2f(t1);
                float p2 = exp2f(t2);
                float p3 = exp2f(t3);
                if (ch == 5) {
                    if (jc >= NTOK) { p0 = 0.f; p2 = 0.f; }
                    if (jc + 1 >= NTOK) { p1 = 0.f; p3 = 0.f; }
                }
                l0 += p0 + p1;
                l1 += p2 + p3;
                s[nt][0] = p0;
                s[nt][1] = p1;
                s[nt][2] = p2;
                s[nt][3] = p3;
            }
            const int src0 = (lane & ~3) | (tg >> 1);
            const int src2 = src0 + 2;
            const bool odd = (tg & 1);
#pragma unroll
            for (int kk = 0; kk < 8; ++kk) {
                float v00 = __shfl_sync(FULLMASK, s[kk][0], src0);
                float v01 = __shfl_sync(FULLMASK, s[kk][1], src0);
                float v20 = __shfl_sync(FULLMASK, s[kk][0], src2);
                float v21 = __shfl_sync(FULLMASK, s[kk][1], src2);
                float v10 = __shfl_sync(FULLMASK, s[kk][2], src0);
                float v11 = __shfl_sync(FULLMASK, s[kk][3], src0);
                float v30 = __shfl_sync(FULLMASK, s[kk][2], src2);
                float v31 = __shfl_sync(FULLMASK, s[kk][3], src2);
                uint32_t aP[4];
                aP[0] = f2tf32(odd ? v01 : v00);
                aP[1] = f2tf32(odd ? v11 : v10);
                aP[2] = f2tf32(odd ? v21 : v20);
                aP[3] = f2tf32(odd ? v31 : v30);
#pragma unroll
                for (int nt = 0; nt < 4; ++nt) {
                    uint32_t bb[2];
                    bb[0] = Vt[(nt * 8 + gr) * 388 + j0 + kk * 8 + tg];
                    bb[1] = Vt[(nt * 8 + gr) * 388 + j0 + kk * 8 + tg + 4];
                    mma_tf32(o[nt], aP, bb);
                }
            }
        }

        l0 += __shfl_xor_sync(FULLMASK, l0, 1);
        l0 += __shfl_xor_sync(FULLMASK, l0, 2);
        l1 += __shfl_xor_sync(FULLMASK, l1, 1);
        l1 += __shfl_xor_sync(FULLMASK, l1, 2);

        if (v_lo) {
            const float il0 = 1.f / l0;
            float* dst = g_attnout + ((size_t)b_ * NTOK + r_lo) * CDIM + h * HD;
#pragma unroll
            for (int nt = 0; nt < 4; ++nt)
                *(float2*)(dst + nt * 8 + tg * 2) =
                    make_float2(__uint_as_float(f2tf32(o[nt][0] * il0)),
                                __uint_as_float(f2tf32(o[nt][1] * il0)));
        }
        if (v_hi) {
            const float il1 = 1.f / l1;
            float* dst = g_attnout + ((size_t)b_ * NTOK + r_hi) * CDIM + h * HD;
#pragma unroll
            for (int nt = 0; nt < 4; ++nt)
                *(float2*)(dst + nt * 8 + tg * 2) =
                    make_float2(__uint_as_float(f2tf32(o[nt][2] * il1)),
                                __uint_as_float(f2tf32(o[nt][3] * il1)));
        }
    }
}

// ---------------- launch ---------------------------------------------------------
extern "C" void kernel_launch(void* const* d_in, const int* in_sizes, int n_in,
                              void* d_out, int out_size) {
    (void)in_sizes; (void)n_in; (void)out_size;
    const float* x = (const float*)d_in[0];
    const float* qkv_w = (const float*)d_in[1];
    const float* q_bias = (const float*)d_in[2];
    const float* v_bias = (const float*)d_in[3];
    const float* logit_scale = (const float*)d_in[4];
    const float* cpb_w1 = (const float*)d_in[5];
    const float* cpb_b1 = (const float*)d_in[6];
    const float* cpb_w2 = (const float*)d_in[7];
    const float* proj_w = (const float*)d_in[8];
    const float* proj_b = (const float*)d_in[9];
    const float* norm1_g = (const float*)d_in[10];
    const float* norm1_b = (const float*)d_in[11];
    const float* fc1_w = (const float*)d_in[12];
    const float* fc1_b = (const float*)d_in[13];
    const float* fc2_w = (const float*)d_in[14];
    const float* fc2_b = (const float*)d_in[15];
    const float* norm2_g = (const float*)d_in[16];
    const float* norm2_b = (const float*)d_in[17];
    float* out = (float*)d_out;

    static bool attr_done = false;
    if (!attr_done) {
        cudaFuncSetAttribute(attn4_kernel, cudaFuncAttributeMaxDynamicSharedMemorySize,
                             ATTN4_SMEM);
        cudaFuncSetAttribute(mma_gemm<0>, cudaFuncAttributeMaxDynamicSharedMemorySize,
                             GT_SMEM);
        cudaFuncSetAttribute(mma_gemm<2>, cudaFuncAttributeMaxDynamicSharedMemorySize,
                             GT_SMEM);
        cudaFuncSetAttribute(gemm_ln<0>, cudaFuncAttributeMaxDynamicSharedMemorySize,
                             LN_SMEM);
        cudaFuncSetAttribute(gemm_ln<1>, cudaFuncAttributeMaxDynamicSharedMemorySize,
                             LN_SMEM);
        attr_done = true;
    }

    // fused tf32 pre-conversion + CPB MLP
    cvt_cpb<<<1024 + 2197, 256>>>(x, qkv_w, proj_w, fc1_w, fc2_w,
                                  cpb_w1, cpb_b1, cpb_w2);

    // qkv (fused shift + window gather) + rpb table (extra 96 blocks at y>=343)
    mma_gemm<0><<<dim3(6, 343 + 16), 256, GT_SMEM>>>(q_bias, v_bias, 192);

    // attention (tensor-core flash, static max, exp2)
    attn4_kernel<<<768, 256, ATTN4_SMEM>>>(logit_scale);

    // proj + LN + residual (fused window reverse + roll scatter): N=192, K=192
    gemm_ln<0><<<343, 512, LN_SMEM>>>(proj_b, x, norm1_g, norm1_b, nullptr, 192);

    // fc1: N=768, K=192 (GELU)
    mma_gemm<2><<<dim3(8, 343), 256, GT_SMEM>>>(fc1_b, nullptr, 192);

    // fc2 + LN + residual: N=192, K=768
    gemm_ln<1><<<343, 512, LN_SMEM>>>(fc2_b, nullptr, norm2_g, norm2_b, out, 768);
}

// round 14
// speedup vs baseline: 1.0834x; 1.0538x over previous
#include <cuda_runtime.h>
#include <cuda_fp16.h>
#include <math.h>
#include <stdint.h>

#define FULLMASK 0xffffffffu
#define LOG2E 1.4426950408889634f

// problem dims
#define NTOK   343
#define NHEAD  6
#define HD     32
#define CDIM   192
#define LTOT   21952
#define NWIN   128
#define NROWS  43904
#define RPBS   344

// ---------------- device scratch ------------------------------------------------
__device__ float g_hb[2197 * 6];
__device__ __align__(16) float g_rpb[6 * 343 * RPBS];
__device__ __align__(16) float g_q[(size_t)NWIN * NHEAD * NTOK * HD];
__device__ __align__(16) float g_k[(size_t)NWIN * NHEAD * NTOK * HD];
__device__ __align__(16) float g_v[(size_t)NWIN * NHEAD * NTOK * HD];
__device__ __align__(16) float g_attnout[(size_t)NWIN * NTOK * CDIM];   // tf32-rounded
__device__ __align__(16) float g_x1[(size_t)2 * LTOT * CDIM];           // fp32
__device__ __align__(16) float g_x1t[(size_t)2 * LTOT * CDIM];          // tf32-rounded
__device__ __align__(16) float g_xt[(size_t)2 * LTOT * CDIM];           // tf32-rounded
__device__ __align__(16) float g_hmid[(size_t)NROWS * 768];             // tf32-rounded
__device__ __align__(16) float g_wq[576 * 192];
__device__ __align__(16) float g_wp[192 * 192];
__device__ __align__(16) float g_w1[768 * 192];
__device__ __align__(16) float g_w2[192 * 768];

// ---------------- helpers -------------------------------------------------------
__device__ __forceinline__ uint32_t f2tf32(float x) {
    uint32_t r;
    asm("cvt.rna.tf32.f32 %0, %1;" : "=r"(r) : "f"(x));
    return r;
}

__device__ __forceinline__ void mma_tf32(float* c, const uint32_t* a, const uint32_t* b) {
    asm volatile(
        "mma.sync.aligned.m16n8k8.row.col.f32.tf32.tf32.f32 "
        "{%0,%1,%2,%3}, {%4,%5,%6,%7}, {%8,%9}, {%0,%1,%2,%3};"
        : "+f"(c[0]), "+f"(c[1]), "+f"(c[2]), "+f"(c[3])
        : "r"(a[0]), "r"(a[1]), "r"(a[2]), "r"(a[3]), "r"(b[0]), "r"(b[1]));
}

__device__ __forceinline__ void mma_f16(float* c, const uint32_t* a, uint32_t b0,
                                        uint32_t b1) {
    asm volatile(
        "mma.sync.aligned.m16n8k16.row.col.f32.f16.f16.f32 "
        "{%0,%1,%2,%3}, {%4,%5,%6,%7}, {%8,%9}, {%0,%1,%2,%3};"
        : "+f"(c[0]), "+f"(c[1]), "+f"(c[2]), "+f"(c[3])
        : "r"(a[0]), "r"(a[1]), "r"(a[2]), "r"(a[3]), "r"(b0), "r"(b1));
}

__device__ __forceinline__ uint32_t pack_h2(float lo, float hi) {
    uint32_t r;
    asm("cvt.rn.f16x2.f32 %0, %1, %2;" : "=r"(r) : "f"(hi), "f"(lo));
    return r;
}

__device__ __forceinline__ uint32_t smem_u32(const void* p) {
    uint32_t a;
    asm("{ .reg .u64 t; cvta.to.shared.u64 t, %1; cvt.u32.u64 %0, t; }" : "=r"(a) : "l"(p));
    return a;
}

__device__ __forceinline__ void cp16(uint32_t dst, const void* src) {
    asm volatile("cp.async.ca.shared.global [%0], [%1], 16;" :: "r"(dst), "l"(src));
}
#define CP_COMMIT() asm volatile("cp.async.commit_group;" ::: "memory")
#define CP_WAIT1()  asm volatile("cp.async.wait_group 1;" ::: "memory")

// ---------------- CPB coord helper ----------------------------------------------
__device__ __forceinline__ float cpb_coord(int i) {
    float v = (float)(i - 6) * (8.0f / 6.0f);
    float av = fabsf(v);
    float r = log2f(av + 1.0f) * (1.0f / 3.0f);
    return (v < 0.f) ? -r : r;
}

// ---------------- fused tf32 convert + CPB MLP kernel ----------------------------
__global__ void __launch_bounds__(256) cvt_cpb(const float* __restrict__ x,
                                               const float* __restrict__ wq,
                                               const float* __restrict__ wp,
                                               const float* __restrict__ w1cv,
                                               const float* __restrict__ w2cv,
                                               const float* __restrict__ cw1,
                                               const float* __restrict__ cb1,
                                               const float* __restrict__ cw2) {
    __shared__ float hid[512];
    if (blockIdx.x >= 1024) {
        int t = blockIdx.x - 1024;
        int a = t / 169;
        int rem = t - a * 169;
        int b = rem / 13;
        int c = rem - b * 13;
        float c0 = cpb_coord(a), c1 = cpb_coord(b), c2 = cpb_coord(c);
        for (int j = threadIdx.x; j < 512; j += blockDim.x) {
            float hv = c0 * cw1[j * 3 + 0] + c1 * cw1[j * 3 + 1] + c2 * cw1[j * 3 + 2] +
                       cb1[j];
            hid[j] = fmaxf(hv, 0.f);
        }
        __syncthreads();
        if (threadIdx.x < 192) {
            int hh = threadIdx.x >> 5, lane = threadIdx.x & 31;
            float s = 0.f;
            for (int j = lane; j < 512; j += 32) s += hid[j] * cw2[hh * 512 + j];
#pragma unroll
            for (int off = 16; off; off >>= 1) s += __shfl_xor_sync(FULLMASK, s, off);
            if (lane == 0) g_hb[t * 6 + hh] = s;
        }
        return;
    }
    const int N0 = 2107392;
    const int N1 = N0 + 27648;
    const int N2 = N1 + 9216;
    const int N3 = N2 + 36864;
    const int N4 = N3 + 36864;
    for (int i = blockIdx.x * blockDim.x + threadIdx.x; i < N4; i += 1024 * 256) {
        const float4* s;
        uint4* d;
        int off;
        if (i < N0) { s = (const float4*)x; d = (uint4*)g_xt; off = i; }
        else if (i < N1) { s = (const float4*)wq; d = (uint4*)g_wq; off = i - N0; }
        else if (i < N2) { s = (const float4*)wp; d = (uint4*)g_wp; off = i - N1; }
        else if (i < N3) { s = (const float4*)w1cv; d = (uint4*)g_w1; off = i - N2; }
        else { s = (const float4*)w2cv; d = (uint4*)g_w2; off = i - N3; }
        float4 v = s[off];
        uint4 u;
        u.x = f2tf32(v.x);
        u.y = f2tf32(v.y);
        u.z = f2tf32(v.z);
        u.w = f2tf32(v.w);
        d[off] = u;
    }
}

// ---------------- tf32 mma GEMM, BK=32, cp.async 3-stage pipeline ----------------
#define BM 128
#define BN 96
#define BK2 32
#define SPAD2 36
#define A2_WORDS (BM * SPAD2)
#define B2_WORDS (BN * SPAD2)
#define GT_SMEM (3 * (A2_WORDS + B2_WORDS) * 4)

template <int MODE>
__global__ void __launch_bounds__(256) mma_gemm(const float* __restrict__ bias1,
                                                const float* __restrict__ bias2,
                                                int K) {
    if (MODE == 0 && blockIdx.y >= 343) {
        const int total = 6 * 343 * RPBS;
        const int slice = blockIdx.x + 6 * (blockIdx.y - 343);
        const int per = 7376;
        const int start = slice * per;
        const int end = (start + per < total) ? (start + per) : total;
        for (int idx = start + threadIdx.x; idx < end; idx += 256) {
            int hh = idx / (343 * RPBS);
            int rem = idx - hh * (343 * RPBS);
            int i = rem / RPBS;
            int j = rem - i * RPBS;
            if (j >= 343) {
                g_rpb[idx] = 0.f;
                continue;
            }
            int dh = i / 49 - j / 49 + 6;
            int dw = (i / 7) % 7 - (j / 7) % 7 + 6;
            int dd = i % 7 - j % 7 + 6;
            int tix = (dh * 13 + dw) * 13 + dd;
            float v = g_hb[tix * 6 + hh];
            g_rpb[idx] = (16.f / (1.f + __expf(-v))) * LOG2E;
        }
        return;
    }

    extern __shared__ uint32_t sh[];
    uint32_t* As = sh;
    uint32_t* Bs = sh + 3 * A2_WORDS;
    const uint32_t sbA = smem_u32(As);
    const uint32_t sbB = smem_u32(Bs);

    const int tid = threadIdx.x;
    const int lane = tid & 31;
    const int warp = tid >> 5;
    const int warpM = warp & 3;
    const int warpN = warp >> 2;
    const int gr = lane >> 2;
    const int tg = lane & 3;

    const int m0 = blockIdx.y * BM;
    const int n0 = blockIdx.x * BN;

    const float* Asrc = (MODE == 0) ? g_xt : g_x1t;
    const float* W = (MODE == 0) ? g_wq : g_w1;

    const float* aptr[4];
    uint32_t aoffB[4];
#pragma unroll
    for (int i = 0; i < 4; ++i) {
        int idx = tid + i * 256;
        int arow = idx >> 3, c8 = idx & 7;
        int rho = m0 + arow;
        const float* p;
        if (MODE == 0) {
            int b_ = rho / 343, n = rho - b_ * 343;
            int bb = b_ >> 6, win = b_ & 63;
            int wa = win >> 4, wb = (win >> 2) & 3, wc = win & 3;
            int ii = n / 49, jj = (n / 7) % 7, kk = n % 7;
            int hs = (wa * 7 + ii + 3) % 28;
            int ws = (wb * 7 + jj + 3) % 28;
            int ds = (wc * 7 + kk + 3) % 28;
            p = Asrc + ((size_t)bb * LTOT + (hs * 784 + ws * 28 + ds)) * CDIM;
        } else {
            p = Asrc + (size_t)rho * K;
        }
        aptr[i] = p + c8 * 4;
        aoffB[i] = (arow * SPAD2 + c8 * 4) * 4;
    }
    const float* bptr[3];
    uint32_t boff[3];
#pragma unroll
    for (int i = 0; i < 3; ++i) {
        int idx = tid + i * 256;
        int brow = idx >> 3, c8 = idx & 7;
        bptr[i] = W + (size_t)(n0 + brow) * K + c8 * 4;
        boff[i] = (brow * SPAD2 + c8 * 4) * 4;
    }

    float acc[2][6][4];
#pragma unroll
    for (int mi = 0; mi < 2; ++mi)
#pragma unroll
        for (int ni = 0; ni < 6; ++ni)
#pragma unroll
            for (int e = 0; e < 4; ++e) acc[mi][ni][e] = 0.f;

    const int ntiles = K >> 5;
#pragma unroll
    for (int s = 0; s < 2; ++s) {
        const int kt = s * BK2;
#pragma unroll
        for (int i = 0; i < 4; ++i) cp16(sbA + s * (A2_WORDS * 4) + aoffB[i], aptr[i] + kt);
#pragma unroll
        for (int i = 0; i < 3; ++i) cp16(sbB + s * (B2_WORDS * 4) + boff[i], bptr[i] + kt);
        CP_COMMIT();
    }

    for (int t = 0; t < ntiles; ++t) {
        const int buf = t % 3;
        CP_WAIT1();
        __syncthreads();

        const uint32_t* Ab = As + buf * A2_WORDS;
        const uint32_t* Bb = Bs + buf * B2_WORDS;
#pragma unroll
        for (int kk = 0; kk < 32; kk += 8) {
            uint32_t afr[2][4];
#pragma unroll
            for (int mi = 0; mi < 2; ++mi) {
                int rb = warpM * 32 + mi * 16;
                afr[mi][0] = Ab[(rb + gr) * SPAD2 + kk + tg];
                afr[mi][1] = Ab[(rb + gr + 8) * SPAD2 + kk + tg];
                afr[mi][2] = Ab[(rb + gr) * SPAD2 + kk + tg + 4];
                afr[mi][3] = Ab[(rb + gr + 8) * SPAD2 + kk + tg + 4];
            }
            uint32_t bfr[6][2];
#pragma unroll
            for (int ni = 0; ni < 6; ++ni) {
                int nb = warpN * 48 + ni * 8 + gr;
                bfr[ni][0] = Bb[nb * SPAD2 + kk + tg];
                bfr[ni][1] = Bb[nb * SPAD2 + kk + tg + 4];
            }
#pragma unroll
            for (int mi = 0; mi < 2; ++mi)
#pragma unroll
                for (int ni = 0; ni < 6; ++ni)
                    mma_tf32(acc[mi][ni], afr[mi], bfr[ni]);
        }

        const int tn = t + 2;
        if (tn < ntiles) {
            const int s = tn % 3;
            const int kt = tn * BK2;
#pragma unroll
            for (int i = 0; i < 4; ++i)
                cp16(sbA + s * (A2_WORDS * 4) + aoffB[i], aptr[i] + kt);
#pragma unroll
            for (int i = 0; i < 3; ++i)
                cp16(sbB + s * (B2_WORDS * 4) + boff[i], bptr[i] + kt);
        }
        CP_COMMIT();
    }

#pragma unroll
    for (int mi = 0; mi < 2; ++mi) {
        int rows[2];
        rows[0] = m0 + warpM * 32 + mi * 16 + gr;
        rows[1] = rows[0] + 8;
#pragma unroll
        for (int half = 0; half < 2; ++half) {
            const int r = rows[half];
            int b_ = 0, n = 0;
            if (MODE == 0) {
                b_ = r / 343;
                n = r - b_ * 343;
            }
#pragma unroll
            for (int ni = 0; ni < 6; ++ni) {
                int c = n0 + warpN * 48 + ni * 8 + tg * 2;
                float v0 = acc[mi][ni][half * 2 + 0];
                float v1 = acc[mi][ni][half * 2 + 1];
                if (MODE == 0) {
                    int sct = c / 192;
                    int remc = c - sct * 192;
                    int hh = remc >> 5, dd = remc & 31;
                    float* dst = (sct == 0 ? g_q : (sct == 1 ? g_k : g_v)) +
                                 ((size_t)(b_ * 6 + hh) * NTOK + n) * HD + dd;
                    float e0 = 0.f, e1 = 0.f;
                    if (sct == 0) { e0 = bias1[remc]; e1 = bias1[remc + 1]; }
                    else if (sct == 2) { e0 = bias2[remc]; e1 = bias2[remc + 1]; }
                    *(float2*)dst = make_float2(v0 + e0, v1 + e1);
                } else {
                    float x0 = v0 + bias1[c], x1 = v1 + bias1[c + 1];
                    float g0 = 0.5f * x0 * (1.f + erff(x0 * 0.70710678118654752f));
                    float g1 = 0.5f * x1 * (1.f + erff(x1 * 0.70710678118654752f));
                    *(float2*)(g_hmid + (size_t)r * 768 + c) =
                        make_float2(__uint_as_float(f2tf32(g0)),
                                    __uint_as_float(f2tf32(g1)));
                }
            }
        }
    }
}

// ---------------- GEMM (BN=192) + fused LayerNorm + residual, BK=32 --------------
#define B2L_WORDS (192 * SPAD2)
#define LN_SMEM ((3 * (A2_WORDS + B2L_WORDS) + 128 * 4 * 2) * 4)

template <int MODE>
__global__ void __launch_bounds__(512) gemm_ln(const float* __restrict__ bias,
                                               const float* __restrict__ basex,
                                               const float* __restrict__ gw,
                                               const float* __restrict__ bw,
                                               float* __restrict__ outp,
                                               int K) {
    extern __shared__ uint32_t sh[];
    uint32_t* Asm = sh;
    uint32_t* Bsm = sh + 3 * A2_WORDS;
    float* part = (float*)(sh + 3 * A2_WORDS + 3 * B2L_WORDS);
    const uint32_t sbA = smem_u32(Asm);
    const uint32_t sbB = smem_u32(Bsm);

    const int tid = threadIdx.x;
    const int lane = tid & 31;
    const int warp = tid >> 5;
    const int warpM = warp & 3;
    const int warpN = warp >> 2;
    const int gr = lane >> 2;
    const int tg = lane & 3;

    const int m0 = blockIdx.x * BM;

    const float* Asrc = (MODE == 0) ? g_attnout : g_hmid;
    const float* W = (MODE == 0) ? g_wp : g_w2;

    const float* aptr[2];
    uint32_t aoff[2];
#pragma unroll
    for (int i = 0; i < 2; ++i) {
        int idx = tid + i * 512;
        int arow = idx >> 3, c8 = idx & 7;
        aptr[i] = Asrc + (size_t)(m0 + arow) * K + c8 * 4;
        aoff[i] = (arow * SPAD2 + c8 * 4) * 4;
    }
    const float* bptr[3];
    uint32_t boff[3];
#pragma unroll
    for (int i = 0; i < 3; ++i) {
        int idx = tid + i * 512;
        int brow = idx >> 3, c8 = idx & 7;
        bptr[i] = W + (size_t)brow * K + c8 * 4;
        boff[i] = (brow * SPAD2 + c8 * 4) * 4;
    }

    float acc[2][6][4];
#pragma unroll
    for (int mi = 0; mi < 2; ++mi)
#pragma unroll
        for (int ni = 0; ni < 6; ++ni)
#pragma unroll
            for (int e = 0; e < 4; ++e) acc[mi][ni][e] = 0.f;

    const int ntiles = K >> 5;
#pragma unroll
    for (int s = 0; s < 2; ++s) {
        const int kt = s * BK2;
#pragma unroll
        for (int i = 0; i < 2; ++i) cp16(sbA + s * (A2_WORDS * 4) + aoff[i], aptr[i] + kt);
#pragma unroll
        for (int i = 0; i < 3; ++i) cp16(sbB + s * (B2L_WORDS * 4) + boff[i], bptr[i] + kt);
        CP_COMMIT();
    }

    for (int t = 0; t < ntiles; ++t) {
        const int buf = t % 3;
        CP_WAIT1();
        __syncthreads();

        const uint32_t* Ab = Asm + buf * A2_WORDS;
        const uint32_t* Bb = Bsm + buf * B2L_WORDS;
#pragma unroll
        for (int kk = 0; kk < 32; kk += 8) {
            uint32_t afr[2][4];
#pragma unroll
            for (int mi = 0; mi < 2; ++mi) {
                int rb = warpM * 32 + mi * 16;
                afr[mi][0] = Ab[(rb + gr) * SPAD2 + kk + tg];
                afr[mi][1] = Ab[(rb + gr + 8) * SPAD2 + kk + tg];
                afr[mi][2] = Ab[(rb + gr) * SPAD2 + kk + tg + 4];
                afr[mi][3] = Ab[(rb + gr + 8) * SPAD2 + kk + tg + 4];
            }
            uint32_t bfr[6][2];
#pragma unroll
            for (int ni = 0; ni < 6; ++ni) {
                int nb = warpN * 48 + ni * 8 + gr;
                bfr[ni][0] = Bb[nb * SPAD2 + kk + tg];
                bfr[ni][1] = Bb[nb * SPAD2 + kk + tg + 4];
            }
#pragma unroll
            for (int mi = 0; mi < 2; ++mi)
#pragma unroll
                for (int ni = 0; ni < 6; ++ni)
                    mma_tf32(acc[mi][ni], afr[mi], bfr[ni]);
        }

        const int tn = t + 2;
        if (tn < ntiles) {
            const int s = tn % 3;
            const int kt = tn * BK2;
#pragma unroll
            for (int i = 0; i < 2; ++i)
                cp16(sbA + s * (A2_WORDS * 4) + aoff[i], aptr[i] + kt);
#pragma unroll
            for (int i = 0; i < 3; ++i)
                cp16(sbB + s * (B2L_WORDS * 4) + boff[i], bptr[i] + kt);
        }
        CP_COMMIT();
    }
    __syncthreads();

#pragma unroll
    for (int mi = 0; mi < 2; ++mi) {
#pragma unroll
        for (int half = 0; half < 2; ++half) {
            const int rl = warpM * 32 + mi * 16 + gr + half * 8;
            float s = 0.f, sq = 0.f;
#pragma unroll
            for (int ni = 0; ni < 6; ++ni) {
                int c = warpN * 48 + ni * 8 + tg * 2;
                float v0 = acc[mi][ni][half * 2 + 0] + bias[c];
                float v1 = acc[mi][ni][half * 2 + 1] + bias[c + 1];
                acc[mi][ni][half * 2 + 0] = v0;
                acc[mi][ni][half * 2 + 1] = v1;
                s += v0 + v1;
                sq += v0 * v0 + v1 * v1;
            }
            s += __shfl_xor_sync(FULLMASK, s, 1);
            s += __shfl_xor_sync(FULLMASK, s, 2);
            sq += __shfl_xor_sync(FULLMASK, sq, 1);
            sq += __shfl_xor_sync(FULLMASK, sq, 2);
            if (tg == 0) {
                part[(rl * 4 + warpN) * 2 + 0] = s;
                part[(rl * 4 + warpN) * 2 + 1] = sq;
            }
        }
    }
    __syncthreads();

#pragma unroll
    for (int mi = 0; mi < 2; ++mi) {
#pragma unroll
        for (int half = 0; half < 2; ++half) {
            const int rl = warpM * 32 + mi * 16 + gr + half * 8;
            const int r = m0 + rl;
            float s = 0.f, sq = 0.f;
#pragma unroll
            for (int g2 = 0; g2 < 4; ++g2) {
                s += part[(rl * 4 + g2) * 2 + 0];
                sq += part[(rl * 4 + g2) * 2 + 1];
            }
            float mean = s * (1.f / 192.f);
            float var = sq * (1.f / 192.f) - mean * mean;
            float inv = rsqrtf(var + 1e-5f);

            const float* bsrow;
            float* orow;
            float* orow2 = nullptr;
            if (MODE == 0) {
                int b_ = r / 343, n = r - b_ * 343;
                int bb2 = b_ >> 6, win = b_ & 63;
                int wa = win >> 4, wb = (win >> 2) & 3, wc = win & 3;
                int i3 = n / 49, j3 = (n / 7) % 7, k3 = n % 7;
                int hd_ = (wa * 7 + i3 + 3) % 28;
                int wd_ = (wb * 7 + j3 + 3) % 28;
                int dd_ = (wc * 7 + k3 + 3) % 28;
                size_t pos = ((size_t)bb2 * LTOT + (hd_ * 784 + wd_ * 28 + dd_)) * CDIM;
                bsrow = basex + pos;
                orow = g_x1 + pos;
                orow2 = g_x1t + pos;
            } else {
                bsrow = g_x1 + (size_t)r * CDIM;
                orow = outp + (size_t)r * CDIM;
            }
#pragma unroll
            for (int ni = 0; ni < 6; ++ni) {
                int c = warpN * 48 + ni * 8 + tg * 2;
                float v0 = acc[mi][ni][half * 2 + 0];
                float v1 = acc[mi][ni][half * 2 + 1];
                float2 bse = *(const float2*)(bsrow + c);
                float2 gg = *(const float2*)(gw + c);
                float2 bb = *(const float2*)(bw + c);
                float o0 = bse.x + (v0 - mean) * inv * gg.x + bb.x;
                float o1 = bse.y + (v1 - mean) * inv * gg.y + bb.y;
                *(float2*)(orow + c) = make_float2(o0, o1);
                if (MODE == 0)
                    *(float2*)(orow2 + c) =
                        make_float2(__uint_as_float(f2tf32(o0)),
                                    __uint_as_float(f2tf32(o1)));
            }
        }
    }
}

// ---------------- tensor-core flash attention (static max, exp2, fp16 PV) --------
#define KS_WORDS (384 * 36)
#define VTH_STRIDE 392
#define VTH_BYTES (32 * VTH_STRIDE * 2)
#define ATTN4_SMEM (KS_WORDS * 4 + VTH_BYTES + 512)

__global__ void __launch_bounds__(256, 2) attn4_kernel(const float* __restrict__ logit_scale) {
    extern __shared__ uint32_t asmem[];
    uint32_t* Ks = asmem;                                  // [384][36] tf32
    __half* Vth = (__half*)(asmem + KS_WORDS);             // [32][392] fp16
    unsigned char* region = (unsigned char*)((char*)Vth + VTH_BYTES);

    const int bh = blockIdx.x;
    const int b_ = bh / 6, h = bh - (bh / 6) * 6;
    const int tid = threadIdx.x;
    const int lane = tid & 31, warp = tid >> 5;
    const int gr = lane >> 2, tg = lane & 3;

    const size_t kvbase = (size_t)bh * (NTOK * HD);
    const float* kg = g_k + kvbase;
    const float* vg = g_v + kvbase;
    const float* qg = g_q + kvbase;

    for (int r = warp; r < 384; r += 8) {
        if (r < NTOK) {
            float v = kg[r * 32 + lane];
            float s = v * v;
#pragma unroll
            for (int o = 16; o; o >>= 1) s += __shfl_xor_sync(FULLMASK, s, o);
            float inv = 1.f / fmaxf(sqrtf(s), 1e-12f);
            Ks[r * 36 + lane] = f2tf32(v * inv);
        } else {
            Ks[r * 36 + lane] = 0u;
        }
    }
    // V transposed -> fp16 smem
    for (int idx = tid; idx < NTOK * 32; idx += 256) {
        int j = idx >> 5, d = idx & 31;
        Vth[d * VTH_STRIDE + j] = __float2half(vg[idx]);
    }
    for (int idx = tid; idx < 32 * (VTH_STRIDE - NTOK); idx += 256) {
        int d = idx / (VTH_STRIDE - NTOK);
        int j = NTOK + idx - d * (VTH_STRIDE - NTOK);
        Vth[d * VTH_STRIDE + j] = __float2half(0.f);
    }
    const int win = b_ & 63;
    const int wa = win >> 4, wb = (win >> 2) & 3, wc = win & 3;
    const bool maskedw = (wa == 3) || (wb == 3) || (wc == 3);
    if (maskedw) {
        for (int t = tid; t < 384; t += 256) {
            if (t < NTOK) {
                int ih = t / 49, iw = (t / 7) % 7, id = t % 7;
                int rH = (wa < 3) ? 0 : ((ih < 4) ? 1 : 2);
                int rW = (wb < 3) ? 0 : ((iw < 4) ? 1 : 2);
                int rD = (wc < 3) ? 0 : ((id < 4) ? 1 : 2);
                region[t] = (unsigned char)(rH * 9 + rW * 3 + rD);
            } else {
                region[t] = 0;
            }
        }
    }
    __syncthreads();

    const float scale = __expf(fminf(logit_scale[h], 4.6051701859880914f));
    const float Mstat = (scale + 16.f) * LOG2E;
    const float* rpbh = g_rpb + (size_t)h * (343 * RPBS);

    for (int rb = 0; rb < 3; ++rb) {
        const int r0 = rb * 128 + warp * 16;
        if (r0 >= NTOK) continue;

        const int r_lo = r0 + gr, r_hi = r0 + gr + 8;
        const bool v_lo = r_lo < NTOK, v_hi = r_hi < NTOK;

        float qf[4][4];
        const float* qlo = qg + (size_t)(v_lo ? r_lo : 0) * 32;
        const float* qhi = qg + (size_t)(v_hi ? r_hi : 0) * 32;
#pragma unroll
        for (int kk = 0; kk < 4; ++kk) {
            qf[kk][0] = v_lo ? qlo[kk * 8 + tg] : 0.f;
            qf[kk][1] = v_hi ? qhi[kk * 8 + tg] : 0.f;
            qf[kk][2] = v_lo ? qlo[kk * 8 + tg + 4] : 0.f;
            qf[kk][3] = v_hi ? qhi[kk * 8 + tg + 4] : 0.f;
        }
        float s0 = 0.f, s1 = 0.f;
#pragma unroll
        for (int kk = 0; kk < 4; ++kk) {
            s0 += qf[kk][0] * qf[kk][0] + qf[kk][2] * qf[kk][2];
            s1 += qf[kk][1] * qf[kk][1] + qf[kk][3] * qf[kk][3];
        }
        s0 += __shfl_xor_sync(FULLMASK, s0, 1);
        s0 += __shfl_xor_sync(FULLMASK, s0, 2);
        s1 += __shfl_xor_sync(FULLMASK, s1, 1);
        s1 += __shfl_xor_sync(FULLMASK, s1, 2);
        const float i0 = scale * LOG2E / fmaxf(sqrtf(s0), 1e-12f);
        const float i1 = scale * LOG2E / fmaxf(sqrtf(s1), 1e-12f);
        uint32_t aQ[4][4];
#pragma unroll
        for (int kk = 0; kk < 4; ++kk) {
            aQ[kk][0] = f2tf32(qf[kk][0] * i0);
            aQ[kk][1] = f2tf32(qf[kk][1] * i1);
            aQ[kk][2] = f2tf32(qf[kk][2] * i0);
            aQ[kk][3] = f2tf32(qf[kk][3] * i1);
        }

        unsigned char rq0 = 0, rq1 = 0;
        if (maskedw) {
            rq0 = region[v_lo ? r_lo : (NTOK - 1)];
            rq1 = region[v_hi ? r_hi : (NTOK - 1)];
        }
        const float* rpr_lo = rpbh + (size_t)(v_lo ? r_lo : 0) * RPBS;
        const float* rpr_hi = rpbh + (size_t)(v_hi ? r_hi : 0) * RPBS;

        float l0 = 0.f, l1 = 0.f;
        float o[4][4];
#pragma unroll
        for (int nt = 0; nt < 4; ++nt)
#pragma unroll
            for (int e = 0; e < 4; ++e) o[nt][e] = 0.f;

        for (int ch = 0; ch < 6; ++ch) {
            const int j0 = ch * 64;
            float s[8][4];
#pragma unroll
            for (int nt = 0; nt < 8; ++nt)
#pragma unroll
                for (int e = 0; e < 4; ++e) s[nt][e] = 0.f;
#pragma unroll
            for (int kk = 0; kk < 4; ++kk) {
#pragma unroll
                for (int nt = 0; nt < 8; ++nt) {
                    uint32_t bb[2];
                    bb[0] = Ks[(j0 + nt * 8 + gr) * 36 + kk * 8 + tg];
                    bb[1] = Ks[(j0 + nt * 8 + gr) * 36 + kk * 8 + tg + 4];
                    mma_tf32(s[nt], aQ[kk], bb);
                }
            }
            // bias + mask + exp2 + per-thread sums
#pragma unroll
            for (int nt = 0; nt < 8; ++nt) {
                const int jc = j0 + nt * 8 + tg * 2;
                float2 blo = *(const float2*)(rpr_lo + jc);
                float2 bhi = *(const float2*)(rpr_hi + jc);
                float t0 = s[nt][0] + blo.x - Mstat;
                float t1 = s[nt][1] + blo.y - Mstat;
                float t2 = s[nt][2] + bhi.x - Mstat;
                float t3 = s[nt][3] + bhi.y - Mstat;
                if (maskedw) {
                    unsigned char rk0 = region[jc];
                    unsigned char rk1 = region[jc + 1];
                    if (rk0 != rq0) t0 -= 144.26950408f;
                    if (rk1 != rq0) t1 -= 144.26950408f;
                    if (rk0 != rq1) t2 -= 144.26950408f;
                    if (rk1 != rq1) t3 -= 144.26950408f;
                }
                float p0 = exp2f(t0);
                float p1 = exp2f(t1);
                float p2 = exp2f(t2);
                float p3 = exp2f(t3);
                if (ch == 5) {
                    if (jc >= NTOK) { p0 = 0.f; p2 = 0.f; }
                    if (jc + 1 >= NTOK) { p1 = 0.f; p3 = 0.f; }
                }
                l0 += p0 + p1;
                l1 += p2 + p3;
                s[nt][0] = p0;
                s[nt][1] = p1;
                s[nt][2] = p2;
                s[nt][3] = p3;
            }
            // O += P * V : fp16 m16n8k16, acc frags pack directly into A-frags
#pragma unroll
            for (int kk2 = 0; kk2 < 4; ++kk2) {
                uint32_t aP[4];
                aP[0] = pack_h2(s[2 * kk2][0], s[2 * kk2][1]);
                aP[1] = pack_h2(s[2 * kk2][2], s[2 * kk2][3]);
                aP[2] = pack_h2(s[2 * kk2 + 1][0], s[2 * kk2 + 1][1]);
                aP[3] = pack_h2(s[2 * kk2 + 1][2], s[2 * kk2 + 1][3]);
                const int jb = j0 + kk2 * 16 + 2 * tg;
#pragma unroll
                for (int nt = 0; nt < 4; ++nt) {
                    const int d = nt * 8 + gr;
                    uint32_t b0 = *(const uint32_t*)&Vth[d * VTH_STRIDE + jb];
                    uint32_t b1 = *(const uint32_t*)&Vth[d * VTH_STRIDE + jb + 8];
                    mma_f16(o[nt], aP, b0, b1);
                }
            }
        }

        l0 += __shfl_xor_sync(FULLMASK, l0, 1);
        l0 += __shfl_xor_sync(FULLMASK, l0, 2);
        l1 += __shfl_xor_sync(FULLMASK, l1, 1);
        l1 += __shfl_xor_sync(FULLMASK, l1, 2);

        if (v_lo) {
            const float il0 = 1.f / l0;
            float* dst = g_attnout + ((size_t)b_ * NTOK + r_lo) * CDIM + h * HD;
#pragma unroll
            for (int nt = 0; nt < 4; ++nt)
                *(float2*)(dst + nt * 8 + tg * 2) =
                    make_float2(__uint_as_float(f2tf32(o[nt][0] * il0)),
                                __uint_as_float(f2tf32(o[nt][1] * il0)));
        }
        if (v_hi) {
            const float il1 = 1.f / l1;
            float* dst = g_attnout + ((size_t)b_ * NTOK + r_hi) * CDIM + h * HD;
#pragma unroll
            for (int nt = 0; nt < 4; ++nt)
                *(float2*)(dst + nt * 8 + tg * 2) =
                    make_float2(__uint_as_float(f2tf32(o[nt][2] * il1)),
                                __uint_as_float(f2tf32(o[nt][3] * il1)));
        }
    }
}

// ---------------- launch ---------------------------------------------------------
extern "C" void kernel_launch(void* const* d_in, const int* in_sizes, int n_in,
                              void* d_out, int out_size) {
    (void)in_sizes; (void)n_in; (void)out_size;
    const float* x = (const float*)d_in[0];
    const float* qkv_w = (const float*)d_in[1];
    const float* q_bias = (const float*)d_in[2];
    const float* v_bias = (const float*)d_in[3];
    const float* logit_scale = (const float*)d_in[4];
    const float* cpb_w1 = (const float*)d_in[5];
    const float* cpb_b1 = (const float*)d_in[6];
    const float* cpb_w2 = (const float*)d_in[7];
    const float* proj_w = (const float*)d_in[8];
    const float* proj_b = (const float*)d_in[9];
    const float* norm1_g = (const float*)d_in[10];
    const float* norm1_b = (const float*)d_in[11];
    const float* fc1_w = (const float*)d_in[12];
    const float* fc1_b = (const float*)d_in[13];
    const float* fc2_w = (const float*)d_in[14];
    const float* fc2_b = (const float*)d_in[15];
    const float* norm2_g = (const float*)d_in[16];
    const float* norm2_b = (const float*)d_in[17];
    float* out = (float*)d_out;

    static bool attr_done = false;
    if (!attr_done) {
        cudaFuncSetAttribute(attn4_kernel, cudaFuncAttributeMaxDynamicSharedMemorySize,
                             ATTN4_SMEM);
        cudaFuncSetAttribute(mma_gemm<0>, cudaFuncAttributeMaxDynamicSharedMemorySize,
                             GT_SMEM);
        cudaFuncSetAttribute(mma_gemm<2>, cudaFuncAttributeMaxDynamicSharedMemorySize,
                             GT_SMEM);
        cudaFuncSetAttribute(gemm_ln<0>, cudaFuncAttributeMaxDynamicSharedMemorySize,
                             LN_SMEM);
        cudaFuncSetAttribute(gemm_ln<1>, cudaFuncAttributeMaxDynamicSharedMemorySize,
                             LN_SMEM);
        attr_done = true;
    }

    // fused tf32 pre-conversion + CPB MLP
    cvt_cpb<<<1024 + 2197, 256>>>(x, qkv_w, proj_w, fc1_w, fc2_w,
                                  cpb_w1, cpb_b1, cpb_w2);

    // qkv (fused shift + window gather) + rpb table (extra 96 blocks at y>=343)
    mma_gemm<0><<<dim3(6, 343 + 16), 256, GT_SMEM>>>(q_bias, v_bias, 192);

    // attention (tensor-core flash, static max, exp2, fp16 PV)
    attn4_kernel<<<768, 256, ATTN4_SMEM>>>(logit_scale);

    // proj + LN + residual (fused window reverse + roll scatter): N=192, K=192
    gemm_ln<0><<<343, 512, LN_SMEM>>>(proj_b, x, norm1_g, norm1_b, nullptr, 192);

    // fc1: N=768, K=192 (GELU)
    mma_gemm<2><<<dim3(8, 343), 256, GT_SMEM>>>(fc1_b, nullptr, 192);

    // fc2 + LN + residual: N=192, K=768
    gemm_ln<1><<<343, 512, LN_SMEM>>>(fc2_b, nullptr, norm2_g, norm2_b, out, 768);
}

// round 15
// speedup vs baseline: 1.1121x; 1.0265x over previous
#include <cuda_runtime.h>
#include <cuda_fp16.h>
#include <math.h>
#include <stdint.h>

#define FULLMASK 0xffffffffu
#define LOG2E 1.4426950408889634f

// problem dims
#define NTOK   343
#define NHEAD  6
#define HD     32
#define CDIM   192
#define LTOT   21952
#define NWIN   128
#define NROWS  43904
#define RPBS   344

// ---------------- device scratch ------------------------------------------------
__device__ float g_hb[2197 * 6];
__device__ __align__(16) float g_rpb[6 * 343 * RPBS];
__device__ __align__(16) float g_q[(size_t)NWIN * NHEAD * NTOK * HD];
__device__ __align__(16) float g_k[(size_t)NWIN * NHEAD * NTOK * HD];
__device__ __align__(16) float g_v[(size_t)NWIN * NHEAD * NTOK * HD];
__device__ __align__(16) float g_attnout[(size_t)NWIN * NTOK * CDIM];   // tf32-rounded
__device__ __align__(16) float g_x1[(size_t)2 * LTOT * CDIM];           // fp32
__device__ __align__(16) float g_x1t[(size_t)2 * LTOT * CDIM];          // tf32-rounded
__device__ __align__(16) float g_xt[(size_t)2 * LTOT * CDIM];           // tf32-rounded
__device__ __align__(16) float g_hmid[(size_t)NROWS * 768];             // tf32-rounded
__device__ __align__(16) float g_wq[576 * 192];
__device__ __align__(16) float g_wp[192 * 192];
__device__ __align__(16) float g_w1[768 * 192];
__device__ __align__(16) float g_w2[192 * 768];

// ---------------- helpers -------------------------------------------------------
__device__ __forceinline__ uint32_t f2tf32(float x) {
    uint32_t r;
    asm("cvt.rna.tf32.f32 %0, %1;" : "=r"(r) : "f"(x));
    return r;
}

__device__ __forceinline__ void mma_tf32(float* c, const uint32_t* a, const uint32_t* b) {
    asm volatile(
        "mma.sync.aligned.m16n8k8.row.col.f32.tf32.tf32.f32 "
        "{%0,%1,%2,%3}, {%4,%5,%6,%7}, {%8,%9}, {%0,%1,%2,%3};"
        : "+f"(c[0]), "+f"(c[1]), "+f"(c[2]), "+f"(c[3])
        : "r"(a[0]), "r"(a[1]), "r"(a[2]), "r"(a[3]), "r"(b[0]), "r"(b[1]));
}

__device__ __forceinline__ void mma_f16(float* c, const uint32_t* a, uint32_t b0,
                                        uint32_t b1) {
    asm volatile(
        "mma.sync.aligned.m16n8k16.row.col.f32.f16.f16.f32 "
        "{%0,%1,%2,%3}, {%4,%5,%6,%7}, {%8,%9}, {%0,%1,%2,%3};"
        : "+f"(c[0]), "+f"(c[1]), "+f"(c[2]), "+f"(c[3])
        : "r"(a[0]), "r"(a[1]), "r"(a[2]), "r"(a[3]), "r"(b0), "r"(b1));
}

__device__ __forceinline__ uint32_t pack_h2(float lo, float hi) {
    uint32_t r;
    asm("cvt.rn.f16x2.f32 %0, %1, %2;" : "=r"(r) : "f"(hi), "f"(lo));
    return r;
}

__device__ __forceinline__ uint32_t smem_u32(const void* p) {
    uint32_t a;
    asm("{ .reg .u64 t; cvta.to.shared.u64 t, %1; cvt.u32.u64 %0, t; }" : "=r"(a) : "l"(p));
    return a;
}

__device__ __forceinline__ void cp16(uint32_t dst, const void* src) {
    asm volatile("cp.async.ca.shared.global [%0], [%1], 16;" :: "r"(dst), "l"(src));
}
#define CP_COMMIT() asm volatile("cp.async.commit_group;" ::: "memory")
#define CP_WAIT1()  asm volatile("cp.async.wait_group 1;" ::: "memory")

// ---------------- CPB coord helper ----------------------------------------------
__device__ __forceinline__ float cpb_coord(int i) {
    float v = (float)(i - 6) * (8.0f / 6.0f);
    float av = fabsf(v);
    float r = log2f(av + 1.0f) * (1.0f / 3.0f);
    return (v < 0.f) ? -r : r;
}

// ---------------- fused tf32 convert + CPB MLP kernel ----------------------------
__global__ void __launch_bounds__(256) cvt_cpb(const float* __restrict__ x,
                                               const float* __restrict__ wq,
                                               const float* __restrict__ wp,
                                               const float* __restrict__ w1cv,
                                               const float* __restrict__ w2cv,
                                               const float* __restrict__ cw1,
                                               const float* __restrict__ cb1,
                                               const float* __restrict__ cw2) {
    __shared__ float hid[512];
    if (blockIdx.x >= 1024) {
        int t = blockIdx.x - 1024;
        int a = t / 169;
        int rem = t - a * 169;
        int b = rem / 13;
        int c = rem - b * 13;
        float c0 = cpb_coord(a), c1 = cpb_coord(b), c2 = cpb_coord(c);
        for (int j = threadIdx.x; j < 512; j += blockDim.x) {
            float hv = c0 * cw1[j * 3 + 0] + c1 * cw1[j * 3 + 1] + c2 * cw1[j * 3 + 2] +
                       cb1[j];
            hid[j] = fmaxf(hv, 0.f);
        }
        __syncthreads();
        if (threadIdx.x < 192) {
            int hh = threadIdx.x >> 5, lane = threadIdx.x & 31;
            float s = 0.f;
            for (int j = lane; j < 512; j += 32) s += hid[j] * cw2[hh * 512 + j];
#pragma unroll
            for (int off = 16; off; off >>= 1) s += __shfl_xor_sync(FULLMASK, s, off);
            if (lane == 0) g_hb[t * 6 + hh] = s;
        }
        return;
    }
    const int N0 = 2107392;
    const int N1 = N0 + 27648;
    const int N2 = N1 + 9216;
    const int N3 = N2 + 36864;
    const int N4 = N3 + 36864;
    for (int i = blockIdx.x * blockDim.x + threadIdx.x; i < N4; i += 1024 * 256) {
        const float4* s;
        uint4* d;
        int off;
        if (i < N0) { s = (const float4*)x; d = (uint4*)g_xt; off = i; }
        else if (i < N1) { s = (const float4*)wq; d = (uint4*)g_wq; off = i - N0; }
        else if (i < N2) { s = (const float4*)wp; d = (uint4*)g_wp; off = i - N1; }
        else if (i < N3) { s = (const float4*)w1cv; d = (uint4*)g_w1; off = i - N2; }
        else { s = (const float4*)w2cv; d = (uint4*)g_w2; off = i - N3; }
        float4 v = s[off];
        uint4 u;
        u.x = f2tf32(v.x);
        u.y = f2tf32(v.y);
        u.z = f2tf32(v.z);
        u.w = f2tf32(v.w);
        d[off] = u;
    }
}

// ---------------- tf32 mma GEMM, BK=32, cp.async 3-stage pipeline ----------------
#define BM 128
#define BN 96
#define BK2 32
#define SPAD2 36
#define A2_WORDS (BM * SPAD2)
#define B2_WORDS (BN * SPAD2)
#define GT_SMEM (3 * (A2_WORDS + B2_WORDS) * 4)

template <int MODE>
__global__ void __launch_bounds__(256) mma_gemm(const float* __restrict__ bias1,
                                                const float* __restrict__ bias2,
                                                int K) {
    if (MODE == 0 && blockIdx.y >= 343) {
        const int total = 6 * 343 * RPBS;
        const int slice = blockIdx.x + 6 * (blockIdx.y - 343);
        const int per = 7376;
        const int start = slice * per;
        const int end = (start + per < total) ? (start + per) : total;
        for (int idx = start + threadIdx.x; idx < end; idx += 256) {
            int hh = idx / (343 * RPBS);
            int rem = idx - hh * (343 * RPBS);
            int i = rem / RPBS;
            int j = rem - i * RPBS;
            if (j >= 343) {
                g_rpb[idx] = 0.f;
                continue;
            }
            int dh = i / 49 - j / 49 + 6;
            int dw = (i / 7) % 7 - (j / 7) % 7 + 6;
            int dd = i % 7 - j % 7 + 6;
            int tix = (dh * 13 + dw) * 13 + dd;
            float v = g_hb[tix * 6 + hh];
            g_rpb[idx] = (16.f / (1.f + __expf(-v))) * LOG2E;
        }
        return;
    }

    extern __shared__ uint32_t sh[];
    uint32_t* As = sh;
    uint32_t* Bs = sh + 3 * A2_WORDS;
    const uint32_t sbA = smem_u32(As);
    const uint32_t sbB = smem_u32(Bs);

    const int tid = threadIdx.x;
    const int lane = tid & 31;
    const int warp = tid >> 5;
    const int warpM = warp & 3;
    const int warpN = warp >> 2;
    const int gr = lane >> 2;
    const int tg = lane & 3;

    const int m0 = blockIdx.y * BM;
    const int n0 = blockIdx.x * BN;

    const float* Asrc = (MODE == 0) ? g_xt : g_x1t;
    const float* W = (MODE == 0) ? g_wq : g_w1;

    const float* aptr[4];
    uint32_t aoffB[4];
#pragma unroll
    for (int i = 0; i < 4; ++i) {
        int idx = tid + i * 256;
        int arow = idx >> 3, c8 = idx & 7;
        int rho = m0 + arow;
        const float* p;
        if (MODE == 0) {
            int b_ = rho / 343, n = rho - b_ * 343;
            int bb = b_ >> 6, win = b_ & 63;
            int wa = win >> 4, wb = (win >> 2) & 3, wc = win & 3;
            int ii = n / 49, jj = (n / 7) % 7, kk = n % 7;
            int hs = (wa * 7 + ii + 3) % 28;
            int ws = (wb * 7 + jj + 3) % 28;
            int ds = (wc * 7 + kk + 3) % 28;
            p = Asrc + ((size_t)bb * LTOT + (hs * 784 + ws * 28 + ds)) * CDIM;
        } else {
            p = Asrc + (size_t)rho * K;
        }
        aptr[i] = p + c8 * 4;
        aoffB[i] = (arow * SPAD2 + c8 * 4) * 4;
    }
    const float* bptr[3];
    uint32_t boff[3];
#pragma unroll
    for (int i = 0; i < 3; ++i) {
        int idx = tid + i * 256;
        int brow = idx >> 3, c8 = idx & 7;
        bptr[i] = W + (size_t)(n0 + brow) * K + c8 * 4;
        boff[i] = (brow * SPAD2 + c8 * 4) * 4;
    }

    float acc[2][6][4];
#pragma unroll
    for (int mi = 0; mi < 2; ++mi)
#pragma unroll
        for (int ni = 0; ni < 6; ++ni)
#pragma unroll
            for (int e = 0; e < 4; ++e) acc[mi][ni][e] = 0.f;

    const int ntiles = K >> 5;
#pragma unroll
    for (int s = 0; s < 2; ++s) {
        const int kt = s * BK2;
#pragma unroll
        for (int i = 0; i < 4; ++i) cp16(sbA + s * (A2_WORDS * 4) + aoffB[i], aptr[i] + kt);
#pragma unroll
        for (int i = 0; i < 3; ++i) cp16(sbB + s * (B2_WORDS * 4) + boff[i], bptr[i] + kt);
        CP_COMMIT();
    }

    for (int t = 0; t < ntiles; ++t) {
        const int buf = t % 3;
        CP_WAIT1();
        __syncthreads();

        const uint32_t* Ab = As + buf * A2_WORDS;
        const uint32_t* Bb = Bs + buf * B2_WORDS;
#pragma unroll
        for (int kk = 0; kk < 32; kk += 8) {
            uint32_t afr[2][4];
#pragma unroll
            for (int mi = 0; mi < 2; ++mi) {
                int rb = warpM * 32 + mi * 16;
                afr[mi][0] = Ab[(rb + gr) * SPAD2 + kk + tg];
                afr[mi][1] = Ab[(rb + gr + 8) * SPAD2 + kk + tg];
                afr[mi][2] = Ab[(rb + gr) * SPAD2 + kk + tg + 4];
                afr[mi][3] = Ab[(rb + gr + 8) * SPAD2 + kk + tg + 4];
            }
            uint32_t bfr[6][2];
#pragma unroll
            for (int ni = 0; ni < 6; ++ni) {
                int nb = warpN * 48 + ni * 8 + gr;
                bfr[ni][0] = Bb[nb * SPAD2 + kk + tg];
                bfr[ni][1] = Bb[nb * SPAD2 + kk + tg + 4];
            }
#pragma unroll
            for (int mi = 0; mi < 2; ++mi)
#pragma unroll
                for (int ni = 0; ni < 6; ++ni)
                    mma_tf32(acc[mi][ni], afr[mi], bfr[ni]);
        }

        const int tn = t + 2;
        if (tn < ntiles) {
            const int s = tn % 3;
            const int kt = tn * BK2;
#pragma unroll
            for (int i = 0; i < 4; ++i)
                cp16(sbA + s * (A2_WORDS * 4) + aoffB[i], aptr[i] + kt);
#pragma unroll
            for (int i = 0; i < 3; ++i)
                cp16(sbB + s * (B2_WORDS * 4) + boff[i], bptr[i] + kt);
        }
        CP_COMMIT();
    }

#pragma unroll
    for (int mi = 0; mi < 2; ++mi) {
        int rows[2];
        rows[0] = m0 + warpM * 32 + mi * 16 + gr;
        rows[1] = rows[0] + 8;
#pragma unroll
        for (int half = 0; half < 2; ++half) {
            const int r = rows[half];
            int b_ = 0, n = 0;
            if (MODE == 0) {
                b_ = r / 343;
                n = r - b_ * 343;
            }
#pragma unroll
            for (int ni = 0; ni < 6; ++ni) {
                int c = n0 + warpN * 48 + ni * 8 + tg * 2;
                float v0 = acc[mi][ni][half * 2 + 0];
                float v1 = acc[mi][ni][half * 2 + 1];
                if (MODE == 0) {
                    int sct = c / 192;
                    int remc = c - sct * 192;
                    int hh = remc >> 5, dd = remc & 31;
                    float* dst = (sct == 0 ? g_q : (sct == 1 ? g_k : g_v)) +
                                 ((size_t)(b_ * 6 + hh) * NTOK + n) * HD + dd;
                    float e0 = 0.f, e1 = 0.f;
                    if (sct == 0) { e0 = bias1[remc]; e1 = bias1[remc + 1]; }
                    else if (sct == 2) { e0 = bias2[remc]; e1 = bias2[remc + 1]; }
                    *(float2*)dst = make_float2(v0 + e0, v1 + e1);
                } else {
                    float x0 = v0 + bias1[c], x1 = v1 + bias1[c + 1];
                    float g0 = 0.5f * x0 * (1.f + erff(x0 * 0.70710678118654752f));
                    float g1 = 0.5f * x1 * (1.f + erff(x1 * 0.70710678118654752f));
                    *(float2*)(g_hmid + (size_t)r * 768 + c) =
                        make_float2(__uint_as_float(f2tf32(g0)),
                                    __uint_as_float(f2tf32(g1)));
                }
            }
        }
    }
}

// ---------------- GEMM (BN=192) + fused LayerNorm + residual, BK=32 --------------
#define B2L_WORDS (192 * SPAD2)
#define LN_SMEM ((3 * (A2_WORDS + B2L_WORDS) + 128 * 4 * 2) * 4)

template <int MODE>
__global__ void __launch_bounds__(512) gemm_ln(const float* __restrict__ bias,
                                               const float* __restrict__ basex,
                                               const float* __restrict__ gw,
                                               const float* __restrict__ bw,
                                               float* __restrict__ outp,
                                               int K) {
    extern __shared__ uint32_t sh[];
    uint32_t* Asm = sh;
    uint32_t* Bsm = sh + 3 * A2_WORDS;
    float* part = (float*)(sh + 3 * A2_WORDS + 3 * B2L_WORDS);
    const uint32_t sbA = smem_u32(Asm);
    const uint32_t sbB = smem_u32(Bsm);

    const int tid = threadIdx.x;
    const int lane = tid & 31;
    const int warp = tid >> 5;
    const int warpM = warp & 3;
    const int warpN = warp >> 2;
    const int gr = lane >> 2;
    const int tg = lane & 3;

    const int m0 = blockIdx.x * BM;

    const float* Asrc = (MODE == 0) ? g_attnout : g_hmid;
    const float* W = (MODE == 0) ? g_wp : g_w2;

    const float* aptr[2];
    uint32_t aoff[2];
#pragma unroll
    for (int i = 0; i < 2; ++i) {
        int idx = tid + i * 512;
        int arow = idx >> 3, c8 = idx & 7;
        aptr[i] = Asrc + (size_t)(m0 + arow) * K + c8 * 4;
        aoff[i] = (arow * SPAD2 + c8 * 4) * 4;
    }
    const float* bptr[3];
    uint32_t boff[3];
#pragma unroll
    for (int i = 0; i < 3; ++i) {
        int idx = tid + i * 512;
        int brow = idx >> 3, c8 = idx & 7;
        bptr[i] = W + (size_t)brow * K + c8 * 4;
        boff[i] = (brow * SPAD2 + c8 * 4) * 4;
    }

    float acc[2][6][4];
#pragma unroll
    for (int mi = 0; mi < 2; ++mi)
#pragma unroll
        for (int ni = 0; ni < 6; ++ni)
#pragma unroll
            for (int e = 0; e < 4; ++e) acc[mi][ni][e] = 0.f;

    const int ntiles = K >> 5;
#pragma unroll
    for (int s = 0; s < 2; ++s) {
        const int kt = s * BK2;
#pragma unroll
        for (int i = 0; i < 2; ++i) cp16(sbA + s * (A2_WORDS * 4) + aoff[i], aptr[i] + kt);
#pragma unroll
        for (int i = 0; i < 3; ++i) cp16(sbB + s * (B2L_WORDS * 4) + boff[i], bptr[i] + kt);
        CP_COMMIT();
    }

    for (int t = 0; t < ntiles; ++t) {
        const int buf = t % 3;
        CP_WAIT1();
        __syncthreads();

        const uint32_t* Ab = Asm + buf * A2_WORDS;
        const uint32_t* Bb = Bsm + buf * B2L_WORDS;
#pragma unroll
        for (int kk = 0; kk < 32; kk += 8) {
            uint32_t afr[2][4];
#pragma unroll
            for (int mi = 0; mi < 2; ++mi) {
                int rb = warpM * 32 + mi * 16;
                afr[mi][0] = Ab[(rb + gr) * SPAD2 + kk + tg];
                afr[mi][1] = Ab[(rb + gr + 8) * SPAD2 + kk + tg];
                afr[mi][2] = Ab[(rb + gr) * SPAD2 + kk + tg + 4];
                afr[mi][3] = Ab[(rb + gr + 8) * SPAD2 + kk + tg + 4];
            }
            uint32_t bfr[6][2];
#pragma unroll
            for (int ni = 0; ni < 6; ++ni) {
                int nb = warpN * 48 + ni * 8 + gr;
                bfr[ni][0] = Bb[nb * SPAD2 + kk + tg];
                bfr[ni][1] = Bb[nb * SPAD2 + kk + tg + 4];
            }
#pragma unroll
            for (int mi = 0; mi < 2; ++mi)
#pragma unroll
                for (int ni = 0; ni < 6; ++ni)
                    mma_tf32(acc[mi][ni], afr[mi], bfr[ni]);
        }

        const int tn = t + 2;
        if (tn < ntiles) {
            const int s = tn % 3;
            const int kt = tn * BK2;
#pragma unroll
            for (int i = 0; i < 2; ++i)
                cp16(sbA + s * (A2_WORDS * 4) + aoff[i], aptr[i] + kt);
#pragma unroll
            for (int i = 0; i < 3; ++i)
                cp16(sbB + s * (B2L_WORDS * 4) + boff[i], bptr[i] + kt);
        }
        CP_COMMIT();
    }
    __syncthreads();

#pragma unroll
    for (int mi = 0; mi < 2; ++mi) {
#pragma unroll
        for (int half = 0; half < 2; ++half) {
            const int rl = warpM * 32 + mi * 16 + gr + half * 8;
            float s = 0.f, sq = 0.f;
#pragma unroll
            for (int ni = 0; ni < 6; ++ni) {
                int c = warpN * 48 + ni * 8 + tg * 2;
                float v0 = acc[mi][ni][half * 2 + 0] + bias[c];
                float v1 = acc[mi][ni][half * 2 + 1] + bias[c + 1];
                acc[mi][ni][half * 2 + 0] = v0;
                acc[mi][ni][half * 2 + 1] = v1;
                s += v0 + v1;
                sq += v0 * v0 + v1 * v1;
            }
            s += __shfl_xor_sync(FULLMASK, s, 1);
            s += __shfl_xor_sync(FULLMASK, s, 2);
            sq += __shfl_xor_sync(FULLMASK, sq, 1);
            sq += __shfl_xor_sync(FULLMASK, sq, 2);
            if (tg == 0) {
                part[(rl * 4 + warpN) * 2 + 0] = s;
                part[(rl * 4 + warpN) * 2 + 1] = sq;
            }
        }
    }
    __syncthreads();

#pragma unroll
    for (int mi = 0; mi < 2; ++mi) {
#pragma unroll
        for (int half = 0; half < 2; ++half) {
            const int rl = warpM * 32 + mi * 16 + gr + half * 8;
            const int r = m0 + rl;
            float s = 0.f, sq = 0.f;
#pragma unroll
            for (int g2 = 0; g2 < 4; ++g2) {
                s += part[(rl * 4 + g2) * 2 + 0];
                sq += part[(rl * 4 + g2) * 2 + 1];
            }
            float mean = s * (1.f / 192.f);
            float var = sq * (1.f / 192.f) - mean * mean;
            float inv = rsqrtf(var + 1e-5f);

            const float* bsrow;
            float* orow;
            float* orow2 = nullptr;
            if (MODE == 0) {
                int b_ = r / 343, n = r - b_ * 343;
                int bb2 = b_ >> 6, win = b_ & 63;
                int wa = win >> 4, wb = (win >> 2) & 3, wc = win & 3;
                int i3 = n / 49, j3 = (n / 7) % 7, k3 = n % 7;
                int hd_ = (wa * 7 + i3 + 3) % 28;
                int wd_ = (wb * 7 + j3 + 3) % 28;
                int dd_ = (wc * 7 + k3 + 3) % 28;
                size_t pos = ((size_t)bb2 * LTOT + (hd_ * 784 + wd_ * 28 + dd_)) * CDIM;
                bsrow = basex + pos;
                orow = g_x1 + pos;
                orow2 = g_x1t + pos;
            } else {
                bsrow = g_x1 + (size_t)r * CDIM;
                orow = outp + (size_t)r * CDIM;
            }
#pragma unroll
            for (int ni = 0; ni < 6; ++ni) {
                int c = warpN * 48 + ni * 8 + tg * 2;
                float v0 = acc[mi][ni][half * 2 + 0];
                float v1 = acc[mi][ni][half * 2 + 1];
                float2 bse = *(const float2*)(bsrow + c);
                float2 gg = *(const float2*)(gw + c);
                float2 bb = *(const float2*)(bw + c);
                float o0 = bse.x + (v0 - mean) * inv * gg.x + bb.x;
                float o1 = bse.y + (v1 - mean) * inv * gg.y + bb.y;
                *(float2*)(orow + c) = make_float2(o0, o1);
                if (MODE == 0)
                    *(float2*)(orow2 + c) =
                        make_float2(__uint_as_float(f2tf32(o0)),
                                    __uint_as_float(f2tf32(o1)));
            }
        }
    }
}

// ---------------- tensor-core flash attention (fp16 QK + PV, static max, exp2) ---
#define KH_STRIDE 40
#define KH_BYTES (384 * KH_STRIDE * 2)
#define VTH_STRIDE 392
#define VTH_BYTES (32 * VTH_STRIDE * 2)
#define ATTN4_SMEM (KH_BYTES + VTH_BYTES + 512)

__global__ void __launch_bounds__(256, 2) attn4_kernel(const float* __restrict__ logit_scale) {
    extern __shared__ uint32_t asmem[];
    __half* Ksh = (__half*)asmem;                          // [384][40] fp16 normalized K
    __half* Vth = (__half*)((char*)asmem + KH_BYTES);      // [32][392] fp16 V^T
    unsigned char* region = (unsigned char*)((char*)Vth + VTH_BYTES);

    const int bh = blockIdx.x;
    const int b_ = bh / 6, h = bh - (bh / 6) * 6;
    const int tid = threadIdx.x;
    const int lane = tid & 31, warp = tid >> 5;
    const int gr = lane >> 2, tg = lane & 3;

    const size_t kvbase = (size_t)bh * (NTOK * HD);
    const float* kg = g_k + kvbase;
    const float* vg = g_v + kvbase;
    const float* qg = g_q + kvbase;

    for (int r = warp; r < 384; r += 8) {
        if (r < NTOK) {
            float v = kg[r * 32 + lane];
            float s = v * v;
#pragma unroll
            for (int o = 16; o; o >>= 1) s += __shfl_xor_sync(FULLMASK, s, o);
            float inv = 1.f / fmaxf(sqrtf(s), 1e-12f);
            Ksh[r * KH_STRIDE + lane] = __float2half(v * inv);
        } else {
            Ksh[r * KH_STRIDE + lane] = __float2half(0.f);
        }
    }
    for (int idx = tid; idx < NTOK * 32; idx += 256) {
        int j = idx >> 5, d = idx & 31;
        Vth[d * VTH_STRIDE + j] = __float2half(vg[idx]);
    }
    for (int idx = tid; idx < 32 * (VTH_STRIDE - NTOK); idx += 256) {
        int d = idx / (VTH_STRIDE - NTOK);
        int j = NTOK + idx - d * (VTH_STRIDE - NTOK);
        Vth[d * VTH_STRIDE + j] = __float2half(0.f);
    }
    const int win = b_ & 63;
    const int wa = win >> 4, wb = (win >> 2) & 3, wc = win & 3;
    const bool maskedw = (wa == 3) || (wb == 3) || (wc == 3);
    if (maskedw) {
        for (int t = tid; t < 384; t += 256) {
            if (t < NTOK) {
                int ih = t / 49, iw = (t / 7) % 7, id = t % 7;
                int rH = (wa < 3) ? 0 : ((ih < 4) ? 1 : 2);
                int rW = (wb < 3) ? 0 : ((iw < 4) ? 1 : 2);
                int rD = (wc < 3) ? 0 : ((id < 4) ? 1 : 2);
                region[t] = (unsigned char)(rH * 9 + rW * 3 + rD);
            } else {
                region[t] = 0;
            }
        }
    }
    __syncthreads();

    const float scale = __expf(fminf(logit_scale[h], 4.6051701859880914f));
    const float Mstat = (scale + 16.f) * LOG2E;
    const float* rpbh = g_rpb + (size_t)h * (343 * RPBS);

    for (int rb = 0; rb < 3; ++rb) {
        const int r0 = rb * 128 + warp * 16;
        if (r0 >= NTOK) continue;

        const int r_lo = r0 + gr, r_hi = r0 + gr + 8;
        const bool v_lo = r_lo < NTOK, v_hi = r_hi < NTOK;

        // Q values for k16 A-frag layout: d = kk*16 + {2tg,2tg+1,2tg+8,2tg+9}
        float qv[2][2][4];   // [kk][row(lo/hi)][elem]
        const float* qlo = qg + (size_t)(v_lo ? r_lo : 0) * 32;
        const float* qhi = qg + (size_t)(v_hi ? r_hi : 0) * 32;
#pragma unroll
        for (int kk = 0; kk < 2; ++kk) {
            const int d0 = kk * 16 + 2 * tg;
            qv[kk][0][0] = v_lo ? qlo[d0] : 0.f;
            qv[kk][0][1] = v_lo ? qlo[d0 + 1] : 0.f;
            qv[kk][0][2] = v_lo ? qlo[d0 + 8] : 0.f;
            qv[kk][0][3] = v_lo ? qlo[d0 + 9] : 0.f;
            qv[kk][1][0] = v_hi ? qhi[d0] : 0.f;
            qv[kk][1][1] = v_hi ? qhi[d0 + 1] : 0.f;
            qv[kk][1][2] = v_hi ? qhi[d0 + 8] : 0.f;
            qv[kk][1][3] = v_hi ? qhi[d0 + 9] : 0.f;
        }
        float s0 = 0.f, s1 = 0.f;
#pragma unroll
        for (int kk = 0; kk < 2; ++kk)
#pragma unroll
            for (int e = 0; e < 4; ++e) {
                s0 += qv[kk][0][e] * qv[kk][0][e];
                s1 += qv[kk][1][e] * qv[kk][1][e];
            }
        s0 += __shfl_xor_sync(FULLMASK, s0, 1);
        s0 += __shfl_xor_sync(FULLMASK, s0, 2);
        s1 += __shfl_xor_sync(FULLMASK, s1, 1);
        s1 += __shfl_xor_sync(FULLMASK, s1, 2);
        const float i0 = scale * LOG2E / fmaxf(sqrtf(s0), 1e-12f);
        const float i1 = scale * LOG2E / fmaxf(sqrtf(s1), 1e-12f);
        uint32_t aQh[2][4];
#pragma unroll
        for (int kk = 0; kk < 2; ++kk) {
            aQh[kk][0] = pack_h2(qv[kk][0][0] * i0, qv[kk][0][1] * i0);
            aQh[kk][1] = pack_h2(qv[kk][1][0] * i1, qv[kk][1][1] * i1);
            aQh[kk][2] = pack_h2(qv[kk][0][2] * i0, qv[kk][0][3] * i0);
            aQh[kk][3] = pack_h2(qv[kk][1][2] * i1, qv[kk][1][3] * i1);
        }

        unsigned char rq0 = 0, rq1 = 0;
        if (maskedw) {
            rq0 = region[v_lo ? r_lo : (NTOK - 1)];
            rq1 = region[v_hi ? r_hi : (NTOK - 1)];
        }
        const float* rpr_lo = rpbh + (size_t)(v_lo ? r_lo : 0) * RPBS;
        const float* rpr_hi = rpbh + (size_t)(v_hi ? r_hi : 0) * RPBS;

        float l0 = 0.f, l1 = 0.f;
        float o[4][4];
#pragma unroll
        for (int nt = 0; nt < 4; ++nt)
#pragma unroll
            for (int e = 0; e < 4; ++e) o[nt][e] = 0.f;

        for (int ch = 0; ch < 6; ++ch) {
            const int j0 = ch * 64;
            float s[8][4];
#pragma unroll
            for (int nt = 0; nt < 8; ++nt)
#pragma unroll
                for (int e = 0; e < 4; ++e) s[nt][e] = 0.f;
            // QK^T: fp16 m16n8k16, 2 k-steps over HD=32
#pragma unroll
            for (int kk = 0; kk < 2; ++kk) {
#pragma unroll
                for (int nt = 0; nt < 8; ++nt) {
                    const __half* kp = Ksh + (j0 + nt * 8 + gr) * KH_STRIDE + kk * 16 +
                                       2 * tg;
                    uint32_t b0 = *(const uint32_t*)kp;
                    uint32_t b1 = *(const uint32_t*)(kp + 8);
                    mma_f16(s[nt], aQh[kk], b0, b1);
                }
            }
            // bias + mask + exp2 + per-thread sums
#pragma unroll
            for (int nt = 0; nt < 8; ++nt) {
                const int jc = j0 + nt * 8 + tg * 2;
                float2 blo = *(const float2*)(rpr_lo + jc);
                float2 bhi = *(const float2*)(rpr_hi + jc);
                float t0 = s[nt][0] + blo.x - Mstat;
                float t1 = s[nt][1] + blo.y - Mstat;
                float t2 = s[nt][2] + bhi.x - Mstat;
                float t3 = s[nt][3] + bhi.y - Mstat;
                if (maskedw) {
                    unsigned char rk0 = region[jc];
                    unsigned char rk1 = region[jc + 1];
                    if (rk0 != rq0) t0 -= 144.26950408f;
                    if (rk1 != rq0) t1 -= 144.26950408f;
                    if (rk0 != rq1) t2 -= 144.26950408f;
                    if (rk1 != rq1) t3 -= 144.26950408f;
                }
                float p0 = exp2f(t0);
                float p1 = exp2f(t1);
                float p2 = exp2f(t2);
                float p3 = exp2f(t3);
                if (ch == 5) {
                    if (jc >= NTOK) { p0 = 0.f; p2 = 0.f; }
                    if (jc + 1 >= NTOK) { p1 = 0.f; p3 = 0.f; }
                }
                l0 += p0 + p1;
                l1 += p2 + p3;
                s[nt][0] = p0;
                s[nt][1] = p1;
                s[nt][2] = p2;
                s[nt][3] = p3;
            }
            // O += P * V : fp16 m16n8k16, acc frags pack directly into A-frags
#pragma unroll
            for (int kk2 = 0; kk2 < 4; ++kk2) {
                uint32_t aP[4];
                aP[0] = pack_h2(s[2 * kk2][0], s[2 * kk2][1]);
                aP[1] = pack_h2(s[2 * kk2][2], s[2 * kk2][3]);
                aP[2] = pack_h2(s[2 * kk2 + 1][0], s[2 * kk2 + 1][1]);
                aP[3] = pack_h2(s[2 * kk2 + 1][2], s[2 * kk2 + 1][3]);
                const int jb = j0 + kk2 * 16 + 2 * tg;
#pragma unroll
                for (int nt = 0; nt < 4; ++nt) {
                    const int d = nt * 8 + gr;
                    uint32_t b0 = *(const uint32_t*)&Vth[d * VTH_STRIDE + jb];
                    uint32_t b1 = *(const uint32_t*)&Vth[d * VTH_STRIDE + jb + 8];
                    mma_f16(o[nt], aP, b0, b1);
                }
            }
        }

        l0 += __shfl_xor_sync(FULLMASK, l0, 1);
        l0 += __shfl_xor_sync(FULLMASK, l0, 2);
        l1 += __shfl_xor_sync(FULLMASK, l1, 1);
        l1 += __shfl_xor_sync(FULLMASK, l1, 2);

        if (v_lo) {
            const float il0 = 1.f / l0;
            float* dst = g_attnout + ((size_t)b_ * NTOK + r_lo) * CDIM + h * HD;
#pragma unroll
            for (int nt = 0; nt < 4; ++nt)
                *(float2*)(dst + nt * 8 + tg * 2) =
                    make_float2(__uint_as_float(f2tf32(o[nt][0] * il0)),
                                __uint_as_float(f2tf32(o[nt][1] * il0)));
        }
        if (v_hi) {
            const float il1 = 1.f / l1;
            float* dst = g_attnout + ((size_t)b_ * NTOK + r_hi) * CDIM + h * HD;
#pragma unroll
            for (int nt = 0; nt < 4; ++nt)
                *(float2*)(dst + nt * 8 + tg * 2) =
                    make_float2(__uint_as_float(f2tf32(o[nt][2] * il1)),
                                __uint_as_float(f2tf32(o[nt][3] * il1)));
        }
    }
}

// ---------------- launch ---------------------------------------------------------
extern "C" void kernel_launch(void* const* d_in, const int* in_sizes, int n_in,
                              void* d_out, int out_size) {
    (void)in_sizes; (void)n_in; (void)out_size;
    const float* x = (const float*)d_in[0];
    const float* qkv_w = (const float*)d_in[1];
    const float* q_bias = (const float*)d_in[2];
    const float* v_bias = (const float*)d_in[3];
    const float* logit_scale = (const float*)d_in[4];
    const float* cpb_w1 = (const float*)d_in[5];
    const float* cpb_b1 = (const float*)d_in[6];
    const float* cpb_w2 = (const float*)d_in[7];
    const float* proj_w = (const float*)d_in[8];
    const float* proj_b = (const float*)d_in[9];
    const float* norm1_g = (const float*)d_in[10];
    const float* norm1_b = (const float*)d_in[11];
    const float* fc1_w = (const float*)d_in[12];
    const float* fc1_b = (const float*)d_in[13];
    const float* fc2_w = (const float*)d_in[14];
    const float* fc2_b = (const float*)d_in[15];
    const float* norm2_g = (const float*)d_in[16];
    const float* norm2_b = (const float*)d_in[17];
    float* out = (float*)d_out;

    static bool attr_done = false;
    if (!attr_done) {
        cudaFuncSetAttribute(attn4_kernel, cudaFuncAttributeMaxDynamicSharedMemorySize,
                             ATTN4_SMEM);
        cudaFuncSetAttribute(mma_gemm<0>, cudaFuncAttributeMaxDynamicSharedMemorySize,
                             GT_SMEM);
        cudaFuncSetAttribute(mma_gemm<2>, cudaFuncAttributeMaxDynamicSharedMemorySize,
                             GT_SMEM);
        cudaFuncSetAttribute(gemm_ln<0>, cudaFuncAttributeMaxDynamicSharedMemorySize,
                             LN_SMEM);
        cudaFuncSetAttribute(gemm_ln<1>, cudaFuncAttributeMaxDynamicSharedMemorySize,
                             LN_SMEM);
        attr_done = true;
    }

    // fused tf32 pre-conversion + CPB MLP
    cvt_cpb<<<1024 + 2197, 256>>>(x, qkv_w, proj_w, fc1_w, fc2_w,
                                  cpb_w1, cpb_b1, cpb_w2);

    // qkv (fused shift + window gather) + rpb table (extra 96 blocks at y>=343)
    mma_gemm<0><<<dim3(6, 343 + 16), 256, GT_SMEM>>>(q_bias, v_bias, 192);

    // attention (tensor-core flash, fp16 QK+PV, static max, exp2)
    attn4_kernel<<<768, 256, ATTN4_SMEM>>>(logit_scale);

    // proj + LN + residual (fused window reverse + roll scatter): N=192, K=192
    gemm_ln<0><<<343, 512, LN_SMEM>>>(proj_b, x, norm1_g, norm1_b, nullptr, 192);

    // fc1: N=768, K=192 (GELU)
    mma_gemm<2><<<dim3(8, 343), 256, GT_SMEM>>>(fc1_b, nullptr, 192);

    // fc2 + LN + residual: N=192, K=768
    gemm_ln<1><<<343, 512, LN_SMEM>>>(fc2_b, nullptr, norm2_g, norm2_b, out, 768);
}

// round 16
// speedup vs baseline: 1.4084x; 1.2664x over previous
#include <cuda_runtime.h>
#include <cuda_fp16.h>
#include <math.h>
#include <stdint.h>

#define FULLMASK 0xffffffffu
#define LOG2E 1.4426950408889634f

// problem dims
#define NTOK   343
#define NHEAD  6
#define HD     32
#define CDIM   192
#define LTOT   21952
#define NWIN   128
#define NROWS  43904
#define RPBS   344

// ---------------- device scratch ------------------------------------------------
__device__ float g_hb[2197 * 6];
__device__ __align__(16) float g_rpb[6 * 343 * RPBS];
__device__ __align__(16) float g_q[(size_t)NWIN * NHEAD * NTOK * HD];
__device__ __align__(16) float g_k[(size_t)NWIN * NHEAD * NTOK * HD];
__device__ __align__(16) float g_v[(size_t)NWIN * NHEAD * NTOK * HD];
__device__ __align__(16) __half g_attnout[(size_t)NWIN * NTOK * CDIM];
__device__ __align__(16) float g_x1[(size_t)2 * LTOT * CDIM];           // fp32
__device__ __align__(16) __half g_x1t[(size_t)2 * LTOT * CDIM];
__device__ __align__(16) __half g_xt[(size_t)2 * LTOT * CDIM];
__device__ __align__(16) __half g_hmid[(size_t)NROWS * 768];
__device__ __align__(16) __half g_wq[576 * 192];
__device__ __align__(16) __half g_wp[192 * 192];
__device__ __align__(16) __half g_w1[768 * 192];
__device__ __align__(16) __half g_w2[192 * 768];

// ---------------- helpers -------------------------------------------------------
__device__ __forceinline__ uint32_t f2tf32(float x) {
    uint32_t r;
    asm("cvt.rna.tf32.f32 %0, %1;" : "=r"(r) : "f"(x));
    return r;
}

__device__ __forceinline__ void mma_f16(float* c, const uint32_t* a, uint32_t b0,
                                        uint32_t b1) {
    asm volatile(
        "mma.sync.aligned.m16n8k16.row.col.f32.f16.f16.f32 "
        "{%0,%1,%2,%3}, {%4,%5,%6,%7}, {%8,%9}, {%0,%1,%2,%3};"
        : "+f"(c[0]), "+f"(c[1]), "+f"(c[2]), "+f"(c[3])
        : "r"(a[0]), "r"(a[1]), "r"(a[2]), "r"(a[3]), "r"(b0), "r"(b1));
}

__device__ __forceinline__ uint32_t pack_h2(float lo, float hi) {
    uint32_t r;
    asm("cvt.rn.f16x2.f32 %0, %1, %2;" : "=r"(r) : "f"(hi), "f"(lo));
    return r;
}

__device__ __forceinline__ uint32_t smem_u32(const void* p) {
    uint32_t a;
    asm("{ .reg .u64 t; cvta.to.shared.u64 t, %1; cvt.u32.u64 %0, t; }" : "=r"(a) : "l"(p));
    return a;
}

__device__ __forceinline__ void cp16(uint32_t dst, const void* src) {
    asm volatile("cp.async.ca.shared.global [%0], [%1], 16;" :: "r"(dst), "l"(src));
}
#define CP_COMMIT() asm volatile("cp.async.commit_group;" ::: "memory")
#define CP_WAIT1()  asm volatile("cp.async.wait_group 1;" ::: "memory")

// ---------------- CPB coord helper ----------------------------------------------
__device__ __forceinline__ float cpb_coord(int i) {
    float v = (float)(i - 6) * (8.0f / 6.0f);
    float av = fabsf(v);
    float r = log2f(av + 1.0f) * (1.0f / 3.0f);
    return (v < 0.f) ? -r : r;
}

// ---------------- fused fp16 convert + CPB MLP kernel ----------------------------
// blocks [0,1024): grid-stride fp16 conversion of x + 4 weights (8 floats/iter)
// blocks [1024, 1024+2197): CPB MLP
__global__ void __launch_bounds__(256) cvt_cpb(const float* __restrict__ x,
                                               const float* __restrict__ wq,
                                               const float* __restrict__ wp,
                                               const float* __restrict__ w1cv,
                                               const float* __restrict__ w2cv,
                                               const float* __restrict__ cw1,
                                               const float* __restrict__ cb1,
                                               const float* __restrict__ cw2) {
    __shared__ float hid[512];
    if (blockIdx.x >= 1024) {
        int t = blockIdx.x - 1024;
        int a = t / 169;
        int rem = t - a * 169;
        int b = rem / 13;
        int c = rem - b * 13;
        float c0 = cpb_coord(a), c1 = cpb_coord(b), c2 = cpb_coord(c);
        for (int j = threadIdx.x; j < 512; j += blockDim.x) {
            float hv = c0 * cw1[j * 3 + 0] + c1 * cw1[j * 3 + 1] + c2 * cw1[j * 3 + 2] +
                       cb1[j];
            hid[j] = fmaxf(hv, 0.f);
        }
        __syncthreads();
        if (threadIdx.x < 192) {
            int hh = threadIdx.x >> 5, lane = threadIdx.x & 31;
            float s = 0.f;
            for (int j = lane; j < 512; j += 32) s += hid[j] * cw2[hh * 512 + j];
#pragma unroll
            for (int off = 16; off; off >>= 1) s += __shfl_xor_sync(FULLMASK, s, off);
            if (lane == 0) g_hb[t * 6 + hh] = s;
        }
        return;
    }
    // ---- fp16 conversion (8-float groups) ----
    const int N0 = 1053696;            // x: 2*LTOT*192/8
    const int N1 = N0 + 13824;         // wq: 576*192/8
    const int N2 = N1 + 4608;          // wp: 192*192/8
    const int N3 = N2 + 18432;         // w1: 768*192/8
    const int N4 = N3 + 18432;         // w2: 192*768/8
    for (int i = blockIdx.x * blockDim.x + threadIdx.x; i < N4; i += 1024 * 256) {
        const float4* s;
        uint4* d;
        int off;
        if (i < N0) { s = (const float4*)x; d = (uint4*)g_xt; off = i; }
        else if (i < N1) { s = (const float4*)wq; d = (uint4*)g_wq; off = i - N0; }
        else if (i < N2) { s = (const float4*)wp; d = (uint4*)g_wp; off = i - N1; }
        else if (i < N3) { s = (const float4*)w1cv; d = (uint4*)g_w1; off = i - N2; }
        else { s = (const float4*)w2cv; d = (uint4*)g_w2; off = i - N3; }
        float4 a = s[2 * off];
        float4 b = s[2 * off + 1];
        uint4 u;
        u.x = pack_h2(a.x, a.y);
        u.y = pack_h2(a.z, a.w);
        u.z = pack_h2(b.x, b.y);
        u.w = pack_h2(b.z, b.w);
        d[off] = u;
    }
}

// ---------------- fp16 mma GEMM, BK=64 halves, cp.async 3-stage ------------------
// MODE 0: QKV (A = g_xt gathered; W = g_wq; out -> g_q/g_k/g_v fp32 + biases)
//         blockIdx.y >= 343: rpb table blocks
// MODE 2: FC1 (A = g_x1t; W = g_w1; out -> g_hmid fp16 with GELU)
#define BM 128
#define BN 96
#define BKH 64
#define KHS 72
#define A2_HALF (BM * KHS)          // 9216 halves
#define B2_HALF (BN * KHS)          // 6912 halves
#define GT_SMEM (3 * (A2_HALF + B2_HALF) * 2)    // 96768 B

template <int MODE>
__global__ void __launch_bounds__(256) mma_gemm(const float* __restrict__ bias1,
                                                const float* __restrict__ bias2,
                                                int K) {
    if (MODE == 0 && blockIdx.y >= 343) {
        const int total = 6 * 343 * RPBS;
        const int slice = blockIdx.x + 6 * (blockIdx.y - 343);
        const int per = 7376;
        const int start = slice * per;
        const int end = (start + per < total) ? (start + per) : total;
        for (int idx = start + threadIdx.x; idx < end; idx += 256) {
            int hh = idx / (343 * RPBS);
            int rem = idx - hh * (343 * RPBS);
            int i = rem / RPBS;
            int j = rem - i * RPBS;
            if (j >= 343) {
                g_rpb[idx] = 0.f;
                continue;
            }
            int dh = i / 49 - j / 49 + 6;
            int dw = (i / 7) % 7 - (j / 7) % 7 + 6;
            int dd = i % 7 - j % 7 + 6;
            int tix = (dh * 13 + dw) * 13 + dd;
            float v = g_hb[tix * 6 + hh];
            g_rpb[idx] = (16.f / (1.f + __expf(-v))) * LOG2E;
        }
        return;
    }

    extern __shared__ __half shh[];
    __half* As = shh;
    __half* Bs = shh + 3 * A2_HALF;
    const uint32_t sbA = smem_u32(As);
    const uint32_t sbB = smem_u32(Bs);

    const int tid = threadIdx.x;
    const int lane = tid & 31;
    const int warp = tid >> 5;
    const int warpM = warp & 3;
    const int warpN = warp >> 2;
    const int gr = lane >> 2;
    const int tg = lane & 3;

    const int m0 = blockIdx.y * BM;
    const int n0 = blockIdx.x * BN;

    const __half* Asrc = (MODE == 0) ? g_xt : g_x1t;
    const __half* W = (MODE == 0) ? g_wq : g_w1;

    // A: 4 chunks of 8 halves per thread per tile (128 rows x 8 chunks)
    const __half* aptr[4];
    uint32_t aoffB[4];
#pragma unroll
    for (int i = 0; i < 4; ++i) {
        int idx = tid + i * 256;
        int arow = idx >> 3, c8 = idx & 7;
        int rho = m0 + arow;
        const __half* p;
        if (MODE == 0) {
            int b_ = rho / 343, n = rho - b_ * 343;
            int bb = b_ >> 6, win = b_ & 63;
            int wa = win >> 4, wb = (win >> 2) & 3, wc = win & 3;
            int ii = n / 49, jj = (n / 7) % 7, kk = n % 7;
            int hs = (wa * 7 + ii + 3) % 28;
            int ws = (wb * 7 + jj + 3) % 28;
            int ds = (wc * 7 + kk + 3) % 28;
            p = Asrc + ((size_t)bb * LTOT + (hs * 784 + ws * 28 + ds)) * CDIM;
        } else {
            p = Asrc + (size_t)rho * K;
        }
        aptr[i] = p + c8 * 8;
        aoffB[i] = (arow * KHS + c8 * 8) * 2;
    }
    // B: 3 chunks per thread per tile (96 rows x 8 chunks = 768)
    const __half* bptr[3];
    uint32_t boff[3];
#pragma unroll
    for (int i = 0; i < 3; ++i) {
        int idx = tid + i * 256;
        int brow = idx >> 3, c8 = idx & 7;
        bptr[i] = W + (size_t)(n0 + brow) * K + c8 * 8;
        boff[i] = (brow * KHS + c8 * 8) * 2;
    }

    float acc[2][6][4];
#pragma unroll
    for (int mi = 0; mi < 2; ++mi)
#pragma unroll
        for (int ni = 0; ni < 6; ++ni)
#pragma unroll
            for (int e = 0; e < 4; ++e) acc[mi][ni][e] = 0.f;

    const int ntiles = K >> 6;   // K / 64
#pragma unroll
    for (int s = 0; s < 2; ++s) {
        const int kt = s * BKH;
#pragma unroll
        for (int i = 0; i < 4; ++i) cp16(sbA + s * (A2_HALF * 2) + aoffB[i], aptr[i] + kt);
#pragma unroll
        for (int i = 0; i < 3; ++i) cp16(sbB + s * (B2_HALF * 2) + boff[i], bptr[i] + kt);
        CP_COMMIT();
    }

    for (int t = 0; t < ntiles; ++t) {
        const int buf = t % 3;
        CP_WAIT1();
        __syncthreads();

        const __half* Ab = As + buf * A2_HALF;
        const __half* Bb = Bs + buf * B2_HALF;
#pragma unroll
        for (int kk = 0; kk < 4; ++kk) {
            uint32_t afr[2][4];
#pragma unroll
            for (int mi = 0; mi < 2; ++mi) {
                int rb = warpM * 32 + mi * 16;
                const __half* pa = Ab + (rb + gr) * KHS + kk * 16 + 2 * tg;
                const __half* pb = Ab + (rb + gr + 8) * KHS + kk * 16 + 2 * tg;
                afr[mi][0] = *(const uint32_t*)pa;
                afr[mi][1] = *(const uint32_t*)pb;
                afr[mi][2] = *(const uint32_t*)(pa + 8);
                afr[mi][3] = *(const uint32_t*)(pb + 8);
            }
#pragma unroll
            for (int ni = 0; ni < 6; ++ni) {
                const __half* pk = Bb + (warpN * 48 + ni * 8 + gr) * KHS + kk * 16 +
                                   2 * tg;
                uint32_t b0 = *(const uint32_t*)pk;
                uint32_t b1 = *(const uint32_t*)(pk + 8);
#pragma unroll
                for (int mi = 0; mi < 2; ++mi) mma_f16(acc[mi][ni], afr[mi], b0, b1);
            }
        }

        const int tn = t + 2;
        if (tn < ntiles) {
            const int s = tn % 3;
            const int kt = tn * BKH;
#pragma unroll
            for (int i = 0; i < 4; ++i)
                cp16(sbA + s * (A2_HALF * 2) + aoffB[i], aptr[i] + kt);
#pragma unroll
            for (int i = 0; i < 3; ++i)
                cp16(sbB + s * (B2_HALF * 2) + boff[i], bptr[i] + kt);
        }
        CP_COMMIT();
    }

    // ---------------- epilogue ----------------------------------------------------
#pragma unroll
    for (int mi = 0; mi < 2; ++mi) {
        int rows[2];
        rows[0] = m0 + warpM * 32 + mi * 16 + gr;
        rows[1] = rows[0] + 8;
#pragma unroll
        for (int half = 0; half < 2; ++half) {
            const int r = rows[half];
            int b_ = 0, n = 0;
            if (MODE == 0) {
                b_ = r / 343;
                n = r - b_ * 343;
            }
#pragma unroll
            for (int ni = 0; ni < 6; ++ni) {
                int c = n0 + warpN * 48 + ni * 8 + tg * 2;
                float v0 = acc[mi][ni][half * 2 + 0];
                float v1 = acc[mi][ni][half * 2 + 1];
                if (MODE == 0) {
                    int sct = c / 192;
                    int remc = c - sct * 192;
                    int hh = remc >> 5, dd = remc & 31;
                    float* dst = (sct == 0 ? g_q : (sct == 1 ? g_k : g_v)) +
                                 ((size_t)(b_ * 6 + hh) * NTOK + n) * HD + dd;
                    float e0 = 0.f, e1 = 0.f;
                    if (sct == 0) { e0 = bias1[remc]; e1 = bias1[remc + 1]; }
                    else if (sct == 2) { e0 = bias2[remc]; e1 = bias2[remc + 1]; }
                    *(float2*)dst = make_float2(v0 + e0, v1 + e1);
                } else {
                    float x0 = v0 + bias1[c], x1 = v1 + bias1[c + 1];
                    float g0 = 0.5f * x0 * (1.f + erff(x0 * 0.70710678118654752f));
                    float g1 = 0.5f * x1 * (1.f + erff(x1 * 0.70710678118654752f));
                    *(uint32_t*)&g_hmid[(size_t)r * 768 + c] = pack_h2(g0, g1);
                }
            }
        }
    }
}

// ---------------- fp16 GEMM (BN=192) + fused LayerNorm + residual ----------------
// MODE 0: PROJ  g_x1[pos]=x[pos]+LN(acc+bias) scatter; g_x1t fp16
// MODE 1: FC2   out[row]=g_x1[row]+LN(acc+bias)
#define B2L_HALF (192 * KHS)        // 13824 halves
#define LN_SMEM ((3 * (A2_HALF + B2L_HALF)) * 2 + 128 * 4 * 2 * 4)

template <int MODE>
__global__ void __launch_bounds__(512) gemm_ln(const float* __restrict__ bias,
                                               const float* __restrict__ basex,
                                               const float* __restrict__ gw,
                                               const float* __restrict__ bw,
                                               float* __restrict__ outp,
                                               int K) {
    extern __shared__ __half shh[];
    __half* Asm = shh;
    __half* Bsm = shh + 3 * A2_HALF;
    float* part = (float*)(shh + 3 * A2_HALF + 3 * B2L_HALF);  // [128][4][2]
    const uint32_t sbA = smem_u32(Asm);
    const uint32_t sbB = smem_u32(Bsm);

    const int tid = threadIdx.x;
    const int lane = tid & 31;
    const int warp = tid >> 5;
    const int warpM = warp & 3;
    const int warpN = warp >> 2;
    const int gr = lane >> 2;
    const int tg = lane & 3;

    const int m0 = blockIdx.x * BM;

    const __half* Asrc = (MODE == 0) ? g_attnout : g_hmid;
    const __half* W = (MODE == 0) ? g_wp : g_w2;

    const __half* aptr[2];
    uint32_t aoff[2];
#pragma unroll
    for (int i = 0; i < 2; ++i) {
        int idx = tid + i * 512;
        int arow = idx >> 3, c8 = idx & 7;
        aptr[i] = Asrc + (size_t)(m0 + arow) * K + c8 * 8;
        aoff[i] = (arow * KHS + c8 * 8) * 2;
    }
    const __half* bptr[3];
    uint32_t boff[3];
#pragma unroll
    for (int i = 0; i < 3; ++i) {
        int idx = tid + i * 512;
        int brow = idx >> 3, c8 = idx & 7;
        bptr[i] = W + (size_t)brow * K + c8 * 8;
        boff[i] = (brow * KHS + c8 * 8) * 2;
    }

    float acc[2][6][4];
#pragma unroll
    for (int mi = 0; mi < 2; ++mi)
#pragma unroll
        for (int ni = 0; ni < 6; ++ni)
#pragma unroll
            for (int e = 0; e < 4; ++e) acc[mi][ni][e] = 0.f;

    const int ntiles = K >> 6;
#pragma unroll
    for (int s = 0; s < 2; ++s) {
        const int kt = s * BKH;
#pragma unroll
        for (int i = 0; i < 2; ++i) cp16(sbA + s * (A2_HALF * 2) + aoff[i], aptr[i] + kt);
#pragma unroll
        for (int i = 0; i < 3; ++i) cp16(sbB + s * (B2L_HALF * 2) + boff[i], bptr[i] + kt);
        CP_COMMIT();
    }

    for (int t = 0; t < ntiles; ++t) {
        const int buf = t % 3;
        CP_WAIT1();
        __syncthreads();

        const __half* Ab = Asm + buf * A2_HALF;
        const __half* Bb = Bsm + buf * B2L_HALF;
#pragma unroll
        for (int kk = 0; kk < 4; ++kk) {
            uint32_t afr[2][4];
#pragma unroll
            for (int mi = 0; mi < 2; ++mi) {
                int rb = warpM * 32 + mi * 16;
                const __half* pa = Ab + (rb + gr) * KHS + kk * 16 + 2 * tg;
                const __half* pb = Ab + (rb + gr + 8) * KHS + kk * 16 + 2 * tg;
                afr[mi][0] = *(const uint32_t*)pa;
                afr[mi][1] = *(const uint32_t*)pb;
                afr[mi][2] = *(const uint32_t*)(pa + 8);
                afr[mi][3] = *(const uint32_t*)(pb + 8);
            }
#pragma unroll
            for (int ni = 0; ni < 6; ++ni) {
                const __half* pk = Bb + (warpN * 48 + ni * 8 + gr) * KHS + kk * 16 +
                                   2 * tg;
                uint32_t b0 = *(const uint32_t*)pk;
                uint32_t b1 = *(const uint32_t*)(pk + 8);
#pragma unroll
                for (int mi = 0; mi < 2; ++mi) mma_f16(acc[mi][ni], afr[mi], b0, b1);
            }
        }

        const int tn = t + 2;
        if (tn < ntiles) {
            const int s = tn % 3;
            const int kt = tn * BKH;
#pragma unroll
            for (int i = 0; i < 2; ++i)
                cp16(sbA + s * (A2_HALF * 2) + aoff[i], aptr[i] + kt);
#pragma unroll
            for (int i = 0; i < 3; ++i)
                cp16(sbB + s * (B2L_HALF * 2) + boff[i], bptr[i] + kt);
        }
        CP_COMMIT();
    }
    __syncthreads();

    // ---------------- fused bias + LN partials -------------------------------------
#pragma unroll
    for (int mi = 0; mi < 2; ++mi) {
#pragma unroll
        for (int half = 0; half < 2; ++half) {
            const int rl = warpM * 32 + mi * 16 + gr + half * 8;
            float s = 0.f, sq = 0.f;
#pragma unroll
            for (int ni = 0; ni < 6; ++ni) {
                int c = warpN * 48 + ni * 8 + tg * 2;
                float v0 = acc[mi][ni][half * 2 + 0] + bias[c];
                float v1 = acc[mi][ni][half * 2 + 1] + bias[c + 1];
                acc[mi][ni][half * 2 + 0] = v0;
                acc[mi][ni][half * 2 + 1] = v1;
                s += v0 + v1;
                sq += v0 * v0 + v1 * v1;
            }
            s += __shfl_xor_sync(FULLMASK, s, 1);
            s += __shfl_xor_sync(FULLMASK, s, 2);
            sq += __shfl_xor_sync(FULLMASK, sq, 1);
            sq += __shfl_xor_sync(FULLMASK, sq, 2);
            if (tg == 0) {
                part[(rl * 4 + warpN) * 2 + 0] = s;
                part[(rl * 4 + warpN) * 2 + 1] = sq;
            }
        }
    }
    __syncthreads();

#pragma unroll
    for (int mi = 0; mi < 2; ++mi) {
#pragma unroll
        for (int half = 0; half < 2; ++half) {
            const int rl = warpM * 32 + mi * 16 + gr + half * 8;
            const int r = m0 + rl;
            float s = 0.f, sq = 0.f;
#pragma unroll
            for (int g2 = 0; g2 < 4; ++g2) {
                s += part[(rl * 4 + g2) * 2 + 0];
                sq += part[(rl * 4 + g2) * 2 + 1];
            }
            float mean = s * (1.f / 192.f);
            float var = sq * (1.f / 192.f) - mean * mean;
            float inv = rsqrtf(var + 1e-5f);

            const float* bsrow;
            float* orow;
            __half* orow2 = nullptr;
            if (MODE == 0) {
                int b_ = r / 343, n = r - b_ * 343;
                int bb2 = b_ >> 6, win = b_ & 63;
                int wa = win >> 4, wb = (win >> 2) & 3, wc = win & 3;
                int i3 = n / 49, j3 = (n / 7) % 7, k3 = n % 7;
                int hd_ = (wa * 7 + i3 + 3) % 28;
                int wd_ = (wb * 7 + j3 + 3) % 28;
                int dd_ = (wc * 7 + k3 + 3) % 28;
                size_t pos = ((size_t)bb2 * LTOT + (hd_ * 784 + wd_ * 28 + dd_)) * CDIM;
                bsrow = basex + pos;
                orow = g_x1 + pos;
                orow2 = g_x1t + pos;
            } else {
                bsrow = g_x1 + (size_t)r * CDIM;
                orow = outp + (size_t)r * CDIM;
            }
#pragma unroll
            for (int ni = 0; ni < 6; ++ni) {
                int c = warpN * 48 + ni * 8 + tg * 2;
                float v0 = acc[mi][ni][half * 2 + 0];
                float v1 = acc[mi][ni][half * 2 + 1];
                float2 bse = *(const float2*)(bsrow + c);
                float2 gg = *(const float2*)(gw + c);
                float2 bb = *(const float2*)(bw + c);
                float o0 = bse.x + (v0 - mean) * inv * gg.x + bb.x;
                float o1 = bse.y + (v1 - mean) * inv * gg.y + bb.y;
                *(float2*)(orow + c) = make_float2(o0, o1);
                if (MODE == 0)
                    *(uint32_t*)&orow2[c] = pack_h2(o0, o1);
            }
        }
    }
}

// ---------------- tensor-core flash attention (fp16 QK + PV, static max, exp2) ---
#define KH_STRIDE 40
#define KH_BYTES (384 * KH_STRIDE * 2)
#define VTH_STRIDE 392
#define VTH_BYTES (32 * VTH_STRIDE * 2)
#define ATTN4_SMEM (KH_BYTES + VTH_BYTES + 512)

__global__ void __launch_bounds__(256, 2) attn4_kernel(const float* __restrict__ logit_scale) {
    extern __shared__ uint32_t asmem[];
    __half* Ksh = (__half*)asmem;
    __half* Vth = (__half*)((char*)asmem + KH_BYTES);
    unsigned char* region = (unsigned char*)((char*)Vth + VTH_BYTES);

    const int bh = blockIdx.x;
    const int b_ = bh / 6, h = bh - (bh / 6) * 6;
    const int tid = threadIdx.x;
    const int lane = tid & 31, warp = tid >> 5;
    const int gr = lane >> 2, tg = lane & 3;

    const size_t kvbase = (size_t)bh * (NTOK * HD);
    const float* kg = g_k + kvbase;
    const float* vg = g_v + kvbase;
    const float* qg = g_q + kvbase;

    for (int r = warp; r < 384; r += 8) {
        if (r < NTOK) {
            float v = kg[r * 32 + lane];
            float s = v * v;
#pragma unroll
            for (int o = 16; o; o >>= 1) s += __shfl_xor_sync(FULLMASK, s, o);
            float inv = 1.f / fmaxf(sqrtf(s), 1e-12f);
            Ksh[r * KH_STRIDE + lane] = __float2half(v * inv);
        } else {
            Ksh[r * KH_STRIDE + lane] = __float2half(0.f);
        }
    }
    for (int idx = tid; idx < NTOK * 32; idx += 256) {
        int j = idx >> 5, d = idx & 31;
        Vth[d * VTH_STRIDE + j] = __float2half(vg[idx]);
    }
    for (int idx = tid; idx < 32 * (VTH_STRIDE - NTOK); idx += 256) {
        int d = idx / (VTH_STRIDE - NTOK);
        int j = NTOK + idx - d * (VTH_STRIDE - NTOK);
        Vth[d * VTH_STRIDE + j] = __float2half(0.f);
    }
    const int win = b_ & 63;
    const int wa = win >> 4, wb = (win >> 2) & 3, wc = win & 3;
    const bool maskedw = (wa == 3) || (wb == 3) || (wc == 3);
    if (maskedw) {
        for (int t = tid; t < 384; t += 256) {
            if (t < NTOK) {
                int ih = t / 49, iw = (t / 7) % 7, id = t % 7;
                int rH = (wa < 3) ? 0 : ((ih < 4) ? 1 : 2);
                int rW = (wb < 3) ? 0 : ((iw < 4) ? 1 : 2);
                int rD = (wc < 3) ? 0 : ((id < 4) ? 1 : 2);
                region[t] = (unsigned char)(rH * 9 + rW * 3 + rD);
            } else {
                region[t] = 0;
            }
        }
    }
    __syncthreads();

    const float scale = __expf(fminf(logit_scale[h], 4.6051701859880914f));
    const float Mstat = (scale + 16.f) * LOG2E;
    const float* rpbh = g_rpb + (size_t)h * (343 * RPBS);

    for (int rb = 0; rb < 3; ++rb) {
        const int r0 = rb * 128 + warp * 16;
        if (r0 >= NTOK) continue;

        const int r_lo = r0 + gr, r_hi = r0 + gr + 8;
        const bool v_lo = r_lo < NTOK, v_hi = r_hi < NTOK;

        float qv[2][2][4];
        const float* qlo = qg + (size_t)(v_lo ? r_lo : 0) * 32;
        const float* qhi = qg + (size_t)(v_hi ? r_hi : 0) * 32;
#pragma unroll
        for (int kk = 0; kk < 2; ++kk) {
            const int d0 = kk * 16 + 2 * tg;
            qv[kk][0][0] = v_lo ? qlo[d0] : 0.f;
            qv[kk][0][1] = v_lo ? qlo[d0 + 1] : 0.f;
            qv[kk][0][2] = v_lo ? qlo[d0 + 8] : 0.f;
            qv[kk][0][3] = v_lo ? qlo[d0 + 9] : 0.f;
            qv[kk][1][0] = v_hi ? qhi[d0] : 0.f;
            qv[kk][1][1] = v_hi ? qhi[d0 + 1] : 0.f;
            qv[kk][1][2] = v_hi ? qhi[d0 + 8] : 0.f;
            qv[kk][1][3] = v_hi ? qhi[d0 + 9] : 0.f;
        }
        float s0 = 0.f, s1 = 0.f;
#pragma unroll
        for (int kk = 0; kk < 2; ++kk)
#pragma unroll
            for (int e = 0; e < 4; ++e) {
                s0 += qv[kk][0][e] * qv[kk][0][e];
                s1 += qv[kk][1][e] * qv[kk][1][e];
            }
        s0 += __shfl_xor_sync(FULLMASK, s0, 1);
        s0 += __shfl_xor_sync(FULLMASK, s0, 2);
        s1 += __shfl_xor_sync(FULLMASK, s1, 1);
        s1 += __shfl_xor_sync(FULLMASK, s1, 2);
        const float i0 = scale * LOG2E / fmaxf(sqrtf(s0), 1e-12f);
        const float i1 = scale * LOG2E / fmaxf(sqrtf(s1), 1e-12f);
        uint32_t aQh[2][4];
#pragma unroll
        for (int kk = 0; kk < 2; ++kk) {
            aQh[kk][0] = pack_h2(qv[kk][0][0] * i0, qv[kk][0][1] * i0);
            aQh[kk][1] = pack_h2(qv[kk][1][0] * i1, qv[kk][1][1] * i1);
            aQh[kk][2] = pack_h2(qv[kk][0][2] * i0, qv[kk][0][3] * i0);
            aQh[kk][3] = pack_h2(qv[kk][1][2] * i1, qv[kk][1][3] * i1);
        }

        unsigned char rq0 = 0, rq1 = 0;
        if (maskedw) {
            rq0 = region[v_lo ? r_lo : (NTOK - 1)];
            rq1 = region[v_hi ? r_hi : (NTOK - 1)];
        }
        const float* rpr_lo = rpbh + (size_t)(v_lo ? r_lo : 0) * RPBS;
        const float* rpr_hi = rpbh + (size_t)(v_hi ? r_hi : 0) * RPBS;

        float l0 = 0.f, l1 = 0.f;
        float o[4][4];
#pragma unroll
        for (int nt = 0; nt < 4; ++nt)
#pragma unroll
            for (int e = 0; e < 4; ++e) o[nt][e] = 0.f;

        for (int ch = 0; ch < 6; ++ch) {
            const int j0 = ch * 64;
            float s[8][4];
#pragma unroll
            for (int nt = 0; nt < 8; ++nt)
#pragma unroll
                for (int e = 0; e < 4; ++e) s[nt][e] = 0.f;
#pragma unroll
            for (int kk = 0; kk < 2; ++kk) {
#pragma unroll
                for (int nt = 0; nt < 8; ++nt) {
                    const __half* kp = Ksh + (j0 + nt * 8 + gr) * KH_STRIDE + kk * 16 +
                                       2 * tg;
                    uint32_t b0 = *(const uint32_t*)kp;
                    uint32_t b1 = *(const uint32_t*)(kp + 8);
                    mma_f16(s[nt], aQh[kk], b0, b1);
                }
            }
#pragma unroll
            for (int nt = 0; nt < 8; ++nt) {
                const int jc = j0 + nt * 8 + tg * 2;
                float2 blo = *(const float2*)(rpr_lo + jc);
                float2 bhi = *(const float2*)(rpr_hi + jc);
                float t0 = s[nt][0] + blo.x - Mstat;
                float t1 = s[nt][1] + blo.y - Mstat;
                float t2 = s[nt][2] + bhi.x - Mstat;
                float t3 = s[nt][3] + bhi.y - Mstat;
                if (maskedw) {
                    unsigned char rk0 = region[jc];
                    unsigned char rk1 = region[jc + 1];
                    if (rk0 != rq0) t0 -= 144.26950408f;
                    if (rk1 != rq0) t1 -= 144.26950408f;
                    if (rk0 != rq1) t2 -= 144.26950408f;
                    if (rk1 != rq1) t3 -= 144.26950408f;
                }
                float p0 = exp2f(t0);
                float p1 = exp2f(t1);
                float p2 = exp2f(t2);
                float p3 = exp2f(t3);
                if (ch == 5) {
                    if (jc >= NTOK) { p0 = 0.f; p2 = 0.f; }
                    if (jc + 1 >= NTOK) { p1 = 0.f; p3 = 0.f; }
                }
                l0 += p0 + p1;
                l1 += p2 + p3;
                s[nt][0] = p0;
                s[nt][1] = p1;
                s[nt][2] = p2;
                s[nt][3] = p3;
            }
#pragma unroll
            for (int kk2 = 0; kk2 < 4; ++kk2) {
                uint32_t aP[4];
                aP[0] = pack_h2(s[2 * kk2][0], s[2 * kk2][1]);
                aP[1] = pack_h2(s[2 * kk2][2], s[2 * kk2][3]);
                aP[2] = pack_h2(s[2 * kk2 + 1][0], s[2 * kk2 + 1][1]);
                aP[3] = pack_h2(s[2 * kk2 + 1][2], s[2 * kk2 + 1][3]);
                const int jb = j0 + kk2 * 16 + 2 * tg;
#pragma unroll
                for (int nt = 0; nt < 4; ++nt) {
                    const int d = nt * 8 + gr;
                    uint32_t b0 = *(const uint32_t*)&Vth[d * VTH_STRIDE + jb];
                    uint32_t b1 = *(const uint32_t*)&Vth[d * VTH_STRIDE + jb + 8];
                    mma_f16(o[nt], aP, b0, b1);
                }
            }
        }

        l0 += __shfl_xor_sync(FULLMASK, l0, 1);
        l0 += __shfl_xor_sync(FULLMASK, l0, 2);
        l1 += __shfl_xor_sync(FULLMASK, l1, 1);
        l1 += __shfl_xor_sync(FULLMASK, l1, 2);

        if (v_lo) {
            const float il0 = 1.f / l0;
            __half* dst = g_attnout + ((size_t)b_ * NTOK + r_lo) * CDIM + h * HD;
#pragma unroll
            for (int nt = 0; nt < 4; ++nt)
                *(uint32_t*)&dst[nt * 8 + tg * 2] =
                    pack_h2(o[nt][0] * il0, o[nt][1] * il0);
        }
        if (v_hi) {
            const float il1 = 1.f / l1;
            __half* dst = g_attnout + ((size_t)b_ * NTOK + r_hi) * CDIM + h * HD;
#pragma unroll
            for (int nt = 0; nt < 4; ++nt)
                *(uint32_t*)&dst[nt * 8 + tg * 2] =
                    pack_h2(o[nt][2] * il1, o[nt][3] * il1);
        }
    }
}

// ---------------- launch ---------------------------------------------------------
extern "C" void kernel_launch(void* const* d_in, const int* in_sizes, int n_in,
                              void* d_out, int out_size) {
    (void)in_sizes; (void)n_in; (void)out_size;
    const float* x = (const float*)d_in[0];
    const float* qkv_w = (const float*)d_in[1];
    const float* q_bias = (const float*)d_in[2];
    const float* v_bias = (const float*)d_in[3];
    const float* logit_scale = (const float*)d_in[4];
    const float* cpb_w1 = (const float*)d_in[5];
    const float* cpb_b1 = (const float*)d_in[6];
    const float* cpb_w2 = (const float*)d_in[7];
    const float* proj_w = (const float*)d_in[8];
    const float* proj_b = (const float*)d_in[9];
    const float* norm1_g = (const float*)d_in[10];
    const float* norm1_b = (const float*)d_in[11];
    const float* fc1_w = (const float*)d_in[12];
    const float* fc1_b = (const float*)d_in[13];
    const float* fc2_w = (const float*)d_in[14];
    const float* fc2_b = (const float*)d_in[15];
    const float* norm2_g = (const float*)d_in[16];
    const float* norm2_b = (const float*)d_in[17];
    float* out = (float*)d_out;

    static bool attr_done = false;
    if (!attr_done) {
        cudaFuncSetAttribute(attn4_kernel, cudaFuncAttributeMaxDynamicSharedMemorySize,
                             ATTN4_SMEM);
        cudaFuncSetAttribute(mma_gemm<0>, cudaFuncAttributeMaxDynamicSharedMemorySize,
                             GT_SMEM);
        cudaFuncSetAttribute(mma_gemm<2>, cudaFuncAttributeMaxDynamicSharedMemorySize,
                             GT_SMEM);
        cudaFuncSetAttribute(gemm_ln<0>, cudaFuncAttributeMaxDynamicSharedMemorySize,
                             LN_SMEM);
        cudaFuncSetAttribute(gemm_ln<1>, cudaFuncAttributeMaxDynamicSharedMemorySize,
                             LN_SMEM);
        attr_done = true;
    }

    // fused fp16 pre-conversion + CPB MLP
    cvt_cpb<<<1024 + 2197, 256>>>(x, qkv_w, proj_w, fc1_w, fc2_w,
                                  cpb_w1, cpb_b1, cpb_w2);

    // qkv (fused shift + window gather) + rpb table (extra 96 blocks at y>=343)
    mma_gemm<0><<<dim3(6, 343 + 16), 256, GT_SMEM>>>(q_bias, v_bias, 192);

    // attention (tensor-core flash, fp16 QK+PV, static max, exp2)
    attn4_kernel<<<768, 256, ATTN4_SMEM>>>(logit_scale);

    // proj + LN + residual (fused window reverse + roll scatter): N=192, K=192
    gemm_ln<0><<<343, 512, LN_SMEM>>>(proj_b, x, norm1_g, norm1_b, nullptr, 192);

    // fc1: N=768, K=192 (GELU)
    mma_gemm<2><<<dim3(8, 343), 256, GT_SMEM>>>(fc1_b, nullptr, 192);

    // fc2 + LN + residual: N=192, K=768
    gemm_ln<1><<<343, 512, LN_SMEM>>>(fc2_b, nullptr, norm2_g, norm2_b, out, 768);
}

// round 17
// speedup vs baseline: 1.4693x; 1.0432x over previous
#include <cuda_runtime.h>
#include <cuda_fp16.h>
#include <math.h>
#include <stdint.h>

#define FULLMASK 0xffffffffu
#define LOG2E 1.4426950408889634f

// problem dims
#define NTOK   343
#define NHEAD  6
#define HD     32
#define CDIM   192
#define LTOT   21952
#define NWIN   128
#define NROWS  43904
#define RPBS   344

// ---------------- device scratch ------------------------------------------------
__device__ float g_hb[2197 * 6];
__device__ __align__(16) float g_rpb[6 * 343 * RPBS];
__device__ __align__(16) float g_q[(size_t)NWIN * NHEAD * NTOK * HD];
__device__ __align__(16) float g_k[(size_t)NWIN * NHEAD * NTOK * HD];
__device__ __align__(16) float g_v[(size_t)NWIN * NHEAD * NTOK * HD];
__device__ __align__(16) __half g_attnout[(size_t)NWIN * NTOK * CDIM];
__device__ __align__(16) float g_x1[(size_t)2 * LTOT * CDIM];           // fp32
__device__ __align__(16) __half g_x1t[(size_t)2 * LTOT * CDIM];
__device__ __align__(16) __half g_xt[(size_t)2 * LTOT * CDIM];
__device__ __align__(16) __half g_hmid[(size_t)NROWS * 768];
__device__ __align__(16) __half g_wq[576 * 192];
__device__ __align__(16) __half g_wp[192 * 192];
__device__ __align__(16) __half g_w1[768 * 192];
__device__ __align__(16) __half g_w2[192 * 768];

// ---------------- helpers -------------------------------------------------------
__device__ __forceinline__ void mma_f16(float* c, const uint32_t* a, uint32_t b0,
                                        uint32_t b1) {
    asm volatile(
        "mma.sync.aligned.m16n8k16.row.col.f32.f16.f16.f32 "
        "{%0,%1,%2,%3}, {%4,%5,%6,%7}, {%8,%9}, {%0,%1,%2,%3};"
        : "+f"(c[0]), "+f"(c[1]), "+f"(c[2]), "+f"(c[3])
        : "r"(a[0]), "r"(a[1]), "r"(a[2]), "r"(a[3]), "r"(b0), "r"(b1));
}

__device__ __forceinline__ uint32_t pack_h2(float lo, float hi) {
    uint32_t r;
    asm("cvt.rn.f16x2.f32 %0, %1, %2;" : "=r"(r) : "f"(hi), "f"(lo));
    return r;
}

__device__ __forceinline__ uint32_t smem_u32(const void* p) {
    uint32_t a;
    asm("{ .reg .u64 t; cvta.to.shared.u64 t, %1; cvt.u32.u64 %0, t; }" : "=r"(a) : "l"(p));
    return a;
}

__device__ __forceinline__ void cp16(uint32_t dst, const void* src) {
    asm volatile("cp.async.ca.shared.global [%0], [%1], 16;" :: "r"(dst), "l"(src));
}
#define CP_COMMIT() asm volatile("cp.async.commit_group;" ::: "memory")
#define CP_WAIT1()  asm volatile("cp.async.wait_group 1;" ::: "memory")

// ---------------- CPB coord helper ----------------------------------------------
__device__ __forceinline__ float cpb_coord(int i) {
    float v = (float)(i - 6) * (8.0f / 6.0f);
    float av = fabsf(v);
    float r = log2f(av + 1.0f) * (1.0f / 3.0f);
    return (v < 0.f) ? -r : r;
}

// ---------------- fused fp16 convert + CPB MLP kernel ----------------------------
__global__ void __launch_bounds__(256) cvt_cpb(const float* __restrict__ x,
                                               const float* __restrict__ wq,
                                               const float* __restrict__ wp,
                                               const float* __restrict__ w1cv,
                                               const float* __restrict__ w2cv,
                                               const float* __restrict__ cw1,
                                               const float* __restrict__ cb1,
                                               const float* __restrict__ cw2) {
    __shared__ float hid[512];
    if (blockIdx.x >= 1024) {
        int t = blockIdx.x - 1024;
        int a = t / 169;
        int rem = t - a * 169;
        int b = rem / 13;
        int c = rem - b * 13;
        float c0 = cpb_coord(a), c1 = cpb_coord(b), c2 = cpb_coord(c);
        for (int j = threadIdx.x; j < 512; j += blockDim.x) {
            float hv = c0 * cw1[j * 3 + 0] + c1 * cw1[j * 3 + 1] + c2 * cw1[j * 3 + 2] +
                       cb1[j];
            hid[j] = fmaxf(hv, 0.f);
        }
        __syncthreads();
        if (threadIdx.x < 192) {
            int hh = threadIdx.x >> 5, lane = threadIdx.x & 31;
            float s = 0.f;
            for (int j = lane; j < 512; j += 32) s += hid[j] * cw2[hh * 512 + j];
#pragma unroll
            for (int off = 16; off; off >>= 1) s += __shfl_xor_sync(FULLMASK, s, off);
            if (lane == 0) g_hb[t * 6 + hh] = s;
        }
        return;
    }
    const int N0 = 1053696;
    const int N1 = N0 + 13824;
    const int N2 = N1 + 4608;
    const int N3 = N2 + 18432;
    const int N4 = N3 + 18432;
    for (int i = blockIdx.x * blockDim.x + threadIdx.x; i < N4; i += 1024 * 256) {
        const float4* s;
        uint4* d;
        int off;
        if (i < N0) { s = (const float4*)x; d = (uint4*)g_xt; off = i; }
        else if (i < N1) { s = (const float4*)wq; d = (uint4*)g_wq; off = i - N0; }
        else if (i < N2) { s = (const float4*)wp; d = (uint4*)g_wp; off = i - N1; }
        else if (i < N3) { s = (const float4*)w1cv; d = (uint4*)g_w1; off = i - N2; }
        else { s = (const float4*)w2cv; d = (uint4*)g_w2; off = i - N3; }
        float4 a = s[2 * off];
        float4 b = s[2 * off + 1];
        uint4 u;
        u.x = pack_h2(a.x, a.y);
        u.y = pack_h2(a.z, a.w);
        u.z = pack_h2(b.x, b.y);
        u.w = pack_h2(b.z, b.w);
        d[off] = u;
    }
}

// ---------------- fp16 mma GEMM, BK=64 halves, cp.async 3-stage ------------------
// MODE 0: QKV (+ rpb table blocks at blockIdx.y >= 343); MODE 2: FC1 (GELU)
#define BM 128
#define BN 96
#define BKH 64
#define KHS 72
#define A2_HALF (BM * KHS)
#define B2_HALF (BN * KHS)
#define GT_SMEM (3 * (A2_HALF + B2_HALF) * 2)

template <int MODE>
__global__ void __launch_bounds__(256) mma_gemm(const float* __restrict__ bias1,
                                                const float* __restrict__ bias2,
                                                int K) {
    if (MODE == 0 && blockIdx.y >= 343) {
        const int total = 6 * 343 * RPBS;
        const int slice = blockIdx.x + 6 * (blockIdx.y - 343);
        const int per = 7376;
        const int start = slice * per;
        const int end = (start + per < total) ? (start + per) : total;
        for (int idx = start + threadIdx.x; idx < end; idx += 256) {
            int hh = idx / (343 * RPBS);
            int rem = idx - hh * (343 * RPBS);
            int i = rem / RPBS;
            int j = rem - i * RPBS;
            if (j >= 343) {
                g_rpb[idx] = 0.f;
                continue;
            }
            int dh = i / 49 - j / 49 + 6;
            int dw = (i / 7) % 7 - (j / 7) % 7 + 6;
            int dd = i % 7 - j % 7 + 6;
            int tix = (dh * 13 + dw) * 13 + dd;
            float v = g_hb[tix * 6 + hh];
            g_rpb[idx] = (16.f / (1.f + __expf(-v))) * LOG2E;
        }
        return;
    }

    extern __shared__ __half shh[];
    __half* As = shh;
    __half* Bs = shh + 3 * A2_HALF;
    const uint32_t sbA = smem_u32(As);
    const uint32_t sbB = smem_u32(Bs);

    const int tid = threadIdx.x;
    const int lane = tid & 31;
    const int warp = tid >> 5;
    const int warpM = warp & 3;
    const int warpN = warp >> 2;
    const int gr = lane >> 2;
    const int tg = lane & 3;

    const int m0 = blockIdx.y * BM;
    const int n0 = blockIdx.x * BN;

    const __half* Asrc = (MODE == 0) ? g_xt : g_x1t;
    const __half* W = (MODE == 0) ? g_wq : g_w1;

    const __half* aptr[4];
    uint32_t aoffB[4];
#pragma unroll
    for (int i = 0; i < 4; ++i) {
        int idx = tid + i * 256;
        int arow = idx >> 3, c8 = idx & 7;
        int rho = m0 + arow;
        const __half* p;
        if (MODE == 0) {
            int b_ = rho / 343, n = rho - b_ * 343;
            int bb = b_ >> 6, win = b_ & 63;
            int wa = win >> 4, wb = (win >> 2) & 3, wc = win & 3;
            int ii = n / 49, jj = (n / 7) % 7, kk = n % 7;
            int hs = (wa * 7 + ii + 3) % 28;
            int ws = (wb * 7 + jj + 3) % 28;
            int ds = (wc * 7 + kk + 3) % 28;
            p = Asrc + ((size_t)bb * LTOT + (hs * 784 + ws * 28 + ds)) * CDIM;
        } else {
            p = Asrc + (size_t)rho * K;
        }
        aptr[i] = p + c8 * 8;
        aoffB[i] = (arow * KHS + c8 * 8) * 2;
    }
    const __half* bptr[3];
    uint32_t boff[3];
#pragma unroll
    for (int i = 0; i < 3; ++i) {
        int idx = tid + i * 256;
        int brow = idx >> 3, c8 = idx & 7;
        bptr[i] = W + (size_t)(n0 + brow) * K + c8 * 8;
        boff[i] = (brow * KHS + c8 * 8) * 2;
    }

    float acc[2][6][4];
#pragma unroll
    for (int mi = 0; mi < 2; ++mi)
#pragma unroll
        for (int ni = 0; ni < 6; ++ni)
#pragma unroll
            for (int e = 0; e < 4; ++e) acc[mi][ni][e] = 0.f;

    const int ntiles = K >> 6;
#pragma unroll
    for (int s = 0; s < 2; ++s) {
        const int kt = s * BKH;
#pragma unroll
        for (int i = 0; i < 4; ++i) cp16(sbA + s * (A2_HALF * 2) + aoffB[i], aptr[i] + kt);
#pragma unroll
        for (int i = 0; i < 3; ++i) cp16(sbB + s * (B2_HALF * 2) + boff[i], bptr[i] + kt);
        CP_COMMIT();
    }

    for (int t = 0; t < ntiles; ++t) {
        const int buf = t % 3;
        CP_WAIT1();
        __syncthreads();

        const __half* Ab = As + buf * A2_HALF;
        const __half* Bb = Bs + buf * B2_HALF;
#pragma unroll
        for (int kk = 0; kk < 4; ++kk) {
            uint32_t afr[2][4];
#pragma unroll
            for (int mi = 0; mi < 2; ++mi) {
                int rb = warpM * 32 + mi * 16;
                const __half* pa = Ab + (rb + gr) * KHS + kk * 16 + 2 * tg;
                const __half* pb = Ab + (rb + gr + 8) * KHS + kk * 16 + 2 * tg;
                afr[mi][0] = *(const uint32_t*)pa;
                afr[mi][1] = *(const uint32_t*)pb;
                afr[mi][2] = *(const uint32_t*)(pa + 8);
                afr[mi][3] = *(const uint32_t*)(pb + 8);
            }
#pragma unroll
            for (int ni = 0; ni < 6; ++ni) {
                const __half* pk = Bb + (warpN * 48 + ni * 8 + gr) * KHS + kk * 16 +
                                   2 * tg;
                uint32_t b0 = *(const uint32_t*)pk;
                uint32_t b1 = *(const uint32_t*)(pk + 8);
#pragma unroll
                for (int mi = 0; mi < 2; ++mi) mma_f16(acc[mi][ni], afr[mi], b0, b1);
            }
        }

        const int tn = t + 2;
        if (tn < ntiles) {
            const int s = tn % 3;
            const int kt = tn * BKH;
#pragma unroll
            for (int i = 0; i < 4; ++i)
                cp16(sbA + s * (A2_HALF * 2) + aoffB[i], aptr[i] + kt);
#pragma unroll
            for (int i = 0; i < 3; ++i)
                cp16(sbB + s * (B2_HALF * 2) + boff[i], bptr[i] + kt);
        }
        CP_COMMIT();
    }

#pragma unroll
    for (int mi = 0; mi < 2; ++mi) {
        int rows[2];
        rows[0] = m0 + warpM * 32 + mi * 16 + gr;
        rows[1] = rows[0] + 8;
#pragma unroll
        for (int half = 0; half < 2; ++half) {
            const int r = rows[half];
            int b_ = 0, n = 0;
            if (MODE == 0) {
                b_ = r / 343;
                n = r - b_ * 343;
            }
#pragma unroll
            for (int ni = 0; ni < 6; ++ni) {
                int c = n0 + warpN * 48 + ni * 8 + tg * 2;
                float v0 = acc[mi][ni][half * 2 + 0];
                float v1 = acc[mi][ni][half * 2 + 1];
                if (MODE == 0) {
                    int sct = c / 192;
                    int remc = c - sct * 192;
                    int hh = remc >> 5, dd = remc & 31;
                    float* dst = (sct == 0 ? g_q : (sct == 1 ? g_k : g_v)) +
                                 ((size_t)(b_ * 6 + hh) * NTOK + n) * HD + dd;
                    float e0 = 0.f, e1 = 0.f;
                    if (sct == 0) { e0 = bias1[remc]; e1 = bias1[remc + 1]; }
                    else if (sct == 2) { e0 = bias2[remc]; e1 = bias2[remc + 1]; }
                    *(float2*)dst = make_float2(v0 + e0, v1 + e1);
                } else {
                    float x0 = v0 + bias1[c], x1 = v1 + bias1[c + 1];
                    float g0 = 0.5f * x0 * (1.f + erff(x0 * 0.70710678118654752f));
                    float g1 = 0.5f * x1 * (1.f + erff(x1 * 0.70710678118654752f));
                    *(uint32_t*)&g_hmid[(size_t)r * 768 + c] = pack_h2(g0, g1);
                }
            }
        }
    }
}

// ---------------- fp16 GEMM (BM=64, BN=192) + fused LayerNorm + residual ---------
// 256 threads = 8 warps (2M x 4N), 2 CTAs/SM.
// MODE 0: PROJ  g_x1[pos]=x[pos]+LN(acc+bias) scatter; g_x1t fp16
// MODE 1: FC2   out[row]=g_x1[row]+LN(acc+bias)
#define BML 64
#define AL_HALF (BML * KHS)         // 4608 halves
#define B2L_HALF (192 * KHS)        // 13824 halves
#define LN_SMEM ((3 * (AL_HALF + B2L_HALF)) * 2 + 64 * 4 * 2 * 4)

template <int MODE>
__global__ void __launch_bounds__(256) gemm_ln(const float* __restrict__ bias,
                                               const float* __restrict__ basex,
                                               const float* __restrict__ gw,
                                               const float* __restrict__ bw,
                                               float* __restrict__ outp,
                                               int K) {
    extern __shared__ __half shh[];
    __half* Asm = shh;
    __half* Bsm = shh + 3 * AL_HALF;
    float* part = (float*)(shh + 3 * AL_HALF + 3 * B2L_HALF);  // [64][4][2]
    const uint32_t sbA = smem_u32(Asm);
    const uint32_t sbB = smem_u32(Bsm);

    const int tid = threadIdx.x;
    const int lane = tid & 31;
    const int warp = tid >> 5;
    const int warpM = warp & 1;      // 0..1
    const int warpN = warp >> 1;     // 0..3
    const int gr = lane >> 2;
    const int tg = lane & 3;

    const int m0 = blockIdx.x * BML;

    const __half* Asrc = (MODE == 0) ? g_attnout : g_hmid;
    const __half* W = (MODE == 0) ? g_wp : g_w2;

    const __half* aptr[2];
    uint32_t aoff[2];
#pragma unroll
    for (int i = 0; i < 2; ++i) {
        int idx = tid + i * 256;
        int arow = idx >> 3, c8 = idx & 7;
        aptr[i] = Asrc + (size_t)(m0 + arow) * K + c8 * 8;
        aoff[i] = (arow * KHS + c8 * 8) * 2;
    }
    const __half* bptr[6];
    uint32_t boff[6];
#pragma unroll
    for (int i = 0; i < 6; ++i) {
        int idx = tid + i * 256;
        int brow = idx >> 3, c8 = idx & 7;
        bptr[i] = W + (size_t)brow * K + c8 * 8;
        boff[i] = (brow * KHS + c8 * 8) * 2;
    }

    float acc[2][6][4];
#pragma unroll
    for (int mi = 0; mi < 2; ++mi)
#pragma unroll
        for (int ni = 0; ni < 6; ++ni)
#pragma unroll
            for (int e = 0; e < 4; ++e) acc[mi][ni][e] = 0.f;

    const int ntiles = K >> 6;
#pragma unroll
    for (int s = 0; s < 2; ++s) {
        const int kt = s * BKH;
#pragma unroll
        for (int i = 0; i < 2; ++i) cp16(sbA + s * (AL_HALF * 2) + aoff[i], aptr[i] + kt);
#pragma unroll
        for (int i = 0; i < 6; ++i) cp16(sbB + s * (B2L_HALF * 2) + boff[i], bptr[i] + kt);
        CP_COMMIT();
    }

    for (int t = 0; t < ntiles; ++t) {
        const int buf = t % 3;
        CP_WAIT1();
        __syncthreads();

        const __half* Ab = Asm + buf * AL_HALF;
        const __half* Bb = Bsm + buf * B2L_HALF;
#pragma unroll
        for (int kk = 0; kk < 4; ++kk) {
            uint32_t afr[2][4];
#pragma unroll
            for (int mi = 0; mi < 2; ++mi) {
                int rb = warpM * 32 + mi * 16;
                const __half* pa = Ab + (rb + gr) * KHS + kk * 16 + 2 * tg;
                const __half* pb = Ab + (rb + gr + 8) * KHS + kk * 16 + 2 * tg;
                afr[mi][0] = *(const uint32_t*)pa;
                afr[mi][1] = *(const uint32_t*)pb;
                afr[mi][2] = *(const uint32_t*)(pa + 8);
                afr[mi][3] = *(const uint32_t*)(pb + 8);
            }
#pragma unroll
            for (int ni = 0; ni < 6; ++ni) {
                const __half* pk = Bb + (warpN * 48 + ni * 8 + gr) * KHS + kk * 16 +
                                   2 * tg;
                uint32_t b0 = *(const uint32_t*)pk;
                uint32_t b1 = *(const uint32_t*)(pk + 8);
#pragma unroll
                for (int mi = 0; mi < 2; ++mi) mma_f16(acc[mi][ni], afr[mi], b0, b1);
            }
        }

        const int tn = t + 2;
        if (tn < ntiles) {
            const int s = tn % 3;
            const int kt = tn * BKH;
#pragma unroll
            for (int i = 0; i < 2; ++i)
                cp16(sbA + s * (AL_HALF * 2) + aoff[i], aptr[i] + kt);
#pragma unroll
            for (int i = 0; i < 6; ++i)
                cp16(sbB + s * (B2L_HALF * 2) + boff[i], bptr[i] + kt);
        }
        CP_COMMIT();
    }
    __syncthreads();

    // ---------------- fused bias + LN partials -------------------------------------
#pragma unroll
    for (int mi = 0; mi < 2; ++mi) {
#pragma unroll
        for (int half = 0; half < 2; ++half) {
            const int rl = warpM * 32 + mi * 16 + gr + half * 8;
            float s = 0.f, sq = 0.f;
#pragma unroll
            for (int ni = 0; ni < 6; ++ni) {
                int c = warpN * 48 + ni * 8 + tg * 2;
                float v0 = acc[mi][ni][half * 2 + 0] + bias[c];
                float v1 = acc[mi][ni][half * 2 + 1] + bias[c + 1];
                acc[mi][ni][half * 2 + 0] = v0;
                acc[mi][ni][half * 2 + 1] = v1;
                s += v0 + v1;
                sq += v0 * v0 + v1 * v1;
            }
            s += __shfl_xor_sync(FULLMASK, s, 1);
            s += __shfl_xor_sync(FULLMASK, s, 2);
            sq += __shfl_xor_sync(FULLMASK, sq, 1);
            sq += __shfl_xor_sync(FULLMASK, sq, 2);
            if (tg == 0) {
                part[(rl * 4 + warpN) * 2 + 0] = s;
                part[(rl * 4 + warpN) * 2 + 1] = sq;
            }
        }
    }
    __syncthreads();

#pragma unroll
    for (int mi = 0; mi < 2; ++mi) {
#pragma unroll
        for (int half = 0; half < 2; ++half) {
            const int rl = warpM * 32 + mi * 16 + gr + half * 8;
            const int r = m0 + rl;
            float s = 0.f, sq = 0.f;
#pragma unroll
            for (int g2 = 0; g2 < 4; ++g2) {
                s += part[(rl * 4 + g2) * 2 + 0];
                sq += part[(rl * 4 + g2) * 2 + 1];
            }
            float mean = s * (1.f / 192.f);
            float var = sq * (1.f / 192.f) - mean * mean;
            float inv = rsqrtf(var + 1e-5f);

            const float* bsrow;
            float* orow;
            __half* orow2 = nullptr;
            if (MODE == 0) {
                int b_ = r / 343, n = r - b_ * 343;
                int bb2 = b_ >> 6, win = b_ & 63;
                int wa = win >> 4, wb = (win >> 2) & 3, wc = win & 3;
                int i3 = n / 49, j3 = (n / 7) % 7, k3 = n % 7;
                int hd_ = (wa * 7 + i3 + 3) % 28;
                int wd_ = (wb * 7 + j3 + 3) % 28;
                int dd_ = (wc * 7 + k3 + 3) % 28;
                size_t pos = ((size_t)bb2 * LTOT + (hd_ * 784 + wd_ * 28 + dd_)) * CDIM;
                bsrow = basex + pos;
                orow = g_x1 + pos;
                orow2 = g_x1t + pos;
            } else {
                bsrow = g_x1 + (size_t)r * CDIM;
                orow = outp + (size_t)r * CDIM;
            }
#pragma unroll
            for (int ni = 0; ni < 6; ++ni) {
                int c = warpN * 48 + ni * 8 + tg * 2;
                float v0 = acc[mi][ni][half * 2 + 0];
                float v1 = acc[mi][ni][half * 2 + 1];
                float2 bse = *(const float2*)(bsrow + c);
                float2 gg = *(const float2*)(gw + c);
                float2 bb = *(const float2*)(bw + c);
                float o0 = bse.x + (v0 - mean) * inv * gg.x + bb.x;
                float o1 = bse.y + (v1 - mean) * inv * gg.y + bb.y;
                *(float2*)(orow + c) = make_float2(o0, o1);
                if (MODE == 0)
                    *(uint32_t*)&orow2[c] = pack_h2(o0, o1);
            }
        }
    }
}

// ---------------- tensor-core flash attention (fp16, low-reg, 3 CTAs/SM) ---------
#define KH_STRIDE 40
#define KH_BYTES (384 * KH_STRIDE * 2)
#define VTH_STRIDE 392
#define VTH_BYTES (32 * VTH_STRIDE * 2)
#define ATTN4_SMEM (KH_BYTES + VTH_BYTES + 512)

__global__ void __launch_bounds__(256, 3) attn4_kernel(const float* __restrict__ logit_scale) {
    extern __shared__ uint32_t asmem[];
    __half* Ksh = (__half*)asmem;
    __half* Vth = (__half*)((char*)asmem + KH_BYTES);
    unsigned char* region = (unsigned char*)((char*)Vth + VTH_BYTES);

    const int bh = blockIdx.x;
    const int b_ = bh / 6, h = bh - (bh / 6) * 6;
    const int tid = threadIdx.x;
    const int lane = tid & 31, warp = tid >> 5;
    const int gr = lane >> 2, tg = lane & 3;

    const size_t kvbase = (size_t)bh * (NTOK * HD);
    const float* kg = g_k + kvbase;
    const float* vg = g_v + kvbase;
    const float* qg = g_q + kvbase;

    for (int r = warp; r < 384; r += 8) {
        if (r < NTOK) {
            float v = kg[r * 32 + lane];
            float s = v * v;
#pragma unroll
            for (int o = 16; o; o >>= 1) s += __shfl_xor_sync(FULLMASK, s, o);
            float inv = 1.f / fmaxf(sqrtf(s), 1e-12f);
            Ksh[r * KH_STRIDE + lane] = __float2half(v * inv);
        } else {
            Ksh[r * KH_STRIDE + lane] = __float2half(0.f);
        }
    }
    for (int idx = tid; idx < NTOK * 32; idx += 256) {
        int j = idx >> 5, d = idx & 31;
        Vth[d * VTH_STRIDE + j] = __float2half(vg[idx]);
    }
    for (int idx = tid; idx < 32 * (VTH_STRIDE - NTOK); idx += 256) {
        int d = idx / (VTH_STRIDE - NTOK);
        int j = NTOK + idx - d * (VTH_STRIDE - NTOK);
        Vth[d * VTH_STRIDE + j] = __float2half(0.f);
    }
    const int win = b_ & 63;
    const int wa = win >> 4, wb = (win >> 2) & 3, wc = win & 3;
    const bool maskedw = (wa == 3) || (wb == 3) || (wc == 3);
    if (maskedw) {
        for (int t = tid; t < 384; t += 256) {
            if (t < NTOK) {
                int ih = t / 49, iw = (t / 7) % 7, id = t % 7;
                int rH = (wa < 3) ? 0 : ((ih < 4) ? 1 : 2);
                int rW = (wb < 3) ? 0 : ((iw < 4) ? 1 : 2);
                int rD = (wc < 3) ? 0 : ((id < 4) ? 1 : 2);
                region[t] = (unsigned char)(rH * 9 + rW * 3 + rD);
            } else {
                region[t] = 0;
            }
        }
    }
    __syncthreads();

    const float scale = __expf(fminf(logit_scale[h], 4.6051701859880914f));
    const float Mstat = (scale + 16.f) * LOG2E;
    const float* rpbh = g_rpb + (size_t)h * (343 * RPBS);

    for (int rb = 0; rb < 3; ++rb) {
        const int r0 = rb * 128 + warp * 16;
        if (r0 >= NTOK) continue;

        const int r_lo = r0 + gr, r_hi = r0 + gr + 8;
        const bool v_lo = r_lo < NTOK, v_hi = r_hi < NTOK;

        float qv[2][2][4];
        const float* qlo = qg + (size_t)(v_lo ? r_lo : 0) * 32;
        const float* qhi = qg + (size_t)(v_hi ? r_hi : 0) * 32;
#pragma unroll
        for (int kk = 0; kk < 2; ++kk) {
            const int d0 = kk * 16 + 2 * tg;
            qv[kk][0][0] = v_lo ? qlo[d0] : 0.f;
            qv[kk][0][1] = v_lo ? qlo[d0 + 1] : 0.f;
            qv[kk][0][2] = v_lo ? qlo[d0 + 8] : 0.f;
            qv[kk][0][3] = v_lo ? qlo[d0 + 9] : 0.f;
            qv[kk][1][0] = v_hi ? qhi[d0] : 0.f;
            qv[kk][1][1] = v_hi ? qhi[d0 + 1] : 0.f;
            qv[kk][1][2] = v_hi ? qhi[d0 + 8] : 0.f;
            qv[kk][1][3] = v_hi ? qhi[d0 + 9] : 0.f;
        }
        float s0 = 0.f, s1 = 0.f;
#pragma unroll
        for (int kk = 0; kk < 2; ++kk)
#pragma unroll
            for (int e = 0; e < 4; ++e) {
                s0 += qv[kk][0][e] * qv[kk][0][e];
                s1 += qv[kk][1][e] * qv[kk][1][e];
            }
        s0 += __shfl_xor_sync(FULLMASK, s0, 1);
        s0 += __shfl_xor_sync(FULLMASK, s0, 2);
        s1 += __shfl_xor_sync(FULLMASK, s1, 1);
        s1 += __shfl_xor_sync(FULLMASK, s1, 2);
        const float i0 = scale * LOG2E / fmaxf(sqrtf(s0), 1e-12f);
        const float i1 = scale * LOG2E / fmaxf(sqrtf(s1), 1e-12f);
        uint32_t aQh[2][4];
#pragma unroll
        for (int kk = 0; kk < 2; ++kk) {
            aQh[kk][0] = pack_h2(qv[kk][0][0] * i0, qv[kk][0][1] * i0);
            aQh[kk][1] = pack_h2(qv[kk][1][0] * i1, qv[kk][1][1] * i1);
            aQh[kk][2] = pack_h2(qv[kk][0][2] * i0, qv[kk][0][3] * i0);
            aQh[kk][3] = pack_h2(qv[kk][1][2] * i1, qv[kk][1][3] * i1);
        }

        unsigned char rq0 = 0, rq1 = 0;
        if (maskedw) {
            rq0 = region[v_lo ? r_lo : (NTOK - 1)];
            rq1 = region[v_hi ? r_hi : (NTOK - 1)];
        }
        const float* rpr_lo = rpbh + (size_t)(v_lo ? r_lo : 0) * RPBS;
        const float* rpr_hi = rpbh + (size_t)(v_hi ? r_hi : 0) * RPBS;

        float l0 = 0.f, l1 = 0.f;
        float o[4][4];
#pragma unroll
        for (int nt = 0; nt < 4; ++nt)
#pragma unroll
            for (int e = 0; e < 4; ++e) o[nt][e] = 0.f;

        for (int ch = 0; ch < 6; ++ch) {
            const int j0 = ch * 64;
            // per nt-pair: QK mma -> softmax -> pack -> PV mma (low register footprint)
#pragma unroll
            for (int kk2 = 0; kk2 < 4; ++kk2) {
                float s2[2][4];
#pragma unroll
                for (int t2 = 0; t2 < 2; ++t2)
#pragma unroll
                    for (int e = 0; e < 4; ++e) s2[t2][e] = 0.f;
#pragma unroll
                for (int t2 = 0; t2 < 2; ++t2) {
                    const int nt = 2 * kk2 + t2;
#pragma unroll
                    for (int kk = 0; kk < 2; ++kk) {
                        const __half* kp = Ksh + (j0 + nt * 8 + gr) * KH_STRIDE +
                                           kk * 16 + 2 * tg;
                        uint32_t b0 = *(const uint32_t*)kp;
                        uint32_t b1 = *(const uint32_t*)(kp + 8);
                        mma_f16(s2[t2], aQh[kk], b0, b1);
                    }
                }
#pragma unroll
                for (int t2 = 0; t2 < 2; ++t2) {
                    const int nt = 2 * kk2 + t2;
                    const int jc = j0 + nt * 8 + tg * 2;
                    float2 blo = *(const float2*)(rpr_lo + jc);
                    float2 bhi = *(const float2*)(rpr_hi + jc);
                    float t0 = s2[t2][0] + blo.x - Mstat;
                    float t1 = s2[t2][1] + blo.y - Mstat;
                    float t2v = s2[t2][2] + bhi.x - Mstat;
                    float t3 = s2[t2][3] + bhi.y - Mstat;
                    if (maskedw) {
                        unsigned char rk0 = region[jc];
                        unsigned char rk1 = region[jc + 1];
                        if (rk0 != rq0) t0 -= 144.26950408f;
                        if (rk1 != rq0) t1 -= 144.26950408f;
                        if (rk0 != rq1) t2v -= 144.26950408f;
                        if (rk1 != rq1) t3 -= 144.26950408f;
                    }
                    float p0 = exp2f(t0);
                    float p1 = exp2f(t1);
                    float p2 = exp2f(t2v);
                    float p3 = exp2f(t3);
                    if (ch == 5) {
                        if (jc >= NTOK) { p0 = 0.f; p2 = 0.f; }
                        if (jc + 1 >= NTOK) { p1 = 0.f; p3 = 0.f; }
                    }
                    l0 += p0 + p1;
                    l1 += p2 + p3;
                    s2[t2][0] = p0;
                    s2[t2][1] = p1;
                    s2[t2][2] = p2;
                    s2[t2][3] = p3;
                }
                uint32_t aP[4];
                aP[0] = pack_h2(s2[0][0], s2[0][1]);
                aP[1] = pack_h2(s2[0][2], s2[0][3]);
                aP[2] = pack_h2(s2[1][0], s2[1][1]);
                aP[3] = pack_h2(s2[1][2], s2[1][3]);
                const int jb = j0 + kk2 * 16 + 2 * tg;
#pragma unroll
                for (int nt = 0; nt < 4; ++nt) {
                    const int d = nt * 8 + gr;
                    uint32_t b0 = *(const uint32_t*)&Vth[d * VTH_STRIDE + jb];
                    uint32_t b1 = *(const uint32_t*)&Vth[d * VTH_STRIDE + jb + 8];
                    mma_f16(o[nt], aP, b0, b1);
                }
            }
        }

        l0 += __shfl_xor_sync(FULLMASK, l0, 1);
        l0 += __shfl_xor_sync(FULLMASK, l0, 2);
        l1 += __shfl_xor_sync(FULLMASK, l1, 1);
        l1 += __shfl_xor_sync(FULLMASK, l1, 2);

        if (v_lo) {
            const float il0 = 1.f / l0;
            __half* dst = g_attnout + ((size_t)b_ * NTOK + r_lo) * CDIM + h * HD;
#pragma unroll
            for (int nt = 0; nt < 4; ++nt)
                *(uint32_t*)&dst[nt * 8 + tg * 2] =
                    pack_h2(o[nt][0] * il0, o[nt][1] * il0);
        }
        if (v_hi) {
            const float il1 = 1.f / l1;
            __half* dst = g_attnout + ((size_t)b_ * NTOK + r_hi) * CDIM + h * HD;
#pragma unroll
            for (int nt = 0; nt < 4; ++nt)
                *(uint32_t*)&dst[nt * 8 + tg * 2] =
                    pack_h2(o[nt][2] * il1, o[nt][3] * il1);
        }
    }
}

// ---------------- launch ---------------------------------------------------------
extern "C" void kernel_launch(void* const* d_in, const int* in_sizes, int n_in,
                              void* d_out, int out_size) {
    (void)in_sizes; (void)n_in; (void)out_size;
    const float* x = (const float*)d_in[0];
    const float* qkv_w = (const float*)d_in[1];
    const float* q_bias = (const float*)d_in[2];
    const float* v_bias = (const float*)d_in[3];
    const float* logit_scale = (const float*)d_in[4];
    const float* cpb_w1 = (const float*)d_in[5];
    const float* cpb_b1 = (const float*)d_in[6];
    const float* cpb_w2 = (const float*)d_in[7];
    const float* proj_w = (const float*)d_in[8];
    const float* proj_b = (const float*)d_in[9];
    const float* norm1_g = (const float*)d_in[10];
    const float* norm1_b = (const float*)d_in[11];
    const float* fc1_w = (const float*)d_in[12];
    const float* fc1_b = (const float*)d_in[13];
    const float* fc2_w = (const float*)d_in[14];
    const float* fc2_b = (const float*)d_in[15];
    const float* norm2_g = (const float*)d_in[16];
    const float* norm2_b = (const float*)d_in[17];
    float* out = (float*)d_out;

    static bool attr_done = false;
    if (!attr_done) {
        cudaFuncSetAttribute(attn4_kernel, cudaFuncAttributeMaxDynamicSharedMemorySize,
                             ATTN4_SMEM);
        cudaFuncSetAttribute(mma_gemm<0>, cudaFuncAttributeMaxDynamicSharedMemorySize,
                             GT_SMEM);
        cudaFuncSetAttribute(mma_gemm<2>, cudaFuncAttributeMaxDynamicSharedMemorySize,
                             GT_SMEM);
        cudaFuncSetAttribute(gemm_ln<0>, cudaFuncAttributeMaxDynamicSharedMemorySize,
                             LN_SMEM);
        cudaFuncSetAttribute(gemm_ln<1>, cudaFuncAttributeMaxDynamicSharedMemorySize,
                             LN_SMEM);
        attr_done = true;
    }

    // fused fp16 pre-conversion + CPB MLP
    cvt_cpb<<<1024 + 2197, 256>>>(x, qkv_w, proj_w, fc1_w, fc2_w,
                                  cpb_w1, cpb_b1, cpb_w2);

    // qkv (fused shift + window gather) + rpb table (extra 96 blocks at y>=343)
    mma_gemm<0><<<dim3(6, 343 + 16), 256, GT_SMEM>>>(q_bias, v_bias, 192);

    // attention (tensor-core flash, fp16, low-reg, 3 CTAs/SM)
    attn4_kernel<<<768, 256, ATTN4_SMEM>>>(logit_scale);

    // proj + LN + residual (fused window reverse + roll scatter): N=192, K=192
    gemm_ln<0><<<686, 256, LN_SMEM>>>(proj_b, x, norm1_g, norm1_b, nullptr, 192);

    // fc1: N=768, K=192 (GELU)
    mma_gemm<2><<<dim3(8, 343), 256, GT_SMEM>>>(fc1_b, nullptr, 192);

    // fc2 + LN + residual: N=192, K=768
    gemm_ln<1><<<686, 256, LN_SMEM>>>(fc2_b, nullptr, norm2_g, norm2_b, out, 768);
}